// round 2
// baseline (speedup 1.0000x reference)
#include <cuda_runtime.h>

#define BM 128
#define BN 128
#define BK 8

// ---------------- scratch (device globals: allocation-free) ----------------
// Q, K, V, attn-out: 4 x 32MB ; P (attention matrix): 64MB
__device__ float g_Q[4 * 2048 * 1024];
__device__ float g_K[4 * 2048 * 1024];
__device__ float g_V[4 * 2048 * 1024];
__device__ float g_O[4 * 2048 * 1024];
__device__ float g_P[4 * 2048 * 2048];

// ---------------------------------------------------------------------------
// Tiled fp32 GEMM, 128x128x8, 256 threads, 8x8 per-thread microtile,
// double-buffered smem with register prefetch.
//
//   B_NT = true : C[m,n] = sum_k A[m,k] * B[n,k]   (B row-major [N,K])
//   B_NT = false: C[m,n] = sum_k A[m,k] * B[k,n]   (B row-major [K,N])
//
// mode 0: plain
// mode 1: causal tile skip (square M==N logits GEMM): skip tiles fully above
//         the diagonal (bn > bm). Crossing tiles compute garbage above the
//         diagonal; the softmax kernel never reads it and zero-fills it.
// mode 2: k-limit for P@V: P[q,k] == 0 for k > q, so stop the K loop at
//         m0 + BM (multiple of BK, all dims are multiples of 128).
// ---------------------------------------------------------------------------
template <bool B_NT>
__global__ __launch_bounds__(256, 2)
void gemm_kernel(const float* __restrict__ A, const float* __restrict__ B,
                 float* __restrict__ C, const float* __restrict__ bias,
                 int M, int N, int K,
                 long long sA, long long sB, long long sC, int mode)
{
    const int bn = blockIdx.x, bm = blockIdx.y, bz = blockIdx.z;
    if (mode == 1 && bn > bm) return;  // fully-above-diagonal tile

    A += (long long)bz * sA;
    B += (long long)bz * sB;
    C += (long long)bz * sC;

    const int m0 = bm * BM, n0 = bn * BN;
    const int kend = (mode == 2) ? min(K, m0 + BM) : K;
    const int nk = kend / BK;

    __shared__ float As[2][BK][BM];
    __shared__ float Bs[2][BK][BN];

    const int tid = threadIdx.x;
    // A tile load: 128 rows x 8 cols = 256 float4; thread -> (row, 4-col)
    const int arow = tid >> 1;
    const int acol = (tid & 1) << 2;
    // B tile load mapping depends on layout
    const int brow = B_NT ? (tid >> 1) : (tid >> 5);
    const int bcol = B_NT ? ((tid & 1) << 2) : ((tid & 31) << 2);
    // compute mapping: 16x16 threads, each 8x8 outputs
    const int ty = tid >> 4, tx = tid & 15;

    float acc[8][8] = {};

    const float* Aptr = A + (long long)(m0 + arow) * K + acol;
    const float* Bptr = B_NT ? (B + (long long)(n0 + brow) * K + bcol)
                             : (B + (long long)brow * N + n0 + bcol);

    // preload tile 0
    float4 ra = *(const float4*)Aptr;
    float4 rb = *(const float4*)Bptr;
    As[0][acol + 0][arow] = ra.x; As[0][acol + 1][arow] = ra.y;
    As[0][acol + 2][arow] = ra.z; As[0][acol + 3][arow] = ra.w;
    if (B_NT) {
        Bs[0][bcol + 0][brow] = rb.x; Bs[0][bcol + 1][brow] = rb.y;
        Bs[0][bcol + 2][brow] = rb.z; Bs[0][bcol + 3][brow] = rb.w;
    } else {
        *(float4*)&Bs[0][brow][bcol] = rb;
    }
    __syncthreads();

    for (int kt = 0; kt < nk; ++kt) {
        const int buf = kt & 1;
        const bool more = (kt + 1 < nk);
        if (more) {
            ra = *(const float4*)(Aptr + (kt + 1) * BK);
            rb = B_NT ? *(const float4*)(Bptr + (kt + 1) * BK)
                      : *(const float4*)(Bptr + (long long)(kt + 1) * BK * N);
        }
        #pragma unroll
        for (int kk = 0; kk < BK; ++kk) {
            float a[8], b[8];
            #pragma unroll
            for (int i = 0; i < 8; ++i) a[i] = As[buf][kk][ty * 8 + i];
            #pragma unroll
            for (int j = 0; j < 8; ++j) b[j] = Bs[buf][kk][tx * 8 + j];
            #pragma unroll
            for (int i = 0; i < 8; ++i)
                #pragma unroll
                for (int j = 0; j < 8; ++j)
                    acc[i][j] = fmaf(a[i], b[j], acc[i][j]);
        }
        if (more) {
            const int nb = buf ^ 1;
            As[nb][acol + 0][arow] = ra.x; As[nb][acol + 1][arow] = ra.y;
            As[nb][acol + 2][arow] = ra.z; As[nb][acol + 3][arow] = ra.w;
            if (B_NT) {
                Bs[nb][bcol + 0][brow] = rb.x; Bs[nb][bcol + 1][brow] = rb.y;
                Bs[nb][bcol + 2][brow] = rb.z; Bs[nb][bcol + 3][brow] = rb.w;
            } else {
                *(float4*)&Bs[nb][brow][bcol] = rb;
            }
            __syncthreads();
        }
    }

    // epilogue
    #pragma unroll
    for (int i = 0; i < 8; ++i) {
        const int m = m0 + ty * 8 + i;
        #pragma unroll
        for (int j = 0; j < 8; j += 4) {
            const int n = n0 + tx * 8 + j;
            float4 v = make_float4(acc[i][j], acc[i][j + 1],
                                   acc[i][j + 2], acc[i][j + 3]);
            if (bias) {
                v.x += bias[n + 0]; v.y += bias[n + 1];
                v.z += bias[n + 2]; v.w += bias[n + 3];
            }
            *(float4*)&C[(long long)m * N + n] = v;
        }
    }
}

// ---------------------------------------------------------------------------
// Causal row softmax over P[b, i, :]. Valid entries j <= i; j > i zero-filled
// so the subsequent P@V GEMM can run dense (with a k-limit).
// ---------------------------------------------------------------------------
__global__ __launch_bounds__(256)
void softmax_causal_kernel(float* __restrict__ P, int S)
{
    const int b = blockIdx.y, i = blockIdx.x;
    float* row = P + ((long long)b * S + i) * S;
    const int n = i + 1;
    const int tid = threadIdx.x;
    __shared__ float red[8];

    // --- row max ---
    float m = -3.4e38f;
    for (int j = tid; j < n; j += 256) m = fmaxf(m, row[j]);
    #pragma unroll
    for (int o = 16; o; o >>= 1) m = fmaxf(m, __shfl_xor_sync(~0u, m, o));
    if ((tid & 31) == 0) red[tid >> 5] = m;
    __syncthreads();
    if (tid < 32) {
        float v = (tid < 8) ? red[tid] : -3.4e38f;
        #pragma unroll
        for (int o = 4; o; o >>= 1) v = fmaxf(v, __shfl_xor_sync(~0u, v, o));
        if (tid == 0) red[0] = v;
    }
    __syncthreads();
    m = red[0];
    __syncthreads();

    // --- exp + sum ---
    float s = 0.f;
    for (int j = tid; j < n; j += 256) {
        float e = __expf(row[j] - m);
        row[j] = e;
        s += e;
    }
    #pragma unroll
    for (int o = 16; o; o >>= 1) s += __shfl_xor_sync(~0u, s, o);
    if ((tid & 31) == 0) red[tid >> 5] = s;
    __syncthreads();
    if (tid < 32) {
        float v = (tid < 8) ? red[tid] : 0.f;
        #pragma unroll
        for (int o = 4; o; o >>= 1) v += __shfl_xor_sync(~0u, v, o);
        if (tid == 0) red[0] = v;
    }
    __syncthreads();
    const float inv = 1.f / red[0];

    // --- normalize + zero the masked tail ---
    for (int j = tid; j < n; j += 256) row[j] *= inv;
    for (int j = n + tid; j < S; j += 256) row[j] = 0.f;
}

// ---------------------------------------------------------------------------
extern "C" void kernel_launch(void* const* d_in, const int* in_sizes, int n_in,
                              void* d_out, int out_size)
{
    const float* X  = (const float*)d_in[0];
    const float* WQ = (const float*)d_in[1];
    const float* WK = (const float*)d_in[2];
    const float* WV = (const float*)d_in[3];
    const float* WO = (const float*)d_in[4];
    const float* bO = (const float*)d_in[5];
    float* out = (float*)d_out;

    float *Q, *K, *V, *O, *P;
    cudaGetSymbolAddress((void**)&Q, g_Q);
    cudaGetSymbolAddress((void**)&K, g_K);
    cudaGetSymbolAddress((void**)&V, g_V);
    cudaGetSymbolAddress((void**)&O, g_O);
    cudaGetSymbolAddress((void**)&P, g_P);

    const int B = 4, S = 2048, D = 1024, M = B * S;
    const long long SD = (long long)S * D;
    const long long SS = (long long)S * S;

    dim3 blk(256);
    dim3 gproj(D / BN, M / BM, 1);

    // Q/K/V projections: [8192,1024] = X @ W^T
    gemm_kernel<true><<<gproj, blk>>>(X, WQ, Q, nullptr, M, D, D, 0, 0, 0, 0);
    gemm_kernel<true><<<gproj, blk>>>(X, WK, K, nullptr, M, D, D, 0, 0, 0, 0);
    gemm_kernel<true><<<gproj, blk>>>(X, WV, V, nullptr, M, D, D, 0, 0, 0, 0);

    // logits: P[b] = Q[b] @ K[b]^T  (causal tile skip)
    dim3 glog(S / BN, S / BM, B);
    gemm_kernel<true><<<glog, blk>>>(Q, K, P, nullptr, S, S, D, SD, SD, SS, 1);

    // causal softmax (also zero-fills masked region)
    softmax_causal_kernel<<<dim3(S, B), 256>>>(P, S);

    // attn out: O[b] = P[b] @ V[b]  (k-limited by causal structure)
    dim3 gpv(D / BN, S / BM, B);
    gemm_kernel<false><<<gpv, blk>>>(P, V, O, nullptr, S, D, S, SS, SD, SD, 2);

    // output projection + bias
    gemm_kernel<true><<<gproj, blk>>>(O, WO, out, bO, M, D, D, 0, 0, 0, 0);
}

// round 5
// speedup vs baseline: 2.3974x; 2.3974x over previous
#include <cuda_runtime.h>
#include <cuda_fp16.h>
#include <stdint.h>

#define BM 128
#define BN 128
#define BK 32
#define STAGES 4
#define TILE_B (BM * BK * 2)            // 8 KB per operand tile
#define STAGE_B (4 * TILE_B)            // 32 KB  (Ah, Al, Bh, Bl)
#define SMEM_TOTAL (STAGES * STAGE_B)   // 128 KB

// ---------------- scratch (device globals: allocation-free) ----------------
__device__ float  g_V[4LL * 2048 * 1024];
__device__ float  g_P[4LL * 2048 * 2048];
__device__ __half g_Xh[8192LL * 1024],  g_Xl[8192LL * 1024];
__device__ __half g_WQh[1024 * 1024],   g_WQl[1024 * 1024];
__device__ __half g_WKh[1024 * 1024],   g_WKl[1024 * 1024];
__device__ __half g_WVh[1024 * 1024],   g_WVl[1024 * 1024];
__device__ __half g_WOh[1024 * 1024],   g_WOl[1024 * 1024];
__device__ __half g_Qh[8192LL * 1024],  g_Ql[8192LL * 1024];
__device__ __half g_Kh[8192LL * 1024],  g_Kl[8192LL * 1024];
__device__ __half g_Vth[4LL * 1024 * 2048], g_Vtl[4LL * 1024 * 2048];
__device__ __half g_Ph[4LL * 2048 * 2048],  g_Pl[4LL * 2048 * 2048];
__device__ __half g_Oh[8192LL * 1024],  g_Ol[8192LL * 1024];

// ---------------- base-PTX helpers (NO tcgen05 / NO "a" features) ----------
__device__ __forceinline__ uint32_t smem_u32(const void* p) {
    uint32_t a;
    asm("{ .reg .u64 t; cvta.to.shared.u64 t, %1; cvt.u32.u64 %0, t; }"
        : "=r"(a) : "l"(p));
    return a;
}
#define CP_ASYNC16(sa, ga) \
    asm volatile("cp.async.cg.shared.global [%0], [%1], 16;" :: "r"(sa), "l"(ga))
#define CP_COMMIT() asm volatile("cp.async.commit_group;" ::: "memory")
#define CP_WAIT(n)  asm volatile("cp.async.wait_group %0;" :: "n"(n) : "memory")
#define LDSM4(d0, d1, d2, d3, a) \
    asm volatile("ldmatrix.sync.aligned.m8n8.x4.shared.b16 {%0,%1,%2,%3}, [%4];" \
                 : "=r"(d0), "=r"(d1), "=r"(d2), "=r"(d3) : "r"(a))
#define MMA(d, a, b0, b1) \
    asm volatile("mma.sync.aligned.m16n8k16.row.col.f32.f16.f16.f32 " \
                 "{%0,%1,%2,%3}, {%4,%5,%6,%7}, {%8,%9}, {%0,%1,%2,%3};" \
                 : "+f"((d)[0]), "+f"((d)[1]), "+f"((d)[2]), "+f"((d)[3]) \
                 : "r"((a)[0]), "r"((a)[1]), "r"((a)[2]), "r"((a)[3]), \
                   "r"(b0), "r"(b1))

// smem tile layout: [128 rows][4 chunks of 16B], chunk xor-swizzled.
// Conflict-free for cp.async writes and ldmatrix reads (verified bank-disjoint).
__device__ __forceinline__ uint32_t swz(uint32_t r, uint32_t c) {
    return r * 64u + ((c ^ ((r >> 1) & 3u)) << 4);
}

__device__ __forceinline__ void split_h(float x, __half& h, __half& l) {
    h = __float2half_rn(x);
    l = __float2half_rn(x - __half2float(h));
}

// ---------------------------------------------------------------------------
// fp16x3 HMMA GEMM:  C[m,n] = sum_k A[m,k] * B[n,k]   (both row-major, NT)
//   A = Ah + Al, B = Bh + Bl (fp16 pairs). 3-pass accumulate in fp32:
//   C ~= Ah*Bh + Al*Bh + Ah*Bl.
// mode 0: plain   mode 1: causal tile skip (bn>bm)   mode 2: k-limit m0+BM
// OUT_HALF 0: write fp32 C (+bias if given).  1: write fp16 hi/lo pair.
// ---------------------------------------------------------------------------
template <int OUT_HALF>
__global__ __launch_bounds__(256, 1)
void hmma_gemm(const __half* __restrict__ pAh, const __half* __restrict__ pAl,
               const __half* __restrict__ pBh, const __half* __restrict__ pBl,
               float* __restrict__ Cf, __half* __restrict__ Ch,
               __half* __restrict__ Cl, const float* __restrict__ bias,
               int M, int N, int K,
               long long sA, long long sB, long long sC, int mode)
{
    extern __shared__ char smem[];
    const int bn = blockIdx.x, bm = blockIdx.y, bz = blockIdx.z;
    if (mode == 1 && bn > bm) return;

    const int m0 = bm * BM, n0 = bn * BN;
    const int kend = (mode == 2) ? (m0 + BM) : K;
    const int nk = kend / BK;

    const long long oA = (long long)bz * sA;
    const long long oB = (long long)bz * sB;

    const int tid = threadIdx.x;
    const int r0 = tid >> 2;        // 0..63
    const int c0 = tid & 3;         // 16B chunk within 64B row

    // gmem sources: 4 tiles (Ah, Al, Bh, Bl) x 2 rows (r0, r0+64) per thread
    const __half* srcs[8];
    srcs[0] = pAh + oA + (long long)(m0 + r0) * K + c0 * 8;
    srcs[1] = srcs[0] + 64LL * K;
    srcs[2] = pAl + oA + (long long)(m0 + r0) * K + c0 * 8;
    srcs[3] = srcs[2] + 64LL * K;
    srcs[4] = pBh + oB + (long long)(n0 + r0) * K + c0 * 8;
    srcs[5] = srcs[4] + 64LL * K;
    srcs[6] = pBl + oB + (long long)(n0 + r0) * K + c0 * 8;
    srcs[7] = srcs[6] + 64LL * K;

    const uint32_t sbase = smem_u32(smem);
    const uint32_t w0 = swz((uint32_t)r0, (uint32_t)c0);
    const uint32_t w1 = w0 + 64u * 64u;        // row r0+64: same xor pattern
    uint32_t dsts[8];
    #pragma unroll
    for (int t = 0; t < 4; ++t) {
        dsts[2 * t]     = (uint32_t)t * TILE_B + w0;
        dsts[2 * t + 1] = (uint32_t)t * TILE_B + w1;
    }

    const int wid = tid >> 5, lid = tid & 31;
    const int wm = (wid >> 2) * 64;     // warp m offset (2 warp-rows)
    const int wn = (wid & 3) * 32;      // warp n offset (4 warp-cols)
    const int lrow = lid & 15;          // ldmatrix row within 16
    const int lkh  = lid >> 4;          // ldmatrix k-half

    float acc[4][4][4] = {};

    // prologue: stages 0..STAGES-2
    #pragma unroll
    for (int s = 0; s < STAGES - 1; ++s) {
        if (s < nk) {
            const uint32_t st = sbase + (uint32_t)(s % STAGES) * STAGE_B;
            const long long ko = (long long)s * BK;
            #pragma unroll
            for (int j = 0; j < 8; ++j) CP_ASYNC16(st + dsts[j], srcs[j] + ko);
        }
        CP_COMMIT();
    }

    for (int kt = 0; kt < nk; ++kt) {
        CP_WAIT(STAGES - 2);
        __syncthreads();     // stage kt ready; everyone done with stage kt-1

        const int nxt = kt + STAGES - 1;
        if (nxt < nk) {
            const uint32_t st = sbase + (uint32_t)(nxt % STAGES) * STAGE_B;
            const long long ko = (long long)nxt * BK;
            #pragma unroll
            for (int j = 0; j < 8; ++j) CP_ASYNC16(st + dsts[j], srcs[j] + ko);
        }
        CP_COMMIT();

        const uint32_t sb = sbase + (uint32_t)(kt % STAGES) * STAGE_B;
        #pragma unroll
        for (int ks = 0; ks < 2; ++ks) {
            const uint32_t ckh = 2u * ks + (uint32_t)lkh;
            uint32_t ah[4][4], al[4][4], bF[4][2];

            // ---- load A-hi frags ----
            #pragma unroll
            for (int mt = 0; mt < 4; ++mt) {
                uint32_t row = (uint32_t)(wm + mt * 16 + lrow);
                uint32_t ad = sb + swz(row, ckh);               // tile 0 = Ah
                LDSM4(ah[mt][0], ah[mt][1], ah[mt][2], ah[mt][3], ad);
            }
            // ---- load B-hi frags ----
            #pragma unroll
            for (int np = 0; np < 2; ++np) {
                uint32_t row = (uint32_t)(wn + np * 16 + lrow);
                uint32_t ad = sb + 2u * TILE_B + swz(row, ckh); // tile 2 = Bh
                uint32_t q0, q1, q2, q3;
                LDSM4(q0, q1, q2, q3, ad);
                bF[2 * np][0] = q0; bF[2 * np + 1][0] = q1;
                bF[2 * np][1] = q2; bF[2 * np + 1][1] = q3;
            }
            // ---- pass 1: Ah * Bh ----
            #pragma unroll
            for (int mt = 0; mt < 4; ++mt)
                #pragma unroll
                for (int nt = 0; nt < 4; ++nt)
                    MMA(acc[mt][nt], ah[mt], bF[nt][0], bF[nt][1]);

            // ---- load A-lo, pass 2: Al * Bh ----
            #pragma unroll
            for (int mt = 0; mt < 4; ++mt) {
                uint32_t row = (uint32_t)(wm + mt * 16 + lrow);
                uint32_t ad = sb + 1u * TILE_B + swz(row, ckh); // tile 1 = Al
                LDSM4(al[mt][0], al[mt][1], al[mt][2], al[mt][3], ad);
            }
            #pragma unroll
            for (int mt = 0; mt < 4; ++mt)
                #pragma unroll
                for (int nt = 0; nt < 4; ++nt)
                    MMA(acc[mt][nt], al[mt], bF[nt][0], bF[nt][1]);

            // ---- load B-lo, pass 3: Ah * Bl ----
            #pragma unroll
            for (int np = 0; np < 2; ++np) {
                uint32_t row = (uint32_t)(wn + np * 16 + lrow);
                uint32_t ad = sb + 3u * TILE_B + swz(row, ckh); // tile 3 = Bl
                uint32_t q0, q1, q2, q3;
                LDSM4(q0, q1, q2, q3, ad);
                bF[2 * np][0] = q0; bF[2 * np + 1][0] = q1;
                bF[2 * np][1] = q2; bF[2 * np + 1][1] = q3;
            }
            #pragma unroll
            for (int mt = 0; mt < 4; ++mt)
                #pragma unroll
                for (int nt = 0; nt < 4; ++nt)
                    MMA(acc[mt][nt], ah[mt], bF[nt][0], bF[nt][1]);
        }
        __syncthreads();  // all warps done reading stage kt before it is reloaded
    }

    // ---------------- epilogue ----------------
    const long long oC = (long long)bz * sC;
    const int lm = lid >> 2, lc = (lid & 3) * 2;
    #pragma unroll
    for (int mt = 0; mt < 4; ++mt) {
        #pragma unroll
        for (int hrow = 0; hrow < 2; ++hrow) {
            const int row = m0 + wm + mt * 16 + lm + hrow * 8;
            #pragma unroll
            for (int nt = 0; nt < 4; ++nt) {
                const int col = n0 + wn + nt * 8 + lc;
                float d0 = acc[mt][nt][hrow * 2 + 0];
                float d1 = acc[mt][nt][hrow * 2 + 1];
                const long long idx = oC + (long long)row * N + col;
                if (OUT_HALF) {
                    __half h0, l0, h1, l1;
                    split_h(d0, h0, l0);
                    split_h(d1, h1, l1);
                    *(__half2*)&Ch[idx] = __halves2half2(h0, h1);
                    *(__half2*)&Cl[idx] = __halves2half2(l0, l1);
                } else {
                    if (bias) { d0 += bias[col]; d1 += bias[col + 1]; }
                    *(float2*)&Cf[idx] = make_float2(d0, d1);
                }
            }
        }
    }
}

// ---------------------------------------------------------------------------
// elementwise fp32 -> fp16 hi/lo split (vectorized by 4)
// ---------------------------------------------------------------------------
__global__ __launch_bounds__(256)
void split_kernel(const float* __restrict__ in, __half* __restrict__ h,
                  __half* __restrict__ l, long long n4)
{
    long long i = (long long)blockIdx.x * 256 + threadIdx.x;
    if (i >= n4) return;
    float4 v = ((const float4*)in)[i];
    __half h0, l0, h1, l1, h2, l2, h3, l3;
    split_h(v.x, h0, l0); split_h(v.y, h1, l1);
    split_h(v.z, h2, l2); split_h(v.w, h3, l3);
    ((__half2*)h)[2 * i]     = __halves2half2(h0, h1);
    ((__half2*)h)[2 * i + 1] = __halves2half2(h2, h3);
    ((__half2*)l)[2 * i]     = __halves2half2(l0, l1);
    ((__half2*)l)[2 * i + 1] = __halves2half2(l2, l3);
}

// ---------------------------------------------------------------------------
// per-batch transpose + split: V[b][s][d] fp32 -> Vt[b][d][s] fp16 hi/lo
// ---------------------------------------------------------------------------
__global__ __launch_bounds__(256)
void trans_split_kernel(const float* __restrict__ V, __half* __restrict__ Th,
                        __half* __restrict__ Tl, int S, int D)
{
    __shared__ float t[32][33];
    const int b = blockIdx.z;
    const int s0 = blockIdx.x * 32, d0 = blockIdx.y * 32;
    const float* Vb = V + (long long)b * S * D;
    #pragma unroll
    for (int i = 0; i < 4; ++i) {
        int s = threadIdx.y + i * 8;
        t[s][threadIdx.x] = Vb[(long long)(s0 + s) * D + d0 + threadIdx.x];
    }
    __syncthreads();
    const long long ob = (long long)b * D * S;
    #pragma unroll
    for (int i = 0; i < 4; ++i) {
        int d = threadIdx.y + i * 8;
        float v = t[threadIdx.x][d];
        __half h, l;
        split_h(v, h, l);
        const long long idx = ob + (long long)(d0 + d) * S + s0 + threadIdx.x;
        Th[idx] = h;
        Tl[idx] = l;
    }
}

// ---------------------------------------------------------------------------
// causal row softmax: read fp32 logits, write fp16 hi/lo probs (zero tail)
// ---------------------------------------------------------------------------
__global__ __launch_bounds__(256)
void softmax_causal_kernel(const float* __restrict__ P, __half* __restrict__ Ph,
                           __half* __restrict__ Pl, int S)
{
    const int b = blockIdx.y, i = blockIdx.x;
    const long long base = ((long long)b * S + i) * S;
    const float* row = P + base;
    const int n = i + 1;
    const int tid = threadIdx.x;
    __shared__ float red[8];

    float m = -3.4e38f;
    for (int j = tid; j < n; j += 256) m = fmaxf(m, row[j]);
    #pragma unroll
    for (int o = 16; o; o >>= 1) m = fmaxf(m, __shfl_xor_sync(~0u, m, o));
    if ((tid & 31) == 0) red[tid >> 5] = m;
    __syncthreads();
    if (tid < 32) {
        float v = (tid < 8) ? red[tid] : -3.4e38f;
        #pragma unroll
        for (int o = 4; o; o >>= 1) v = fmaxf(v, __shfl_xor_sync(~0u, v, o));
        if (tid == 0) red[0] = v;
    }
    __syncthreads();
    m = red[0];
    __syncthreads();

    float s = 0.f;
    for (int j = tid; j < n; j += 256) s += __expf(row[j] - m);
    #pragma unroll
    for (int o = 16; o; o >>= 1) s += __shfl_xor_sync(~0u, s, o);
    if ((tid & 31) == 0) red[tid >> 5] = s;
    __syncthreads();
    if (tid < 32) {
        float v = (tid < 8) ? red[tid] : 0.f;
        #pragma unroll
        for (int o = 4; o; o >>= 1) v += __shfl_xor_sync(~0u, v, o);
        if (tid == 0) red[0] = v;
    }
    __syncthreads();
    const float inv = 1.f / red[0];

    for (int j = tid; j < n; j += 256) {
        float p = __expf(row[j] - m) * inv;
        __half h, l;
        split_h(p, h, l);
        Ph[base + j] = h;
        Pl[base + j] = l;
    }
    const __half z = __float2half_rn(0.f);
    for (int j = n + tid; j < S; j += 256) {
        Ph[base + j] = z;
        Pl[base + j] = z;
    }
}

// ---------------------------------------------------------------------------
extern "C" void kernel_launch(void* const* d_in, const int* in_sizes, int n_in,
                              void* d_out, int out_size)
{
    const float* X  = (const float*)d_in[0];
    const float* WQ = (const float*)d_in[1];
    const float* WK = (const float*)d_in[2];
    const float* WV = (const float*)d_in[3];
    const float* WO = (const float*)d_in[4];
    const float* bO = (const float*)d_in[5];
    float* out = (float*)d_out;

    float *V, *P;
    __half *Xh, *Xl, *WQh, *WQl, *WKh, *WKl, *WVh, *WVl, *WOh, *WOl;
    __half *Qh, *Ql, *Kh, *Kl, *Vth, *Vtl, *Ph, *Pl, *Oh, *Ol;
    cudaGetSymbolAddress((void**)&V, g_V);
    cudaGetSymbolAddress((void**)&P, g_P);
    cudaGetSymbolAddress((void**)&Xh, g_Xh);   cudaGetSymbolAddress((void**)&Xl, g_Xl);
    cudaGetSymbolAddress((void**)&WQh, g_WQh); cudaGetSymbolAddress((void**)&WQl, g_WQl);
    cudaGetSymbolAddress((void**)&WKh, g_WKh); cudaGetSymbolAddress((void**)&WKl, g_WKl);
    cudaGetSymbolAddress((void**)&WVh, g_WVh); cudaGetSymbolAddress((void**)&WVl, g_WVl);
    cudaGetSymbolAddress((void**)&WOh, g_WOh); cudaGetSymbolAddress((void**)&WOl, g_WOl);
    cudaGetSymbolAddress((void**)&Qh, g_Qh);   cudaGetSymbolAddress((void**)&Ql, g_Ql);
    cudaGetSymbolAddress((void**)&Kh, g_Kh);   cudaGetSymbolAddress((void**)&Kl, g_Kl);
    cudaGetSymbolAddress((void**)&Vth, g_Vth); cudaGetSymbolAddress((void**)&Vtl, g_Vtl);
    cudaGetSymbolAddress((void**)&Ph, g_Ph);   cudaGetSymbolAddress((void**)&Pl, g_Pl);
    cudaGetSymbolAddress((void**)&Oh, g_Oh);   cudaGetSymbolAddress((void**)&Ol, g_Ol);

    cudaFuncSetAttribute(hmma_gemm<0>,
                         cudaFuncAttributeMaxDynamicSharedMemorySize, SMEM_TOTAL);
    cudaFuncSetAttribute(hmma_gemm<1>,
                         cudaFuncAttributeMaxDynamicSharedMemorySize, SMEM_TOTAL);

    const int B = 4, S = 2048, D = 1024, M = B * S;
    const long long SD = (long long)S * D;
    const long long SS = (long long)S * S;

    dim3 blk(256);

    // ---- split inputs into fp16 hi/lo ----
    split_kernel<<<(unsigned)((long long)M * D / 4 / 256), blk>>>(X, Xh, Xl, (long long)M * D / 4);
    split_kernel<<<D * D / 4 / 256, blk>>>(WQ, WQh, WQl, D * D / 4);
    split_kernel<<<D * D / 4 / 256, blk>>>(WK, WKh, WKl, D * D / 4);
    split_kernel<<<D * D / 4 / 256, blk>>>(WV, WVh, WVl, D * D / 4);
    split_kernel<<<D * D / 4 / 256, blk>>>(WO, WOh, WOl, D * D / 4);

    dim3 gproj(D / BN, M / BM, 1);
    // Q/K projections -> fp16 hi/lo directly
    hmma_gemm<1><<<gproj, blk, SMEM_TOTAL>>>(Xh, Xl, WQh, WQl, nullptr, Qh, Ql,
                                             nullptr, M, D, D, 0, 0, 0, 0);
    hmma_gemm<1><<<gproj, blk, SMEM_TOTAL>>>(Xh, Xl, WKh, WKl, nullptr, Kh, Kl,
                                             nullptr, M, D, D, 0, 0, 0, 0);
    // V projection -> fp32 (then transpose+split)
    hmma_gemm<0><<<gproj, blk, SMEM_TOTAL>>>(Xh, Xl, WVh, WVl, V, nullptr, nullptr,
                                             nullptr, M, D, D, 0, 0, 0, 0);
    trans_split_kernel<<<dim3(S / 32, D / 32, B), dim3(32, 8)>>>(V, Vth, Vtl, S, D);

    // logits: P[b] = Q[b] @ K[b]^T  (causal tile skip) -> fp32
    dim3 glog(S / BN, S / BM, B);
    hmma_gemm<0><<<glog, blk, SMEM_TOTAL>>>(Qh, Ql, Kh, Kl, P, nullptr, nullptr,
                                            nullptr, S, S, D, SD, SD, SS, 1);

    // causal softmax -> fp16 hi/lo probs (zero-filled tail)
    softmax_causal_kernel<<<dim3(S, B), blk>>>(P, Ph, Pl, S);

    // attn out: O[b] = P[b] @ V[b] = P[b] @ Vt[b]^T (NT, k-limited) -> fp16 hi/lo
    dim3 gpv(D / BN, S / BM, B);
    hmma_gemm<1><<<gpv, blk, SMEM_TOTAL>>>(Ph, Pl, Vth, Vtl, nullptr, Oh, Ol,
                                           nullptr, S, D, S, SS, SD, SD, 2);

    // output projection + bias -> fp32 out
    hmma_gemm<0><<<gproj, blk, SMEM_TOTAL>>>(Oh, Ol, WOh, WOl, out, nullptr, nullptr,
                                             bO, M, D, D, 0, 0, 0, 0);
}

// round 6
// speedup vs baseline: 2.9252x; 1.2201x over previous
#include <cuda_runtime.h>
#include <cuda_fp16.h>
#include <stdint.h>

#define BM 128
#define BN 128
#define BK 32
#define STAGES 4
#define TILE_B (BM * BK * 2)            // 8 KB per operand tile
#define STAGE_B (4 * TILE_B)            // 32 KB  (Ah, Al, Bh, Bl)
#define SMEM_TOTAL (STAGES * STAGE_B)   // 128 KB

// ---------------- scratch (device globals: allocation-free) ----------------
__device__ float  g_V[4LL * 2048 * 1024];
__device__ float  g_P[4LL * 2048 * 2048];
__device__ __half g_Xh[8192LL * 1024],  g_Xl[8192LL * 1024];
__device__ __half g_WQh[1024 * 1024],   g_WQl[1024 * 1024];
__device__ __half g_WKh[1024 * 1024],   g_WKl[1024 * 1024];
__device__ __half g_WVh[1024 * 1024],   g_WVl[1024 * 1024];
__device__ __half g_WOh[1024 * 1024],   g_WOl[1024 * 1024];
__device__ __half g_Qh[8192LL * 1024],  g_Ql[8192LL * 1024];
__device__ __half g_Kh[8192LL * 1024],  g_Kl[8192LL * 1024];
__device__ __half g_Vth[4LL * 1024 * 2048], g_Vtl[4LL * 1024 * 2048];
__device__ __half g_Ph[4LL * 2048 * 2048],  g_Pl[4LL * 2048 * 2048];
__device__ __half g_Oh[8192LL * 1024],  g_Ol[8192LL * 1024];

// ---------------- base-PTX helpers (NO tcgen05 / NO "a" features) ----------
__device__ __forceinline__ uint32_t smem_u32(const void* p) {
    uint32_t a;
    asm("{ .reg .u64 t; cvta.to.shared.u64 t, %1; cvt.u32.u64 %0, t; }"
        : "=r"(a) : "l"(p));
    return a;
}
#define CP_ASYNC16(sa, ga) \
    asm volatile("cp.async.cg.shared.global [%0], [%1], 16;" :: "r"(sa), "l"(ga))
#define CP_COMMIT() asm volatile("cp.async.commit_group;" ::: "memory")
#define CP_WAIT(n)  asm volatile("cp.async.wait_group %0;" :: "n"(n) : "memory")
#define LDSM4(d0, d1, d2, d3, a) \
    asm volatile("ldmatrix.sync.aligned.m8n8.x4.shared.b16 {%0,%1,%2,%3}, [%4];" \
                 : "=r"(d0), "=r"(d1), "=r"(d2), "=r"(d3) : "r"(a))
#define MMA(d, a, b0, b1) \
    asm volatile("mma.sync.aligned.m16n8k16.row.col.f32.f16.f16.f32 " \
                 "{%0,%1,%2,%3}, {%4,%5,%6,%7}, {%8,%9}, {%0,%1,%2,%3};" \
                 : "+f"((d)[0]), "+f"((d)[1]), "+f"((d)[2]), "+f"((d)[3]) \
                 : "r"((a)[0]), "r"((a)[1]), "r"((a)[2]), "r"((a)[3]), \
                   "r"(b0), "r"(b1))

// smem tile layout: [128 rows][4 chunks of 16B], chunk xor-swizzled.
__device__ __forceinline__ uint32_t swz(uint32_t r, uint32_t c) {
    return r * 64u + ((c ^ ((r >> 1) & 3u)) << 4);
}

__device__ __forceinline__ void split_h(float x, __half& h, __half& l) {
    h = __float2half_rn(x);
    l = __float2half_rn(x - __half2float(h));
}

// ---------------------------------------------------------------------------
// fp16x3 HMMA GEMM body:  C[m,n] = sum_k A[m,k] * B[n,k]  (NT, row-major)
//   passes==3: Ah*Bh + Al*Bh + Ah*Bl.  passes==2: Ah*Bh + Al*Bh.
// OUT_HALF 0: write fp32 C (+bias).  1: write fp16 hi/lo pair.
// ---------------------------------------------------------------------------
template <int OUT_HALF>
__device__ __forceinline__ void gemm_body(
    const __half* __restrict__ pAh, const __half* __restrict__ pAl,
    const __half* __restrict__ pBh, const __half* __restrict__ pBl,
    float* __restrict__ Cf, __half* __restrict__ Ch, __half* __restrict__ Cl,
    const float* __restrict__ bias,
    int N, int K, int kend, int m0, int n0, int passes)
{
    extern __shared__ char smem[];
    const int nk = kend / BK;

    const int tid = threadIdx.x;
    const int r0 = tid >> 2;        // 0..63
    const int c0 = tid & 3;         // 16B chunk within 64B row

    const __half* srcs[8];
    srcs[0] = pAh + (long long)(m0 + r0) * K + c0 * 8;
    srcs[1] = srcs[0] + 64LL * K;
    srcs[2] = pAl + (long long)(m0 + r0) * K + c0 * 8;
    srcs[3] = srcs[2] + 64LL * K;
    srcs[4] = pBh + (long long)(n0 + r0) * K + c0 * 8;
    srcs[5] = srcs[4] + 64LL * K;
    srcs[6] = pBl + (long long)(n0 + r0) * K + c0 * 8;
    srcs[7] = srcs[6] + 64LL * K;

    const uint32_t sbase = smem_u32(smem);
    const uint32_t w0 = swz((uint32_t)r0, (uint32_t)c0);
    const uint32_t w1 = w0 + 64u * 64u;
    uint32_t dsts[8];
    #pragma unroll
    for (int t = 0; t < 4; ++t) {
        dsts[2 * t]     = (uint32_t)t * TILE_B + w0;
        dsts[2 * t + 1] = (uint32_t)t * TILE_B + w1;
    }
    const int nload = (passes >= 3) ? 8 : 6;   // skip Bl tiles in 2-pass mode

    const int wid = tid >> 5, lid = tid & 31;
    const int wm = (wid >> 2) * 64;
    const int wn = (wid & 3) * 32;
    const int lrow = lid & 15;
    const int lkh  = lid >> 4;

    float acc[4][4][4] = {};

    #pragma unroll
    for (int s = 0; s < STAGES - 1; ++s) {
        if (s < nk) {
            const uint32_t st = sbase + (uint32_t)(s % STAGES) * STAGE_B;
            const long long ko = (long long)s * BK;
            #pragma unroll
            for (int j = 0; j < 8; ++j)
                if (j < nload) CP_ASYNC16(st + dsts[j], srcs[j] + ko);
        }
        CP_COMMIT();
    }

    for (int kt = 0; kt < nk; ++kt) {
        CP_WAIT(STAGES - 2);
        __syncthreads();   // stage kt visible; all threads past iter kt-1 compute

        const int nxt = kt + STAGES - 1;
        if (nxt < nk) {
            const uint32_t st = sbase + (uint32_t)(nxt % STAGES) * STAGE_B;
            const long long ko = (long long)nxt * BK;
            #pragma unroll
            for (int j = 0; j < 8; ++j)
                if (j < nload) CP_ASYNC16(st + dsts[j], srcs[j] + ko);
        }
        CP_COMMIT();

        const uint32_t sb = sbase + (uint32_t)(kt % STAGES) * STAGE_B;
        #pragma unroll
        for (int ks = 0; ks < 2; ++ks) {
            const uint32_t ckh = 2u * ks + (uint32_t)lkh;
            uint32_t ah[4][4], al[4][4], bF[4][2];

            #pragma unroll
            for (int mt = 0; mt < 4; ++mt) {
                uint32_t row = (uint32_t)(wm + mt * 16 + lrow);
                uint32_t ad = sb + swz(row, ckh);               // Ah
                LDSM4(ah[mt][0], ah[mt][1], ah[mt][2], ah[mt][3], ad);
            }
            #pragma unroll
            for (int np = 0; np < 2; ++np) {
                uint32_t row = (uint32_t)(wn + np * 16 + lrow);
                uint32_t ad = sb + 2u * TILE_B + swz(row, ckh); // Bh
                uint32_t q0, q1, q2, q3;
                LDSM4(q0, q1, q2, q3, ad);
                bF[2 * np][0] = q0; bF[2 * np + 1][0] = q1;
                bF[2 * np][1] = q2; bF[2 * np + 1][1] = q3;
            }
            #pragma unroll
            for (int mt = 0; mt < 4; ++mt)
                #pragma unroll
                for (int nt = 0; nt < 4; ++nt)
                    MMA(acc[mt][nt], ah[mt], bF[nt][0], bF[nt][1]);

            #pragma unroll
            for (int mt = 0; mt < 4; ++mt) {
                uint32_t row = (uint32_t)(wm + mt * 16 + lrow);
                uint32_t ad = sb + 1u * TILE_B + swz(row, ckh); // Al
                LDSM4(al[mt][0], al[mt][1], al[mt][2], al[mt][3], ad);
            }
            #pragma unroll
            for (int mt = 0; mt < 4; ++mt)
                #pragma unroll
                for (int nt = 0; nt < 4; ++nt)
                    MMA(acc[mt][nt], al[mt], bF[nt][0], bF[nt][1]);

            if (passes >= 3) {
                #pragma unroll
                for (int np = 0; np < 2; ++np) {
                    uint32_t row = (uint32_t)(wn + np * 16 + lrow);
                    uint32_t ad = sb + 3u * TILE_B + swz(row, ckh); // Bl
                    uint32_t q0, q1, q2, q3;
                    LDSM4(q0, q1, q2, q3, ad);
                    bF[2 * np][0] = q0; bF[2 * np + 1][0] = q1;
                    bF[2 * np][1] = q2; bF[2 * np + 1][1] = q3;
                }
                #pragma unroll
                for (int mt = 0; mt < 4; ++mt)
                    #pragma unroll
                    for (int nt = 0; nt < 4; ++nt)
                        MMA(acc[mt][nt], ah[mt], bF[nt][0], bF[nt][1]);
            }
        }
        // NOTE: no bottom barrier — the top barrier of the next iteration
        // orders "all compute of kt done" before stage kt's slot is rewritten.
    }

    const int lm = lid >> 2, lc = (lid & 3) * 2;
    #pragma unroll
    for (int mt = 0; mt < 4; ++mt) {
        #pragma unroll
        for (int hrow = 0; hrow < 2; ++hrow) {
            const int row = m0 + wm + mt * 16 + lm + hrow * 8;
            #pragma unroll
            for (int nt = 0; nt < 4; ++nt) {
                const int col = n0 + wn + nt * 8 + lc;
                float d0 = acc[mt][nt][hrow * 2 + 0];
                float d1 = acc[mt][nt][hrow * 2 + 1];
                const long long idx = (long long)row * N + col;
                if (OUT_HALF) {
                    __half h0, l0, h1, l1;
                    split_h(d0, h0, l0);
                    split_h(d1, h1, l1);
                    *(__half2*)&Ch[idx] = __halves2half2(h0, h1);
                    *(__half2*)&Cl[idx] = __halves2half2(l0, l1);
                } else {
                    if (bias) { d0 += bias[col]; d1 += bias[col + 1]; }
                    *(float2*)&Cf[idx] = make_float2(d0, d1);
                }
            }
        }
    }
}

// ---------------------------------------------------------------------------
// Generic wrapper. mode 0: plain  mode 1: causal tile skip  mode 2: k-limit
// (bm reversed so heavy CTAs launch first).
// ---------------------------------------------------------------------------
template <int OUT_HALF>
__global__ __launch_bounds__(256, 1)
void hmma_gemm(const __half* __restrict__ pAh, const __half* __restrict__ pAl,
               const __half* __restrict__ pBh, const __half* __restrict__ pBl,
               float* __restrict__ Cf, __half* __restrict__ Ch,
               __half* __restrict__ Cl, const float* __restrict__ bias,
               int M, int N, int K,
               long long sA, long long sB, long long sC, int mode, int passes)
{
    const int bn = blockIdx.x, bz = blockIdx.z;
    int bm = blockIdx.y;
    if (mode == 1 && bn > bm) return;
    if (mode == 2) bm = gridDim.y - 1 - blockIdx.y;
    const int kend = (mode == 2) ? (bm * BM + BM) : K;

    gemm_body<OUT_HALF>(pAh + (long long)bz * sA, pAl + (long long)bz * sA,
                        pBh + (long long)bz * sB, pBl + (long long)bz * sB,
                        OUT_HALF ? nullptr : Cf + (long long)bz * sC,
                        OUT_HALF ? Ch + (long long)bz * sC : nullptr,
                        OUT_HALF ? Cl + (long long)bz * sC : nullptr,
                        bias, N, K, kend, bm * BM, bn * BN, passes);
}

// ---------------------------------------------------------------------------
// Merged Q/K/V projection: blockIdx.z selects the weight + output.
// Q,K -> fp16 hi/lo (3-pass).  V -> fp32 (2-pass).
// ---------------------------------------------------------------------------
__global__ __launch_bounds__(256, 1)
void qkv_gemm(const __half* __restrict__ Xh, const __half* __restrict__ Xl,
              const __half* __restrict__ WQh, const __half* __restrict__ WQl,
              const __half* __restrict__ WKh, const __half* __restrict__ WKl,
              const __half* __restrict__ WVh, const __half* __restrict__ WVl,
              __half* __restrict__ Qh, __half* __restrict__ Ql,
              __half* __restrict__ Kh, __half* __restrict__ Kl,
              float* __restrict__ Vf, int N, int K)
{
    const int m0 = blockIdx.y * BM, n0 = blockIdx.x * BN, bz = blockIdx.z;
    if (bz == 0)
        gemm_body<1>(Xh, Xl, WQh, WQl, nullptr, Qh, Ql, nullptr,
                     N, K, K, m0, n0, 3);
    else if (bz == 1)
        gemm_body<1>(Xh, Xl, WKh, WKl, nullptr, Kh, Kl, nullptr,
                     N, K, K, m0, n0, 3);
    else
        gemm_body<0>(Xh, Xl, WVh, WVl, Vf, nullptr, nullptr, nullptr,
                     N, K, K, m0, n0, 2);
}

// ---------------------------------------------------------------------------
__global__ __launch_bounds__(256)
void split_kernel(const float* __restrict__ in, __half* __restrict__ h,
                  __half* __restrict__ l, long long n4)
{
    long long i = (long long)blockIdx.x * 256 + threadIdx.x;
    if (i >= n4) return;
    float4 v = ((const float4*)in)[i];
    __half h0, l0, h1, l1, h2, l2, h3, l3;
    split_h(v.x, h0, l0); split_h(v.y, h1, l1);
    split_h(v.z, h2, l2); split_h(v.w, h3, l3);
    ((__half2*)h)[2 * i]     = __halves2half2(h0, h1);
    ((__half2*)h)[2 * i + 1] = __halves2half2(h2, h3);
    ((__half2*)l)[2 * i]     = __halves2half2(l0, l1);
    ((__half2*)l)[2 * i + 1] = __halves2half2(l2, l3);
}

__global__ __launch_bounds__(256)
void trans_split_kernel(const float* __restrict__ V, __half* __restrict__ Th,
                        __half* __restrict__ Tl, int S, int D)
{
    __shared__ float t[32][33];
    const int b = blockIdx.z;
    const int s0 = blockIdx.x * 32, d0 = blockIdx.y * 32;
    const float* Vb = V + (long long)b * S * D;
    #pragma unroll
    for (int i = 0; i < 4; ++i) {
        int s = threadIdx.y + i * 8;
        t[s][threadIdx.x] = Vb[(long long)(s0 + s) * D + d0 + threadIdx.x];
    }
    __syncthreads();
    const long long ob = (long long)b * D * S;
    #pragma unroll
    for (int i = 0; i < 4; ++i) {
        int d = threadIdx.y + i * 8;
        float v = t[threadIdx.x][d];
        __half h, l;
        split_h(v, h, l);
        const long long idx = ob + (long long)(d0 + d) * S + s0 + threadIdx.x;
        Th[idx] = h;
        Tl[idx] = l;
    }
}

__global__ __launch_bounds__(256)
void softmax_causal_kernel(const float* __restrict__ P, __half* __restrict__ Ph,
                           __half* __restrict__ Pl, int S)
{
    const int b = blockIdx.y, i = blockIdx.x;
    const long long base = ((long long)b * S + i) * S;
    const float* row = P + base;
    const int n = i + 1;
    const int tid = threadIdx.x;
    __shared__ float red[8];

    float m = -3.4e38f;
    for (int j = tid; j < n; j += 256) m = fmaxf(m, row[j]);
    #pragma unroll
    for (int o = 16; o; o >>= 1) m = fmaxf(m, __shfl_xor_sync(~0u, m, o));
    if ((tid & 31) == 0) red[tid >> 5] = m;
    __syncthreads();
    if (tid < 32) {
        float v = (tid < 8) ? red[tid] : -3.4e38f;
        #pragma unroll
        for (int o = 4; o; o >>= 1) v = fmaxf(v, __shfl_xor_sync(~0u, v, o));
        if (tid == 0) red[0] = v;
    }
    __syncthreads();
    m = red[0];
    __syncthreads();

    float s = 0.f;
    for (int j = tid; j < n; j += 256) s += __expf(row[j] - m);
    #pragma unroll
    for (int o = 16; o; o >>= 1) s += __shfl_xor_sync(~0u, s, o);
    if ((tid & 31) == 0) red[tid >> 5] = s;
    __syncthreads();
    if (tid < 32) {
        float v = (tid < 8) ? red[tid] : 0.f;
        #pragma unroll
        for (int o = 4; o; o >>= 1) v += __shfl_xor_sync(~0u, v, o);
        if (tid == 0) red[0] = v;
    }
    __syncthreads();
    const float inv = 1.f / red[0];

    for (int j = tid; j < n; j += 256) {
        float p = __expf(row[j] - m) * inv;
        __half h, l;
        split_h(p, h, l);
        Ph[base + j] = h;
        Pl[base + j] = l;
    }
    const __half z = __float2half_rn(0.f);
    for (int j = n + tid; j < S; j += 256) {
        Ph[base + j] = z;
        Pl[base + j] = z;
    }
}

// ---------------------------------------------------------------------------
extern "C" void kernel_launch(void* const* d_in, const int* in_sizes, int n_in,
                              void* d_out, int out_size)
{
    const float* X  = (const float*)d_in[0];
    const float* WQ = (const float*)d_in[1];
    const float* WK = (const float*)d_in[2];
    const float* WV = (const float*)d_in[3];
    const float* WO = (const float*)d_in[4];
    const float* bO = (const float*)d_in[5];
    float* out = (float*)d_out;

    float *V, *P;
    __half *Xh, *Xl, *WQh, *WQl, *WKh, *WKl, *WVh, *WVl, *WOh, *WOl;
    __half *Qh, *Ql, *Kh, *Kl, *Vth, *Vtl, *Ph, *Pl, *Oh, *Ol;
    cudaGetSymbolAddress((void**)&V, g_V);
    cudaGetSymbolAddress((void**)&P, g_P);
    cudaGetSymbolAddress((void**)&Xh, g_Xh);   cudaGetSymbolAddress((void**)&Xl, g_Xl);
    cudaGetSymbolAddress((void**)&WQh, g_WQh); cudaGetSymbolAddress((void**)&WQl, g_WQl);
    cudaGetSymbolAddress((void**)&WKh, g_WKh); cudaGetSymbolAddress((void**)&WKl, g_WKl);
    cudaGetSymbolAddress((void**)&WVh, g_WVh); cudaGetSymbolAddress((void**)&WVl, g_WVl);
    cudaGetSymbolAddress((void**)&WOh, g_WOh); cudaGetSymbolAddress((void**)&WOl, g_WOl);
    cudaGetSymbolAddress((void**)&Qh, g_Qh);   cudaGetSymbolAddress((void**)&Ql, g_Ql);
    cudaGetSymbolAddress((void**)&Kh, g_Kh);   cudaGetSymbolAddress((void**)&Kl, g_Kl);
    cudaGetSymbolAddress((void**)&Vth, g_Vth); cudaGetSymbolAddress((void**)&Vtl, g_Vtl);
    cudaGetSymbolAddress((void**)&Ph, g_Ph);   cudaGetSymbolAddress((void**)&Pl, g_Pl);
    cudaGetSymbolAddress((void**)&Oh, g_Oh);   cudaGetSymbolAddress((void**)&Ol, g_Ol);

    cudaFuncSetAttribute(hmma_gemm<0>,
                         cudaFuncAttributeMaxDynamicSharedMemorySize, SMEM_TOTAL);
    cudaFuncSetAttribute(hmma_gemm<1>,
                         cudaFuncAttributeMaxDynamicSharedMemorySize, SMEM_TOTAL);
    cudaFuncSetAttribute(qkv_gemm,
                         cudaFuncAttributeMaxDynamicSharedMemorySize, SMEM_TOTAL);

    const int B = 4, S = 2048, D = 1024, M = B * S;
    const long long SD = (long long)S * D;
    const long long SS = (long long)S * S;

    dim3 blk(256);

    // ---- split inputs into fp16 hi/lo ----
    split_kernel<<<(unsigned)((long long)M * D / 4 / 256), blk>>>(X, Xh, Xl, (long long)M * D / 4);
    split_kernel<<<D * D / 4 / 256, blk>>>(WQ, WQh, WQl, D * D / 4);
    split_kernel<<<D * D / 4 / 256, blk>>>(WK, WKh, WKl, D * D / 4);
    split_kernel<<<D * D / 4 / 256, blk>>>(WV, WVh, WVl, D * D / 4);
    split_kernel<<<D * D / 4 / 256, blk>>>(WO, WOh, WOl, D * D / 4);

    // merged Q/K/V projections (Q,K 3-pass fp16 out; V 2-pass fp32 out)
    dim3 gqkv(D / BN, M / BM, 3);
    qkv_gemm<<<gqkv, blk, SMEM_TOTAL>>>(Xh, Xl, WQh, WQl, WKh, WKl, WVh, WVl,
                                        Qh, Ql, Kh, Kl, V, D, D);
    trans_split_kernel<<<dim3(S / 32, D / 32, B), dim3(32, 8)>>>(V, Vth, Vtl, S, D);

    // logits: P[b] = Q[b] @ K[b]^T  (causal tile skip, 3-pass)
    dim3 glog(S / BN, S / BM, B);
    hmma_gemm<0><<<glog, blk, SMEM_TOTAL>>>(Qh, Ql, Kh, Kl, P, nullptr, nullptr,
                                            nullptr, S, S, D, SD, SD, SS, 1, 3);

    // causal softmax -> fp16 hi/lo probs (zero-filled tail)
    softmax_causal_kernel<<<dim3(S, B), blk>>>(P, Ph, Pl, S);

    // attn out: O[b] = P[b] @ Vt[b]^T (NT, k-limited, heavy tiles first, 3-pass)
    dim3 gpv(D / BN, S / BM, B);
    hmma_gemm<1><<<gpv, blk, SMEM_TOTAL>>>(Ph, Pl, Vth, Vtl, nullptr, Oh, Ol,
                                           nullptr, S, D, S, SS, SD, SD, 2, 3);

    // output projection + bias -> fp32 out (2-pass)
    dim3 gproj(D / BN, M / BM, 1);
    hmma_gemm<0><<<gproj, blk, SMEM_TOTAL>>>(Oh, Ol, WOh, WOl, out, nullptr, nullptr,
                                             bO, M, D, D, 0, 0, 0, 0, 2);
}

// round 7
// speedup vs baseline: 3.1345x; 1.0715x over previous
#include <cuda_runtime.h>
#include <cuda_fp16.h>
#include <stdint.h>

#define BM 128
#define BN 128
#define BK 32
#define STAGES 4
#define TILE_B (BM * BK * 2)            // 8 KB per operand tile
#define STAGE_B (4 * TILE_B)            // 32 KB  (Ah, Al, Bh, Bl)
#define SMEM_TOTAL (STAGES * STAGE_B)   // 128 KB

// ---------------- scratch (device globals: allocation-free) ----------------
__device__ float  g_V[4LL * 2048 * 1024];
__device__ float  g_P[4LL * 2048 * 2048];
__device__ __half g_Xh[8192LL * 1024],  g_Xl[8192LL * 1024];
__device__ __half g_WQh[1024 * 1024],   g_WQl[1024 * 1024];
__device__ __half g_WKh[1024 * 1024],   g_WKl[1024 * 1024];
__device__ __half g_WVh[1024 * 1024],   g_WVl[1024 * 1024];
__device__ __half g_WOh[1024 * 1024],   g_WOl[1024 * 1024];
__device__ __half g_Qh[8192LL * 1024],  g_Ql[8192LL * 1024];
__device__ __half g_Kh[8192LL * 1024],  g_Kl[8192LL * 1024];
__device__ __half g_Vth[4LL * 1024 * 2048];
__device__ __half g_Ph[4LL * 2048 * 2048],  g_Pl[4LL * 2048 * 2048];
__device__ __half g_Oh[8192LL * 1024],  g_Ol[8192LL * 1024];

// ---------------- base-PTX helpers ----------------
__device__ __forceinline__ uint32_t smem_u32(const void* p) {
    uint32_t a;
    asm("{ .reg .u64 t; cvta.to.shared.u64 t, %1; cvt.u32.u64 %0, t; }"
        : "=r"(a) : "l"(p));
    return a;
}
#define CP_ASYNC16(sa, ga) \
    asm volatile("cp.async.cg.shared.global [%0], [%1], 16;" :: "r"(sa), "l"(ga))
#define CP_COMMIT() asm volatile("cp.async.commit_group;" ::: "memory")
#define CP_WAIT(n)  asm volatile("cp.async.wait_group %0;" :: "n"(n) : "memory")
#define LDSM4(d0, d1, d2, d3, a) \
    asm volatile("ldmatrix.sync.aligned.m8n8.x4.shared.b16 {%0,%1,%2,%3}, [%4];" \
                 : "=r"(d0), "=r"(d1), "=r"(d2), "=r"(d3) : "r"(a))
#define MMA(d, a, b0, b1) \
    asm volatile("mma.sync.aligned.m16n8k16.row.col.f32.f16.f16.f32 " \
                 "{%0,%1,%2,%3}, {%4,%5,%6,%7}, {%8,%9}, {%0,%1,%2,%3};" \
                 : "+f"((d)[0]), "+f"((d)[1]), "+f"((d)[2]), "+f"((d)[3]) \
                 : "r"((a)[0]), "r"((a)[1]), "r"((a)[2]), "r"((a)[3]), \
                   "r"(b0), "r"(b1))

// smem tile layout: [128 rows][4 chunks of 16B], chunk xor-swizzled.
__device__ __forceinline__ uint32_t swz(uint32_t r, uint32_t c) {
    return r * 64u + ((c ^ ((r >> 1) & 3u)) << 4);
}

__device__ __forceinline__ void split_h(float x, __half& h, __half& l) {
    h = __float2half_rn(x);
    l = __float2half_rn(x - __half2float(h));
}

// ---------------------------------------------------------------------------
// fp16x3 HMMA GEMM body:  C[m,n] = sum_k A[m,k] * B[n,k]  (NT, row-major)
//   passes==3: Ah*Bh + Al*Bh + Ah*Bl.  passes==2: Ah*Bh + Al*Bh (Bl unused).
// OUT_HALF 0: write fp32 C (+bias).  1: write fp16 hi/lo pair.
// ---------------------------------------------------------------------------
template <int OUT_HALF>
__device__ __forceinline__ void gemm_body(
    const __half* __restrict__ pAh, const __half* __restrict__ pAl,
    const __half* __restrict__ pBh, const __half* __restrict__ pBl,
    float* __restrict__ Cf, __half* __restrict__ Ch, __half* __restrict__ Cl,
    const float* __restrict__ bias,
    int N, int K, int kend, int m0, int n0, int passes)
{
    extern __shared__ char smem[];
    const int nk = kend / BK;

    const int tid = threadIdx.x;
    const int r0 = tid >> 2;        // 0..63
    const int c0 = tid & 3;         // 16B chunk within 64B row

    const __half* srcs[8];
    srcs[0] = pAh + (long long)(m0 + r0) * K + c0 * 8;
    srcs[1] = srcs[0] + 64LL * K;
    srcs[2] = pAl + (long long)(m0 + r0) * K + c0 * 8;
    srcs[3] = srcs[2] + 64LL * K;
    srcs[4] = pBh + (long long)(n0 + r0) * K + c0 * 8;
    srcs[5] = srcs[4] + 64LL * K;
    srcs[6] = pBl + (long long)(n0 + r0) * K + c0 * 8;
    srcs[7] = srcs[6] + 64LL * K;

    const uint32_t sbase = smem_u32(smem);
    const uint32_t w0 = swz((uint32_t)r0, (uint32_t)c0);
    const uint32_t w1 = w0 + 64u * 64u;
    uint32_t dsts[8];
    #pragma unroll
    for (int t = 0; t < 4; ++t) {
        dsts[2 * t]     = (uint32_t)t * TILE_B + w0;
        dsts[2 * t + 1] = (uint32_t)t * TILE_B + w1;
    }
    const int nload = (passes >= 3) ? 8 : 6;   // skip Bl tiles in 2-pass mode

    const int wid = tid >> 5, lid = tid & 31;
    const int wm = (wid >> 2) * 64;
    const int wn = (wid & 3) * 32;
    const int lrow = lid & 15;
    const int lkh  = lid >> 4;

    float acc[4][4][4] = {};

    #pragma unroll
    for (int s = 0; s < STAGES - 1; ++s) {
        if (s < nk) {
            const uint32_t st = sbase + (uint32_t)(s % STAGES) * STAGE_B;
            const long long ko = (long long)s * BK;
            #pragma unroll
            for (int j = 0; j < 8; ++j)
                if (j < nload) CP_ASYNC16(st + dsts[j], srcs[j] + ko);
        }
        CP_COMMIT();
    }

    for (int kt = 0; kt < nk; ++kt) {
        CP_WAIT(STAGES - 2);
        __syncthreads();   // stage kt visible; all threads past iter kt-1 compute

        const int nxt = kt + STAGES - 1;
        if (nxt < nk) {
            const uint32_t st = sbase + (uint32_t)(nxt % STAGES) * STAGE_B;
            const long long ko = (long long)nxt * BK;
            #pragma unroll
            for (int j = 0; j < 8; ++j)
                if (j < nload) CP_ASYNC16(st + dsts[j], srcs[j] + ko);
        }
        CP_COMMIT();

        const uint32_t sb = sbase + (uint32_t)(kt % STAGES) * STAGE_B;
        #pragma unroll
        for (int ks = 0; ks < 2; ++ks) {
            const uint32_t ckh = 2u * ks + (uint32_t)lkh;
            uint32_t ah[4][4], al[4][4], bF[4][2];

            #pragma unroll
            for (int mt = 0; mt < 4; ++mt) {
                uint32_t row = (uint32_t)(wm + mt * 16 + lrow);
                uint32_t ad = sb + swz(row, ckh);               // Ah
                LDSM4(ah[mt][0], ah[mt][1], ah[mt][2], ah[mt][3], ad);
            }
            #pragma unroll
            for (int np = 0; np < 2; ++np) {
                uint32_t row = (uint32_t)(wn + np * 16 + lrow);
                uint32_t ad = sb + 2u * TILE_B + swz(row, ckh); // Bh
                uint32_t q0, q1, q2, q3;
                LDSM4(q0, q1, q2, q3, ad);
                bF[2 * np][0] = q0; bF[2 * np + 1][0] = q1;
                bF[2 * np][1] = q2; bF[2 * np + 1][1] = q3;
            }
            #pragma unroll
            for (int mt = 0; mt < 4; ++mt)
                #pragma unroll
                for (int nt = 0; nt < 4; ++nt)
                    MMA(acc[mt][nt], ah[mt], bF[nt][0], bF[nt][1]);

            #pragma unroll
            for (int mt = 0; mt < 4; ++mt) {
                uint32_t row = (uint32_t)(wm + mt * 16 + lrow);
                uint32_t ad = sb + 1u * TILE_B + swz(row, ckh); // Al
                LDSM4(al[mt][0], al[mt][1], al[mt][2], al[mt][3], ad);
            }
            #pragma unroll
            for (int mt = 0; mt < 4; ++mt)
                #pragma unroll
                for (int nt = 0; nt < 4; ++nt)
                    MMA(acc[mt][nt], al[mt], bF[nt][0], bF[nt][1]);

            if (passes >= 3) {
                #pragma unroll
                for (int np = 0; np < 2; ++np) {
                    uint32_t row = (uint32_t)(wn + np * 16 + lrow);
                    uint32_t ad = sb + 3u * TILE_B + swz(row, ckh); // Bl
                    uint32_t q0, q1, q2, q3;
                    LDSM4(q0, q1, q2, q3, ad);
                    bF[2 * np][0] = q0; bF[2 * np + 1][0] = q1;
                    bF[2 * np][1] = q2; bF[2 * np + 1][1] = q3;
                }
                #pragma unroll
                for (int mt = 0; mt < 4; ++mt)
                    #pragma unroll
                    for (int nt = 0; nt < 4; ++nt)
                        MMA(acc[mt][nt], ah[mt], bF[nt][0], bF[nt][1]);
            }
        }
        // no bottom barrier: next iteration's top barrier orders reuse
    }

    const int lm = lid >> 2, lc = (lid & 3) * 2;
    #pragma unroll
    for (int mt = 0; mt < 4; ++mt) {
        #pragma unroll
        for (int hrow = 0; hrow < 2; ++hrow) {
            const int row = m0 + wm + mt * 16 + lm + hrow * 8;
            #pragma unroll
            for (int nt = 0; nt < 4; ++nt) {
                const int col = n0 + wn + nt * 8 + lc;
                float d0 = acc[mt][nt][hrow * 2 + 0];
                float d1 = acc[mt][nt][hrow * 2 + 1];
                const long long idx = (long long)row * N + col;
                if (OUT_HALF) {
                    __half h0, l0, h1, l1;
                    split_h(d0, h0, l0);
                    split_h(d1, h1, l1);
                    *(__half2*)&Ch[idx] = __halves2half2(h0, h1);
                    *(__half2*)&Cl[idx] = __halves2half2(l0, l1);
                } else {
                    if (bias) { d0 += bias[col]; d1 += bias[col + 1]; }
                    *(float2*)&Cf[idx] = make_float2(d0, d1);
                }
            }
        }
    }
}

// ---------------------------------------------------------------------------
// mode 0: plain  mode 1: causal tile skip  mode 2: k-limit (heavy tiles first)
// ---------------------------------------------------------------------------
template <int OUT_HALF>
__global__ __launch_bounds__(256, 1)
void hmma_gemm(const __half* __restrict__ pAh, const __half* __restrict__ pAl,
               const __half* __restrict__ pBh, const __half* __restrict__ pBl,
               float* __restrict__ Cf, __half* __restrict__ Ch,
               __half* __restrict__ Cl, const float* __restrict__ bias,
               int M, int N, int K,
               long long sA, long long sB, long long sC, int mode, int passes)
{
    const int bn = blockIdx.x, bz = blockIdx.z;
    int bm = blockIdx.y;
    if (mode == 1 && bn > bm) return;
    if (mode == 2) bm = gridDim.y - 1 - blockIdx.y;
    const int kend = (mode == 2) ? (bm * BM + BM) : K;

    gemm_body<OUT_HALF>(pAh + (long long)bz * sA, pAl + (long long)bz * sA,
                        pBh + (long long)bz * sB, pBl + (long long)bz * sB,
                        OUT_HALF ? nullptr : Cf + (long long)bz * sC,
                        OUT_HALF ? Ch + (long long)bz * sC : nullptr,
                        OUT_HALF ? Cl + (long long)bz * sC : nullptr,
                        bias, N, K, kend, bm * BM, bn * BN, passes);
}

// ---------------------------------------------------------------------------
// Merged Q/K/V projection: blockIdx.z selects the weight + output.
// Q,K -> fp16 hi/lo (3-pass).  V -> fp32 (2-pass).
// ---------------------------------------------------------------------------
__global__ __launch_bounds__(256, 1)
void qkv_gemm(const __half* __restrict__ Xh, const __half* __restrict__ Xl,
              const __half* __restrict__ WQh, const __half* __restrict__ WQl,
              const __half* __restrict__ WKh, const __half* __restrict__ WKl,
              const __half* __restrict__ WVh, const __half* __restrict__ WVl,
              __half* __restrict__ Qh, __half* __restrict__ Ql,
              __half* __restrict__ Kh, __half* __restrict__ Kl,
              float* __restrict__ Vf, int N, int K)
{
    const int m0 = blockIdx.y * BM, n0 = blockIdx.x * BN, bz = blockIdx.z;
    if (bz == 0)
        gemm_body<1>(Xh, Xl, WQh, WQl, nullptr, Qh, Ql, nullptr,
                     N, K, K, m0, n0, 3);
    else if (bz == 1)
        gemm_body<1>(Xh, Xl, WKh, WKl, nullptr, Kh, Kl, nullptr,
                     N, K, K, m0, n0, 3);
    else
        gemm_body<0>(Xh, Xl, WVh, WVl, Vf, nullptr, nullptr, nullptr,
                     N, K, K, m0, n0, 2);
}

// ---------------------------------------------------------------------------
// Merged fp32 -> fp16 hi/lo split for X + the 4 weight matrices (one launch).
// blocks [0, nbX) -> X ; then 4 chunks of nbW blocks for WQ, WK, WV, WO.
// ---------------------------------------------------------------------------
__global__ __launch_bounds__(256)
void split_all_kernel(const float* __restrict__ X, const float* __restrict__ WQ,
                      const float* __restrict__ WK, const float* __restrict__ WV,
                      const float* __restrict__ WO,
                      __half* __restrict__ Xh, __half* __restrict__ Xl,
                      __half* __restrict__ WQh, __half* __restrict__ WQl,
                      __half* __restrict__ WKh, __half* __restrict__ WKl,
                      __half* __restrict__ WVh, __half* __restrict__ WVl,
                      __half* __restrict__ WOh, __half* __restrict__ WOl,
                      int nbX, int nbW)
{
    const float* in;
    __half *h, *l;
    long long i;
    int bid = blockIdx.x;
    if (bid < nbX) {
        in = X; h = Xh; l = Xl;
        i = (long long)bid * 256 + threadIdx.x;
    } else {
        int w = (bid - nbX) / nbW;
        int rb = (bid - nbX) - w * nbW;
        in = (w == 0) ? WQ : (w == 1) ? WK : (w == 2) ? WV : WO;
        h  = (w == 0) ? WQh : (w == 1) ? WKh : (w == 2) ? WVh : WOh;
        l  = (w == 0) ? WQl : (w == 1) ? WKl : (w == 2) ? WVl : WOl;
        i = (long long)rb * 256 + threadIdx.x;
    }
    float4 v = ((const float4*)in)[i];
    __half h0, l0, h1, l1, h2, l2, h3, l3;
    split_h(v.x, h0, l0); split_h(v.y, h1, l1);
    split_h(v.z, h2, l2); split_h(v.w, h3, l3);
    ((__half2*)h)[2 * i]     = __halves2half2(h0, h1);
    ((__half2*)h)[2 * i + 1] = __halves2half2(h2, h3);
    ((__half2*)l)[2 * i]     = __halves2half2(l0, l1);
    ((__half2*)l)[2 * i + 1] = __halves2half2(l2, l3);
}

// ---------------------------------------------------------------------------
// per-batch transpose: V[b][s][d] fp32 -> Vt[b][d][s] fp16 (hi only; the
// lo residual of V is dropped by the 2-pass P@V GEMM anyway)
// ---------------------------------------------------------------------------
__global__ __launch_bounds__(256)
void trans_split_kernel(const float* __restrict__ V, __half* __restrict__ Th,
                        int S, int D)
{
    __shared__ float t[32][33];
    const int b = blockIdx.z;
    const int s0 = blockIdx.x * 32, d0 = blockIdx.y * 32;
    const float* Vb = V + (long long)b * S * D;
    #pragma unroll
    for (int i = 0; i < 4; ++i) {
        int s = threadIdx.y + i * 8;
        t[s][threadIdx.x] = Vb[(long long)(s0 + s) * D + d0 + threadIdx.x];
    }
    __syncthreads();
    const long long ob = (long long)b * D * S;
    #pragma unroll
    for (int i = 0; i < 4; ++i) {
        int d = threadIdx.y + i * 8;
        Th[ob + (long long)(d0 + d) * S + s0 + threadIdx.x] =
            __float2half_rn(t[threadIdx.x][d]);
    }
}

// ---------------------------------------------------------------------------
// Causal row softmax. Register-cached (1 gmem read, 1 exp per element).
// Writes fp16 hi/lo probs for j <= i; zero-fills ONLY the diagonal 128-band
// (j in [i+1, ceil128(i+1)) ) — all the k-limited P@V GEMM can ever read.
// ---------------------------------------------------------------------------
__global__ __launch_bounds__(256)
void softmax_causal_kernel(const float* __restrict__ P, __half* __restrict__ Ph,
                           __half* __restrict__ Pl, int S)
{
    const int b = blockIdx.y, i = blockIdx.x;
    const long long base = ((long long)b * S + i) * S;
    const float* row = P + base;
    const int n = i + 1;
    const int tid = threadIdx.x;
    __shared__ float red[8];

    float v[8];
    const int nt = (n + 255) >> 8;       // per-thread element count bound

    // --- load + row max ---
    float m = -3.4e38f;
    #pragma unroll
    for (int t = 0; t < 8; ++t) {
        if (t < nt) {
            int j = t * 256 + tid;
            v[t] = (j < n) ? row[j] : -3.4e38f;
            m = fmaxf(m, v[t]);
        }
    }
    #pragma unroll
    for (int o = 16; o; o >>= 1) m = fmaxf(m, __shfl_xor_sync(~0u, m, o));
    if ((tid & 31) == 0) red[tid >> 5] = m;
    __syncthreads();
    if (tid < 32) {
        float x = (tid < 8) ? red[tid] : -3.4e38f;
        #pragma unroll
        for (int o = 4; o; o >>= 1) x = fmaxf(x, __shfl_xor_sync(~0u, x, o));
        if (tid == 0) red[0] = x;
    }
    __syncthreads();
    m = red[0];
    __syncthreads();

    // --- exp + sum (exp computed once, kept in registers) ---
    float s = 0.f;
    #pragma unroll
    for (int t = 0; t < 8; ++t) {
        if (t < nt) {
            int j = t * 256 + tid;
            v[t] = (j < n) ? __expf(v[t] - m) : 0.f;
            s += v[t];
        }
    }
    #pragma unroll
    for (int o = 16; o; o >>= 1) s += __shfl_xor_sync(~0u, s, o);
    if ((tid & 31) == 0) red[tid >> 5] = s;
    __syncthreads();
    if (tid < 32) {
        float x = (tid < 8) ? red[tid] : 0.f;
        #pragma unroll
        for (int o = 4; o; o >>= 1) x += __shfl_xor_sync(~0u, x, o);
        if (tid == 0) red[0] = x;
    }
    __syncthreads();
    const float inv = 1.f / red[0];

    // --- write probs ---
    #pragma unroll
    for (int t = 0; t < 8; ++t) {
        if (t < nt) {
            int j = t * 256 + tid;
            if (j < n) {
                __half h, l;
                split_h(v[t] * inv, h, l);
                Ph[base + j] = h;
                Pl[base + j] = l;
            }
        }
    }
    // --- zero only the diagonal band tail ---
    const int band_end = (i & ~127) + 128;
    const __half z = __float2half_rn(0.f);
    for (int j = n + tid; j < band_end; j += 256) {
        Ph[base + j] = z;
        Pl[base + j] = z;
    }
}

// ---------------------------------------------------------------------------
extern "C" void kernel_launch(void* const* d_in, const int* in_sizes, int n_in,
                              void* d_out, int out_size)
{
    const float* X  = (const float*)d_in[0];
    const float* WQ = (const float*)d_in[1];
    const float* WK = (const float*)d_in[2];
    const float* WV = (const float*)d_in[3];
    const float* WO = (const float*)d_in[4];
    const float* bO = (const float*)d_in[5];
    float* out = (float*)d_out;

    float *V, *P;
    __half *Xh, *Xl, *WQh, *WQl, *WKh, *WKl, *WVh, *WVl, *WOh, *WOl;
    __half *Qh, *Ql, *Kh, *Kl, *Vth, *Ph, *Pl, *Oh, *Ol;
    cudaGetSymbolAddress((void**)&V, g_V);
    cudaGetSymbolAddress((void**)&P, g_P);
    cudaGetSymbolAddress((void**)&Xh, g_Xh);   cudaGetSymbolAddress((void**)&Xl, g_Xl);
    cudaGetSymbolAddress((void**)&WQh, g_WQh); cudaGetSymbolAddress((void**)&WQl, g_WQl);
    cudaGetSymbolAddress((void**)&WKh, g_WKh); cudaGetSymbolAddress((void**)&WKl, g_WKl);
    cudaGetSymbolAddress((void**)&WVh, g_WVh); cudaGetSymbolAddress((void**)&WVl, g_WVl);
    cudaGetSymbolAddress((void**)&WOh, g_WOh); cudaGetSymbolAddress((void**)&WOl, g_WOl);
    cudaGetSymbolAddress((void**)&Qh, g_Qh);   cudaGetSymbolAddress((void**)&Ql, g_Ql);
    cudaGetSymbolAddress((void**)&Kh, g_Kh);   cudaGetSymbolAddress((void**)&Kl, g_Kl);
    cudaGetSymbolAddress((void**)&Vth, g_Vth);
    cudaGetSymbolAddress((void**)&Ph, g_Ph);   cudaGetSymbolAddress((void**)&Pl, g_Pl);
    cudaGetSymbolAddress((void**)&Oh, g_Oh);   cudaGetSymbolAddress((void**)&Ol, g_Ol);

    cudaFuncSetAttribute(hmma_gemm<0>,
                         cudaFuncAttributeMaxDynamicSharedMemorySize, SMEM_TOTAL);
    cudaFuncSetAttribute(hmma_gemm<1>,
                         cudaFuncAttributeMaxDynamicSharedMemorySize, SMEM_TOTAL);
    cudaFuncSetAttribute(qkv_gemm,
                         cudaFuncAttributeMaxDynamicSharedMemorySize, SMEM_TOTAL);

    const int B = 4, S = 2048, D = 1024, M = B * S;
    const long long SD = (long long)S * D;
    const long long SS = (long long)S * S;

    dim3 blk(256);

    // ---- merged split: X + 4 weights, one launch ----
    const int nbX = (int)((long long)M * D / 4 / 256);   // 8192
    const int nbW = D * D / 4 / 256;                     // 1024
    split_all_kernel<<<nbX + 4 * nbW, blk>>>(X, WQ, WK, WV, WO,
                                             Xh, Xl, WQh, WQl, WKh, WKl,
                                             WVh, WVl, WOh, WOl, nbX, nbW);

    // merged Q/K/V projections (Q,K 3-pass fp16 out; V 2-pass fp32 out)
    dim3 gqkv(D / BN, M / BM, 3);
    qkv_gemm<<<gqkv, blk, SMEM_TOTAL>>>(Xh, Xl, WQh, WQl, WKh, WKl, WVh, WVl,
                                        Qh, Ql, Kh, Kl, V, D, D);
    trans_split_kernel<<<dim3(S / 32, D / 32, B), dim3(32, 8)>>>(V, Vth, S, D);

    // logits: P[b] = Q[b] @ K[b]^T  (causal tile skip, 3-pass)
    dim3 glog(S / BN, S / BM, B);
    hmma_gemm<0><<<glog, blk, SMEM_TOTAL>>>(Qh, Ql, Kh, Kl, P, nullptr, nullptr,
                                            nullptr, S, S, D, SD, SD, SS, 1, 3);

    // causal softmax -> fp16 hi/lo probs (diagonal-band zero fill only)
    softmax_causal_kernel<<<dim3(S, B), blk>>>(P, Ph, Pl, S);

    // attn out: O[b] = P[b] @ Vt[b]^T (NT, k-limited, heavy-first, 2-pass:
    // Ph*Vth + Pl*Vth; the Vt-lo term is dropped)
    dim3 gpv(D / BN, S / BM, B);
    hmma_gemm<1><<<gpv, blk, SMEM_TOTAL>>>(Ph, Pl, Vth, Vth, nullptr, Oh, Ol,
                                           nullptr, S, D, S, SS, SD, SD, 2, 2);

    // output projection + bias -> fp32 out (2-pass)
    dim3 gproj(D / BN, M / BM, 1);
    hmma_gemm<0><<<gproj, blk, SMEM_TOTAL>>>(Oh, Ol, WOh, WOl, out, nullptr, nullptr,
                                             bO, M, D, D, 0, 0, 0, 0, 2);
}

// round 8
// speedup vs baseline: 3.2821x; 1.0471x over previous
#include <cuda_runtime.h>
#include <cuda_fp16.h>
#include <stdint.h>

#define BM 128
#define BN 128
#define BK 32
#define STAGES 3
#define TILE_B (BM * BK * 2)            // 8 KB per operand tile
#define STAGE_B (4 * TILE_B)            // 32 KB  (Ah, Al, Bh, Bl)
#define SMEM_TOTAL (STAGES * STAGE_B)   // 96 KB -> 2 CTAs/SM

// ---------------- scratch (device globals: allocation-free) ----------------
__device__ float  g_V[4LL * 2048 * 1024];
__device__ float  g_P[4LL * 2048 * 2048];
__device__ __half g_Xh[8192LL * 1024],  g_Xl[8192LL * 1024];
__device__ __half g_WQh[1024 * 1024],   g_WQl[1024 * 1024];
__device__ __half g_WKh[1024 * 1024],   g_WKl[1024 * 1024];
__device__ __half g_WVh[1024 * 1024],   g_WVl[1024 * 1024];
__device__ __half g_WOh[1024 * 1024],   g_WOl[1024 * 1024];
__device__ __half g_Qh[8192LL * 1024],  g_Ql[8192LL * 1024];
__device__ __half g_Kh[8192LL * 1024],  g_Kl[8192LL * 1024];
__device__ __half g_Vth[4LL * 1024 * 2048];
__device__ __half g_Ph[4LL * 2048 * 2048],  g_Pl[4LL * 2048 * 2048];
__device__ __half g_Oh[8192LL * 1024],  g_Ol[8192LL * 1024];

// ---------------- base-PTX helpers ----------------
__device__ __forceinline__ uint32_t smem_u32(const void* p) {
    uint32_t a;
    asm("{ .reg .u64 t; cvta.to.shared.u64 t, %1; cvt.u32.u64 %0, t; }"
        : "=r"(a) : "l"(p));
    return a;
}
#define CP_ASYNC16(sa, ga) \
    asm volatile("cp.async.cg.shared.global [%0], [%1], 16;" :: "r"(sa), "l"(ga))
#define CP_COMMIT() asm volatile("cp.async.commit_group;" ::: "memory")
#define CP_WAIT(n)  asm volatile("cp.async.wait_group %0;" :: "n"(n) : "memory")
#define LDSM4(d0, d1, d2, d3, a) \
    asm volatile("ldmatrix.sync.aligned.m8n8.x4.shared.b16 {%0,%1,%2,%3}, [%4];" \
                 : "=r"(d0), "=r"(d1), "=r"(d2), "=r"(d3) : "r"(a))
#define MMA(d, a, b0, b1) \
    asm volatile("mma.sync.aligned.m16n8k16.row.col.f32.f16.f16.f32 " \
                 "{%0,%1,%2,%3}, {%4,%5,%6,%7}, {%8,%9}, {%0,%1,%2,%3};" \
                 : "+f"((d)[0]), "+f"((d)[1]), "+f"((d)[2]), "+f"((d)[3]) \
                 : "r"((a)[0]), "r"((a)[1]), "r"((a)[2]), "r"((a)[3]), \
                   "r"(b0), "r"(b1))

// smem tile layout: [128 rows][4 chunks of 16B], chunk xor-swizzled.
__device__ __forceinline__ uint32_t swz(uint32_t r, uint32_t c) {
    return r * 64u + ((c ^ ((r >> 1) & 3u)) << 4);
}

__device__ __forceinline__ void split_h(float x, __half& h, __half& l) {
    h = __float2half_rn(x);
    l = __float2half_rn(x - __half2float(h));
}

// ---------------------------------------------------------------------------
// fp16x3 HMMA GEMM body:  C[m,n] = sum_k A[m,k] * B[n,k]  (NT, row-major)
//   passes==3: Ah*Bh + Al*Bh + Ah*Bl.  passes==2: Ah*Bh + Al*Bh (Bl unused).
// OUT_HALF 0: write fp32 C (+bias).  1: write fp16 hi/lo pair.
// ---------------------------------------------------------------------------
template <int OUT_HALF>
__device__ __forceinline__ void gemm_body(
    const __half* __restrict__ pAh, const __half* __restrict__ pAl,
    const __half* __restrict__ pBh, const __half* __restrict__ pBl,
    float* __restrict__ Cf, __half* __restrict__ Ch, __half* __restrict__ Cl,
    const float* __restrict__ bias,
    int N, int K, int kend, int m0, int n0, int passes)
{
    extern __shared__ char smem[];
    const int nk = kend / BK;

    const int tid = threadIdx.x;
    const int r0 = tid >> 2;        // 0..63
    const int c0 = tid & 3;         // 16B chunk within 64B row

    const __half* srcs[8];
    srcs[0] = pAh + (long long)(m0 + r0) * K + c0 * 8;
    srcs[1] = srcs[0] + 64LL * K;
    srcs[2] = pAl + (long long)(m0 + r0) * K + c0 * 8;
    srcs[3] = srcs[2] + 64LL * K;
    srcs[4] = pBh + (long long)(n0 + r0) * K + c0 * 8;
    srcs[5] = srcs[4] + 64LL * K;
    srcs[6] = pBl + (long long)(n0 + r0) * K + c0 * 8;
    srcs[7] = srcs[6] + 64LL * K;

    const uint32_t sbase = smem_u32(smem);
    const uint32_t w0 = swz((uint32_t)r0, (uint32_t)c0);
    const uint32_t w1 = w0 + 64u * 64u;
    uint32_t dsts[8];
    #pragma unroll
    for (int t = 0; t < 4; ++t) {
        dsts[2 * t]     = (uint32_t)t * TILE_B + w0;
        dsts[2 * t + 1] = (uint32_t)t * TILE_B + w1;
    }
    const int nload = (passes >= 3) ? 8 : 6;   // skip Bl tiles in 2-pass mode

    const int wid = tid >> 5, lid = tid & 31;
    const int wm = (wid >> 2) * 64;
    const int wn = (wid & 3) * 32;
    const int lrow = lid & 15;
    const int lkh  = lid >> 4;

    float acc[4][4][4] = {};

    #pragma unroll
    for (int s = 0; s < STAGES - 1; ++s) {
        if (s < nk) {
            const uint32_t st = sbase + (uint32_t)(s % STAGES) * STAGE_B;
            const long long ko = (long long)s * BK;
            #pragma unroll
            for (int j = 0; j < 8; ++j)
                if (j < nload) CP_ASYNC16(st + dsts[j], srcs[j] + ko);
        }
        CP_COMMIT();
    }

    for (int kt = 0; kt < nk; ++kt) {
        CP_WAIT(STAGES - 2);
        __syncthreads();   // stage kt visible; all threads past iter kt-1 compute

        const int nxt = kt + STAGES - 1;
        if (nxt < nk) {
            const uint32_t st = sbase + (uint32_t)(nxt % STAGES) * STAGE_B;
            const long long ko = (long long)nxt * BK;
            #pragma unroll
            for (int j = 0; j < 8; ++j)
                if (j < nload) CP_ASYNC16(st + dsts[j], srcs[j] + ko);
        }
        CP_COMMIT();

        const uint32_t sb = sbase + (uint32_t)(kt % STAGES) * STAGE_B;
        #pragma unroll
        for (int ks = 0; ks < 2; ++ks) {
            const uint32_t ckh = 2u * ks + (uint32_t)lkh;
            uint32_t ah[4][4], al[4][4], bF[4][2];

            #pragma unroll
            for (int mt = 0; mt < 4; ++mt) {
                uint32_t row = (uint32_t)(wm + mt * 16 + lrow);
                uint32_t ad = sb + swz(row, ckh);               // Ah
                LDSM4(ah[mt][0], ah[mt][1], ah[mt][2], ah[mt][3], ad);
            }
            #pragma unroll
            for (int np = 0; np < 2; ++np) {
                uint32_t row = (uint32_t)(wn + np * 16 + lrow);
                uint32_t ad = sb + 2u * TILE_B + swz(row, ckh); // Bh
                uint32_t q0, q1, q2, q3;
                LDSM4(q0, q1, q2, q3, ad);
                bF[2 * np][0] = q0; bF[2 * np + 1][0] = q1;
                bF[2 * np][1] = q2; bF[2 * np + 1][1] = q3;
            }
            #pragma unroll
            for (int mt = 0; mt < 4; ++mt)
                #pragma unroll
                for (int nt = 0; nt < 4; ++nt)
                    MMA(acc[mt][nt], ah[mt], bF[nt][0], bF[nt][1]);

            #pragma unroll
            for (int mt = 0; mt < 4; ++mt) {
                uint32_t row = (uint32_t)(wm + mt * 16 + lrow);
                uint32_t ad = sb + 1u * TILE_B + swz(row, ckh); // Al
                LDSM4(al[mt][0], al[mt][1], al[mt][2], al[mt][3], ad);
            }
            #pragma unroll
            for (int mt = 0; mt < 4; ++mt)
                #pragma unroll
                for (int nt = 0; nt < 4; ++nt)
                    MMA(acc[mt][nt], al[mt], bF[nt][0], bF[nt][1]);

            if (passes >= 3) {
                #pragma unroll
                for (int np = 0; np < 2; ++np) {
                    uint32_t row = (uint32_t)(wn + np * 16 + lrow);
                    uint32_t ad = sb + 3u * TILE_B + swz(row, ckh); // Bl
                    uint32_t q0, q1, q2, q3;
                    LDSM4(q0, q1, q2, q3, ad);
                    bF[2 * np][0] = q0; bF[2 * np + 1][0] = q1;
                    bF[2 * np][1] = q2; bF[2 * np + 1][1] = q3;
                }
                #pragma unroll
                for (int mt = 0; mt < 4; ++mt)
                    #pragma unroll
                    for (int nt = 0; nt < 4; ++nt)
                        MMA(acc[mt][nt], ah[mt], bF[nt][0], bF[nt][1]);
            }
        }
        // no bottom barrier: next iteration's top barrier orders reuse
    }

    const int lm = lid >> 2, lc = (lid & 3) * 2;
    #pragma unroll
    for (int mt = 0; mt < 4; ++mt) {
        #pragma unroll
        for (int hrow = 0; hrow < 2; ++hrow) {
            const int row = m0 + wm + mt * 16 + lm + hrow * 8;
            #pragma unroll
            for (int nt = 0; nt < 4; ++nt) {
                const int col = n0 + wn + nt * 8 + lc;
                float d0 = acc[mt][nt][hrow * 2 + 0];
                float d1 = acc[mt][nt][hrow * 2 + 1];
                const long long idx = (long long)row * N + col;
                if (OUT_HALF) {
                    __half h0, l0, h1, l1;
                    split_h(d0, h0, l0);
                    split_h(d1, h1, l1);
                    *(__half2*)&Ch[idx] = __halves2half2(h0, h1);
                    *(__half2*)&Cl[idx] = __halves2half2(l0, l1);
                } else {
                    if (bias) { d0 += bias[col]; d1 += bias[col + 1]; }
                    *(float2*)&Cf[idx] = make_float2(d0, d1);
                }
            }
        }
    }
}

// ---------------------------------------------------------------------------
// mode 0: plain  mode 1: causal tile skip  mode 2: k-limit (heavy tiles first)
// ---------------------------------------------------------------------------
template <int OUT_HALF>
__global__ __launch_bounds__(256, 2)
void hmma_gemm(const __half* __restrict__ pAh, const __half* __restrict__ pAl,
               const __half* __restrict__ pBh, const __half* __restrict__ pBl,
               float* __restrict__ Cf, __half* __restrict__ Ch,
               __half* __restrict__ Cl, const float* __restrict__ bias,
               int M, int N, int K,
               long long sA, long long sB, long long sC, int mode, int passes)
{
    const int bn = blockIdx.x, bz = blockIdx.z;
    int bm = blockIdx.y;
    if (mode == 1 && bn > bm) return;
    if (mode == 2) bm = gridDim.y - 1 - blockIdx.y;
    const int kend = (mode == 2) ? (bm * BM + BM) : K;

    gemm_body<OUT_HALF>(pAh + (long long)bz * sA, pAl + (long long)bz * sA,
                        pBh + (long long)bz * sB, pBl + (long long)bz * sB,
                        OUT_HALF ? nullptr : Cf + (long long)bz * sC,
                        OUT_HALF ? Ch + (long long)bz * sC : nullptr,
                        OUT_HALF ? Cl + (long long)bz * sC : nullptr,
                        bias, N, K, kend, bm * BM, bn * BN, passes);
}

// ---------------------------------------------------------------------------
// Merged Q/K/V projection: blockIdx.z selects the weight + output.
// Q,K -> fp16 hi/lo (3-pass).  V -> fp32 (2-pass).
// ---------------------------------------------------------------------------
__global__ __launch_bounds__(256, 2)
void qkv_gemm(const __half* __restrict__ Xh, const __half* __restrict__ Xl,
              const __half* __restrict__ WQh, const __half* __restrict__ WQl,
              const __half* __restrict__ WKh, const __half* __restrict__ WKl,
              const __half* __restrict__ WVh, const __half* __restrict__ WVl,
              __half* __restrict__ Qh, __half* __restrict__ Ql,
              __half* __restrict__ Kh, __half* __restrict__ Kl,
              float* __restrict__ Vf, int N, int K)
{
    const int m0 = blockIdx.y * BM, n0 = blockIdx.x * BN, bz = blockIdx.z;
    if (bz == 0)
        gemm_body<1>(Xh, Xl, WQh, WQl, nullptr, Qh, Ql, nullptr,
                     N, K, K, m0, n0, 3);
    else if (bz == 1)
        gemm_body<1>(Xh, Xl, WKh, WKl, nullptr, Kh, Kl, nullptr,
                     N, K, K, m0, n0, 3);
    else
        gemm_body<0>(Xh, Xl, WVh, WVl, Vf, nullptr, nullptr, nullptr,
                     N, K, K, m0, n0, 2);
}

// ---------------------------------------------------------------------------
// Merged fp32 -> fp16 hi/lo split for X + the 4 weight matrices (one launch).
// ---------------------------------------------------------------------------
__global__ __launch_bounds__(256)
void split_all_kernel(const float* __restrict__ X, const float* __restrict__ WQ,
                      const float* __restrict__ WK, const float* __restrict__ WV,
                      const float* __restrict__ WO,
                      __half* __restrict__ Xh, __half* __restrict__ Xl,
                      __half* __restrict__ WQh, __half* __restrict__ WQl,
                      __half* __restrict__ WKh, __half* __restrict__ WKl,
                      __half* __restrict__ WVh, __half* __restrict__ WVl,
                      __half* __restrict__ WOh, __half* __restrict__ WOl,
                      int nbX, int nbW)
{
    const float* in;
    __half *h, *l;
    long long i;
    int bid = blockIdx.x;
    if (bid < nbX) {
        in = X; h = Xh; l = Xl;
        i = (long long)bid * 256 + threadIdx.x;
    } else {
        int w = (bid - nbX) / nbW;
        int rb = (bid - nbX) - w * nbW;
        in = (w == 0) ? WQ : (w == 1) ? WK : (w == 2) ? WV : WO;
        h  = (w == 0) ? WQh : (w == 1) ? WKh : (w == 2) ? WVh : WOh;
        l  = (w == 0) ? WQl : (w == 1) ? WKl : (w == 2) ? WVl : WOl;
        i = (long long)rb * 256 + threadIdx.x;
    }
    float4 v = ((const float4*)in)[i];
    __half h0, l0, h1, l1, h2, l2, h3, l3;
    split_h(v.x, h0, l0); split_h(v.y, h1, l1);
    split_h(v.z, h2, l2); split_h(v.w, h3, l3);
    ((__half2*)h)[2 * i]     = __halves2half2(h0, h1);
    ((__half2*)h)[2 * i + 1] = __halves2half2(h2, h3);
    ((__half2*)l)[2 * i]     = __halves2half2(l0, l1);
    ((__half2*)l)[2 * i + 1] = __halves2half2(l2, l3);
}

// ---------------------------------------------------------------------------
// per-batch transpose: V[b][s][d] fp32 -> Vt[b][d][s] fp16 (hi only)
// ---------------------------------------------------------------------------
__global__ __launch_bounds__(256)
void trans_split_kernel(const float* __restrict__ V, __half* __restrict__ Th,
                        int S, int D)
{
    __shared__ float t[32][33];
    const int b = blockIdx.z;
    const int s0 = blockIdx.x * 32, d0 = blockIdx.y * 32;
    const float* Vb = V + (long long)b * S * D;
    #pragma unroll
    for (int i = 0; i < 4; ++i) {
        int s = threadIdx.y + i * 8;
        t[s][threadIdx.x] = Vb[(long long)(s0 + s) * D + d0 + threadIdx.x];
    }
    __syncthreads();
    const long long ob = (long long)b * D * S;
    #pragma unroll
    for (int i = 0; i < 4; ++i) {
        int d = threadIdx.y + i * 8;
        Th[ob + (long long)(d0 + d) * S + s0 + threadIdx.x] =
            __float2half_rn(t[threadIdx.x][d]);
    }
}

// ---------------------------------------------------------------------------
// Causal row softmax. Register-cached; zero-fills only the diagonal 128-band.
// ---------------------------------------------------------------------------
__global__ __launch_bounds__(256)
void softmax_causal_kernel(const float* __restrict__ P, __half* __restrict__ Ph,
                           __half* __restrict__ Pl, int S)
{
    const int b = blockIdx.y, i = blockIdx.x;
    const long long base = ((long long)b * S + i) * S;
    const float* row = P + base;
    const int n = i + 1;
    const int tid = threadIdx.x;
    __shared__ float red[8];

    float v[8];
    const int nt = (n + 255) >> 8;

    float m = -3.4e38f;
    #pragma unroll
    for (int t = 0; t < 8; ++t) {
        if (t < nt) {
            int j = t * 256 + tid;
            v[t] = (j < n) ? row[j] : -3.4e38f;
            m = fmaxf(m, v[t]);
        }
    }
    #pragma unroll
    for (int o = 16; o; o >>= 1) m = fmaxf(m, __shfl_xor_sync(~0u, m, o));
    if ((tid & 31) == 0) red[tid >> 5] = m;
    __syncthreads();
    if (tid < 32) {
        float x = (tid < 8) ? red[tid] : -3.4e38f;
        #pragma unroll
        for (int o = 4; o; o >>= 1) x = fmaxf(x, __shfl_xor_sync(~0u, x, o));
        if (tid == 0) red[0] = x;
    }
    __syncthreads();
    m = red[0];
    __syncthreads();

    float s = 0.f;
    #pragma unroll
    for (int t = 0; t < 8; ++t) {
        if (t < nt) {
            int j = t * 256 + tid;
            v[t] = (j < n) ? __expf(v[t] - m) : 0.f;
            s += v[t];
        }
    }
    #pragma unroll
    for (int o = 16; o; o >>= 1) s += __shfl_xor_sync(~0u, s, o);
    if ((tid & 31) == 0) red[tid >> 5] = s;
    __syncthreads();
    if (tid < 32) {
        float x = (tid < 8) ? red[tid] : 0.f;
        #pragma unroll
        for (int o = 4; o; o >>= 1) x += __shfl_xor_sync(~0u, x, o);
        if (tid == 0) red[0] = x;
    }
    __syncthreads();
    const float inv = 1.f / red[0];

    #pragma unroll
    for (int t = 0; t < 8; ++t) {
        if (t < nt) {
            int j = t * 256 + tid;
            if (j < n) {
                __half h, l;
                split_h(v[t] * inv, h, l);
                Ph[base + j] = h;
                Pl[base + j] = l;
            }
        }
    }
    const int band_end = (i & ~127) + 128;
    const __half z = __float2half_rn(0.f);
    for (int j = n + tid; j < band_end; j += 256) {
        Ph[base + j] = z;
        Pl[base + j] = z;
    }
}

// ---------------------------------------------------------------------------
extern "C" void kernel_launch(void* const* d_in, const int* in_sizes, int n_in,
                              void* d_out, int out_size)
{
    const float* X  = (const float*)d_in[0];
    const float* WQ = (const float*)d_in[1];
    const float* WK = (const float*)d_in[2];
    const float* WV = (const float*)d_in[3];
    const float* WO = (const float*)d_in[4];
    const float* bO = (const float*)d_in[5];
    float* out = (float*)d_out;

    float *V, *P;
    __half *Xh, *Xl, *WQh, *WQl, *WKh, *WKl, *WVh, *WVl, *WOh, *WOl;
    __half *Qh, *Ql, *Kh, *Kl, *Vth, *Ph, *Pl, *Oh, *Ol;
    cudaGetSymbolAddress((void**)&V, g_V);
    cudaGetSymbolAddress((void**)&P, g_P);
    cudaGetSymbolAddress((void**)&Xh, g_Xh);   cudaGetSymbolAddress((void**)&Xl, g_Xl);
    cudaGetSymbolAddress((void**)&WQh, g_WQh); cudaGetSymbolAddress((void**)&WQl, g_WQl);
    cudaGetSymbolAddress((void**)&WKh, g_WKh); cudaGetSymbolAddress((void**)&WKl, g_WKl);
    cudaGetSymbolAddress((void**)&WVh, g_WVh); cudaGetSymbolAddress((void**)&WVl, g_WVl);
    cudaGetSymbolAddress((void**)&WOh, g_WOh); cudaGetSymbolAddress((void**)&WOl, g_WOl);
    cudaGetSymbolAddress((void**)&Qh, g_Qh);   cudaGetSymbolAddress((void**)&Ql, g_Ql);
    cudaGetSymbolAddress((void**)&Kh, g_Kh);   cudaGetSymbolAddress((void**)&Kl, g_Kl);
    cudaGetSymbolAddress((void**)&Vth, g_Vth);
    cudaGetSymbolAddress((void**)&Ph, g_Ph);   cudaGetSymbolAddress((void**)&Pl, g_Pl);
    cudaGetSymbolAddress((void**)&Oh, g_Oh);   cudaGetSymbolAddress((void**)&Ol, g_Ol);

    cudaFuncSetAttribute(hmma_gemm<0>,
                         cudaFuncAttributeMaxDynamicSharedMemorySize, SMEM_TOTAL);
    cudaFuncSetAttribute(hmma_gemm<1>,
                         cudaFuncAttributeMaxDynamicSharedMemorySize, SMEM_TOTAL);
    cudaFuncSetAttribute(qkv_gemm,
                         cudaFuncAttributeMaxDynamicSharedMemorySize, SMEM_TOTAL);

    const int B = 4, S = 2048, D = 1024, M = B * S;
    const long long SD = (long long)S * D;
    const long long SS = (long long)S * S;

    dim3 blk(256);

    // ---- merged split: X + 4 weights, one launch ----
    const int nbX = (int)((long long)M * D / 4 / 256);   // 8192
    const int nbW = D * D / 4 / 256;                     // 1024
    split_all_kernel<<<nbX + 4 * nbW, blk>>>(X, WQ, WK, WV, WO,
                                             Xh, Xl, WQh, WQl, WKh, WKl,
                                             WVh, WVl, WOh, WOl, nbX, nbW);

    // merged Q/K/V projections (Q,K 3-pass fp16 out; V 2-pass fp32 out)
    dim3 gqkv(D / BN, M / BM, 3);
    qkv_gemm<<<gqkv, blk, SMEM_TOTAL>>>(Xh, Xl, WQh, WQl, WKh, WKl, WVh, WVl,
                                        Qh, Ql, Kh, Kl, V, D, D);
    trans_split_kernel<<<dim3(S / 32, D / 32, B), dim3(32, 8)>>>(V, Vth, S, D);

    // logits: P[b] = Q[b] @ K[b]^T  (causal tile skip, 3-pass)
    dim3 glog(S / BN, S / BM, B);
    hmma_gemm<0><<<glog, blk, SMEM_TOTAL>>>(Qh, Ql, Kh, Kl, P, nullptr, nullptr,
                                            nullptr, S, S, D, SD, SD, SS, 1, 3);

    // causal softmax -> fp16 hi/lo probs (diagonal-band zero fill only)
    softmax_causal_kernel<<<dim3(S, B), blk>>>(P, Ph, Pl, S);

    // attn out: O[b] = P[b] @ Vt[b]^T (NT, k-limited, heavy-first, 2-pass)
    dim3 gpv(D / BN, S / BM, B);
    hmma_gemm<1><<<gpv, blk, SMEM_TOTAL>>>(Ph, Pl, Vth, Vth, nullptr, Oh, Ol,
                                           nullptr, S, D, S, SS, SD, SD, 2, 2);

    // output projection + bias -> fp32 out (2-pass)
    dim3 gproj(D / BN, M / BM, 1);
    hmma_gemm<0><<<gproj, blk, SMEM_TOTAL>>>(Oh, Ol, WOh, WOl, out, nullptr, nullptr,
                                             bO, M, D, D, 0, 0, 0, 0, 2);
}

// round 9
// speedup vs baseline: 3.3050x; 1.0070x over previous
#include <cuda_runtime.h>
#include <cuda_fp16.h>
#include <stdint.h>

#define BM 128
#define BN 128
#define BK 32
#define STAGES 3
#define TILE_B (BM * BK * 2)            // 8 KB per operand tile
#define STAGE_B (4 * TILE_B)            // 32 KB  (Ah, Al, Bh, Bl)
#define SMEM_TOTAL (STAGES * STAGE_B)   // 96 KB -> 2 CTAs/SM

// ---------------- scratch (device globals: allocation-free) ----------------
__device__ float  g_V[4LL * 2048 * 1024];
__device__ float  g_P[4LL * 2048 * 2048];
__device__ __half g_Xh[8192LL * 1024],  g_Xl[8192LL * 1024];
__device__ __half g_WQh[1024 * 1024],   g_WQl[1024 * 1024];
__device__ __half g_WKh[1024 * 1024],   g_WKl[1024 * 1024];
__device__ __half g_WVh[1024 * 1024],   g_WVl[1024 * 1024];
__device__ __half g_WOh[1024 * 1024],   g_WOl[1024 * 1024];
__device__ __half g_Qh[8192LL * 1024],  g_Ql[8192LL * 1024];
__device__ __half g_Kh[8192LL * 1024],  g_Kl[8192LL * 1024];
__device__ __half g_Vth[4LL * 1024 * 2048];
__device__ __half g_Ph[4LL * 2048 * 2048],  g_Pl[4LL * 2048 * 2048];
__device__ __half g_Oh[8192LL * 1024],  g_Ol[8192LL * 1024];

// ---------------- base-PTX helpers ----------------
__device__ __forceinline__ uint32_t smem_u32(const void* p) {
    uint32_t a;
    asm("{ .reg .u64 t; cvta.to.shared.u64 t, %1; cvt.u32.u64 %0, t; }"
        : "=r"(a) : "l"(p));
    return a;
}
#define CP_ASYNC16(sa, ga) \
    asm volatile("cp.async.cg.shared.global [%0], [%1], 16;" :: "r"(sa), "l"(ga))
#define CP_COMMIT() asm volatile("cp.async.commit_group;" ::: "memory")
#define CP_WAIT(n)  asm volatile("cp.async.wait_group %0;" :: "n"(n) : "memory")
#define LDSM4(d0, d1, d2, d3, a) \
    asm volatile("ldmatrix.sync.aligned.m8n8.x4.shared.b16 {%0,%1,%2,%3}, [%4];" \
                 : "=r"(d0), "=r"(d1), "=r"(d2), "=r"(d3) : "r"(a))
#define MMA(d, a, b0, b1) \
    asm volatile("mma.sync.aligned.m16n8k16.row.col.f32.f16.f16.f32 " \
                 "{%0,%1,%2,%3}, {%4,%5,%6,%7}, {%8,%9}, {%0,%1,%2,%3};" \
                 : "+f"((d)[0]), "+f"((d)[1]), "+f"((d)[2]), "+f"((d)[3]) \
                 : "r"((a)[0]), "r"((a)[1]), "r"((a)[2]), "r"((a)[3]), \
                   "r"(b0), "r"(b1))

// smem tile layout: [128 rows][4 chunks of 16B], chunk xor-swizzled.
__device__ __forceinline__ uint32_t swz(uint32_t r, uint32_t c) {
    return r * 64u + ((c ^ ((r >> 1) & 3u)) << 4);
}

__device__ __forceinline__ void split_h(float x, __half& h, __half& l) {
    h = __float2half_rn(x);
    l = __float2half_rn(x - __half2float(h));
}

// ---------------------------------------------------------------------------
// fp16x3 HMMA GEMM body:  C[m,n] = sum_k A[m,k] * B[n,k]  (NT, row-major)
//   passes==3: Ah*Bh + Al*Bh + Ah*Bl.  passes==2: Ah*Bh + Al*Bh (Bl unused).
// Inner loop is latency-scheduled: all A/Bh fragment loads are issued before
// the first MMA block; the Bl loads are issued under the pass-2 MMA shadow.
// OUT_HALF 0: write fp32 C (+bias).  1: write fp16 hi/lo pair.
// ---------------------------------------------------------------------------
template <int OUT_HALF>
__device__ __forceinline__ void gemm_body(
    const __half* __restrict__ pAh, const __half* __restrict__ pAl,
    const __half* __restrict__ pBh, const __half* __restrict__ pBl,
    float* __restrict__ Cf, __half* __restrict__ Ch, __half* __restrict__ Cl,
    const float* __restrict__ bias,
    int N, int K, int kend, int m0, int n0, int passes)
{
    extern __shared__ char smem[];
    const int nk = kend / BK;

    const int tid = threadIdx.x;
    const int r0 = tid >> 2;        // 0..63
    const int c0 = tid & 3;         // 16B chunk within 64B row

    const __half* srcs[8];
    srcs[0] = pAh + (long long)(m0 + r0) * K + c0 * 8;
    srcs[1] = srcs[0] + 64LL * K;
    srcs[2] = pAl + (long long)(m0 + r0) * K + c0 * 8;
    srcs[3] = srcs[2] + 64LL * K;
    srcs[4] = pBh + (long long)(n0 + r0) * K + c0 * 8;
    srcs[5] = srcs[4] + 64LL * K;
    srcs[6] = pBl + (long long)(n0 + r0) * K + c0 * 8;
    srcs[7] = srcs[6] + 64LL * K;

    const uint32_t sbase = smem_u32(smem);
    const uint32_t w0 = swz((uint32_t)r0, (uint32_t)c0);
    const uint32_t w1 = w0 + 64u * 64u;
    uint32_t dsts[8];
    #pragma unroll
    for (int t = 0; t < 4; ++t) {
        dsts[2 * t]     = (uint32_t)t * TILE_B + w0;
        dsts[2 * t + 1] = (uint32_t)t * TILE_B + w1;
    }
    const int nload = (passes >= 3) ? 8 : 6;   // skip Bl tiles in 2-pass mode

    const int wid = tid >> 5, lid = tid & 31;
    const int wm = (wid >> 2) * 64;
    const int wn = (wid & 3) * 32;
    const int lrow = lid & 15;
    const int lkh  = lid >> 4;

    float acc[4][4][4] = {};

    #pragma unroll
    for (int s = 0; s < STAGES - 1; ++s) {
        if (s < nk) {
            const uint32_t st = sbase + (uint32_t)(s % STAGES) * STAGE_B;
            const long long ko = (long long)s * BK;
            #pragma unroll
            for (int j = 0; j < 8; ++j)
                if (j < nload) CP_ASYNC16(st + dsts[j], srcs[j] + ko);
        }
        CP_COMMIT();
    }

    for (int kt = 0; kt < nk; ++kt) {
        CP_WAIT(STAGES - 2);
        __syncthreads();   // stage kt visible; all threads past iter kt-1 compute

        const int nxt = kt + STAGES - 1;
        if (nxt < nk) {
            const uint32_t st = sbase + (uint32_t)(nxt % STAGES) * STAGE_B;
            const long long ko = (long long)nxt * BK;
            #pragma unroll
            for (int j = 0; j < 8; ++j)
                if (j < nload) CP_ASYNC16(st + dsts[j], srcs[j] + ko);
        }
        CP_COMMIT();

        const uint32_t sb = sbase + (uint32_t)(kt % STAGES) * STAGE_B;
        #pragma unroll
        for (int ks = 0; ks < 2; ++ks) {
            const uint32_t ckh = 2u * ks + (uint32_t)lkh;
            uint32_t ah[4][4], al[4][4], bh[4][2], bl[4][2];

            // ---- front-loaded fragment loads: Ah(4), Bh(2), Al(4) ----
            #pragma unroll
            for (int mt = 0; mt < 4; ++mt) {
                uint32_t row = (uint32_t)(wm + mt * 16 + lrow);
                uint32_t ad = sb + swz(row, ckh);               // Ah
                LDSM4(ah[mt][0], ah[mt][1], ah[mt][2], ah[mt][3], ad);
            }
            #pragma unroll
            for (int np = 0; np < 2; ++np) {
                uint32_t row = (uint32_t)(wn + np * 16 + lrow);
                uint32_t ad = sb + 2u * TILE_B + swz(row, ckh); // Bh
                uint32_t q0, q1, q2, q3;
                LDSM4(q0, q1, q2, q3, ad);
                bh[2 * np][0] = q0; bh[2 * np + 1][0] = q1;
                bh[2 * np][1] = q2; bh[2 * np + 1][1] = q3;
            }
            #pragma unroll
            for (int mt = 0; mt < 4; ++mt) {
                uint32_t row = (uint32_t)(wm + mt * 16 + lrow);
                uint32_t ad = sb + 1u * TILE_B + swz(row, ckh); // Al
                LDSM4(al[mt][0], al[mt][1], al[mt][2], al[mt][3], ad);
            }

            // ---- pass 1: Ah * Bh ----
            #pragma unroll
            for (int mt = 0; mt < 4; ++mt)
                #pragma unroll
                for (int nt = 0; nt < 4; ++nt)
                    MMA(acc[mt][nt], ah[mt], bh[nt][0], bh[nt][1]);

            // ---- Bl loads issued under the pass-2 MMA shadow ----
            if (passes >= 3) {
                #pragma unroll
                for (int np = 0; np < 2; ++np) {
                    uint32_t row = (uint32_t)(wn + np * 16 + lrow);
                    uint32_t ad = sb + 3u * TILE_B + swz(row, ckh); // Bl
                    uint32_t q0, q1, q2, q3;
                    LDSM4(q0, q1, q2, q3, ad);
                    bl[2 * np][0] = q0; bl[2 * np + 1][0] = q1;
                    bl[2 * np][1] = q2; bl[2 * np + 1][1] = q3;
                }
            }

            // ---- pass 2: Al * Bh (Al loaded long ago; no stall) ----
            #pragma unroll
            for (int mt = 0; mt < 4; ++mt)
                #pragma unroll
                for (int nt = 0; nt < 4; ++nt)
                    MMA(acc[mt][nt], al[mt], bh[nt][0], bh[nt][1]);

            // ---- pass 3: Ah * Bl (Bl latency hidden by pass 2) ----
            if (passes >= 3) {
                #pragma unroll
                for (int mt = 0; mt < 4; ++mt)
                    #pragma unroll
                    for (int nt = 0; nt < 4; ++nt)
                        MMA(acc[mt][nt], ah[mt], bl[nt][0], bl[nt][1]);
            }
        }
        // no bottom barrier: next iteration's top barrier orders reuse
    }

    const int lm = lid >> 2, lc = (lid & 3) * 2;
    #pragma unroll
    for (int mt = 0; mt < 4; ++mt) {
        #pragma unroll
        for (int hrow = 0; hrow < 2; ++hrow) {
            const int row = m0 + wm + mt * 16 + lm + hrow * 8;
            #pragma unroll
            for (int nt = 0; nt < 4; ++nt) {
                const int col = n0 + wn + nt * 8 + lc;
                float d0 = acc[mt][nt][hrow * 2 + 0];
                float d1 = acc[mt][nt][hrow * 2 + 1];
                const long long idx = (long long)row * N + col;
                if (OUT_HALF) {
                    __half h0, l0, h1, l1;
                    split_h(d0, h0, l0);
                    split_h(d1, h1, l1);
                    *(__half2*)&Ch[idx] = __halves2half2(h0, h1);
                    *(__half2*)&Cl[idx] = __halves2half2(l0, l1);
                } else {
                    if (bias) { d0 += bias[col]; d1 += bias[col + 1]; }
                    *(float2*)&Cf[idx] = make_float2(d0, d1);
                }
            }
        }
    }
}

// ---------------------------------------------------------------------------
// mode 0: plain  mode 1: causal tile skip  mode 2: k-limit (heavy tiles first)
// ---------------------------------------------------------------------------
template <int OUT_HALF>
__global__ __launch_bounds__(256, 2)
void hmma_gemm(const __half* __restrict__ pAh, const __half* __restrict__ pAl,
               const __half* __restrict__ pBh, const __half* __restrict__ pBl,
               float* __restrict__ Cf, __half* __restrict__ Ch,
               __half* __restrict__ Cl, const float* __restrict__ bias,
               int M, int N, int K,
               long long sA, long long sB, long long sC, int mode, int passes)
{
    const int bn = blockIdx.x, bz = blockIdx.z;
    int bm = blockIdx.y;
    if (mode == 1 && bn > bm) return;
    if (mode == 2) bm = gridDim.y - 1 - blockIdx.y;
    const int kend = (mode == 2) ? (bm * BM + BM) : K;

    gemm_body<OUT_HALF>(pAh + (long long)bz * sA, pAl + (long long)bz * sA,
                        pBh + (long long)bz * sB, pBl + (long long)bz * sB,
                        OUT_HALF ? nullptr : Cf + (long long)bz * sC,
                        OUT_HALF ? Ch + (long long)bz * sC : nullptr,
                        OUT_HALF ? Cl + (long long)bz * sC : nullptr,
                        bias, N, K, kend, bm * BM, bn * BN, passes);
}

// ---------------------------------------------------------------------------
// Merged Q/K/V projection: blockIdx.z selects the weight + output.
// Q,K -> fp16 hi/lo (3-pass).  V -> fp32 (2-pass).
// ---------------------------------------------------------------------------
__global__ __launch_bounds__(256, 2)
void qkv_gemm(const __half* __restrict__ Xh, const __half* __restrict__ Xl,
              const __half* __restrict__ WQh, const __half* __restrict__ WQl,
              const __half* __restrict__ WKh, const __half* __restrict__ WKl,
              const __half* __restrict__ WVh, const __half* __restrict__ WVl,
              __half* __restrict__ Qh, __half* __restrict__ Ql,
              __half* __restrict__ Kh, __half* __restrict__ Kl,
              float* __restrict__ Vf, int N, int K)
{
    const int m0 = blockIdx.y * BM, n0 = blockIdx.x * BN, bz = blockIdx.z;
    if (bz == 0)
        gemm_body<1>(Xh, Xl, WQh, WQl, nullptr, Qh, Ql, nullptr,
                     N, K, K, m0, n0, 3);
    else if (bz == 1)
        gemm_body<1>(Xh, Xl, WKh, WKl, nullptr, Kh, Kl, nullptr,
                     N, K, K, m0, n0, 3);
    else
        gemm_body<0>(Xh, Xl, WVh, WVl, Vf, nullptr, nullptr, nullptr,
                     N, K, K, m0, n0, 2);
}

// ---------------------------------------------------------------------------
// Merged fp32 -> fp16 hi/lo split for X + the 4 weight matrices (one launch).
// ---------------------------------------------------------------------------
__global__ __launch_bounds__(256)
void split_all_kernel(const float* __restrict__ X, const float* __restrict__ WQ,
                      const float* __restrict__ WK, const float* __restrict__ WV,
                      const float* __restrict__ WO,
                      __half* __restrict__ Xh, __half* __restrict__ Xl,
                      __half* __restrict__ WQh, __half* __restrict__ WQl,
                      __half* __restrict__ WKh, __half* __restrict__ WKl,
                      __half* __restrict__ WVh, __half* __restrict__ WVl,
                      __half* __restrict__ WOh, __half* __restrict__ WOl,
                      int nbX, int nbW)
{
    const float* in;
    __half *h, *l;
    long long i;
    int bid = blockIdx.x;
    if (bid < nbX) {
        in = X; h = Xh; l = Xl;
        i = (long long)bid * 256 + threadIdx.x;
    } else {
        int w = (bid - nbX) / nbW;
        int rb = (bid - nbX) - w * nbW;
        in = (w == 0) ? WQ : (w == 1) ? WK : (w == 2) ? WV : WO;
        h  = (w == 0) ? WQh : (w == 1) ? WKh : (w == 2) ? WVh : WOh;
        l  = (w == 0) ? WQl : (w == 1) ? WKl : (w == 2) ? WVl : WOl;
        i = (long long)rb * 256 + threadIdx.x;
    }
    float4 v = ((const float4*)in)[i];
    __half h0, l0, h1, l1, h2, l2, h3, l3;
    split_h(v.x, h0, l0); split_h(v.y, h1, l1);
    split_h(v.z, h2, l2); split_h(v.w, h3, l3);
    ((__half2*)h)[2 * i]     = __halves2half2(h0, h1);
    ((__half2*)h)[2 * i + 1] = __halves2half2(h2, h3);
    ((__half2*)l)[2 * i]     = __halves2half2(l0, l1);
    ((__half2*)l)[2 * i + 1] = __halves2half2(l2, l3);
}

// ---------------------------------------------------------------------------
// per-batch transpose: V[b][s][d] fp32 -> Vt[b][d][s] fp16 (hi only)
// ---------------------------------------------------------------------------
__global__ __launch_bounds__(256)
void trans_split_kernel(const float* __restrict__ V, __half* __restrict__ Th,
                        int S, int D)
{
    __shared__ float t[32][33];
    const int b = blockIdx.z;
    const int s0 = blockIdx.x * 32, d0 = blockIdx.y * 32;
    const float* Vb = V + (long long)b * S * D;
    #pragma unroll
    for (int i = 0; i < 4; ++i) {
        int s = threadIdx.y + i * 8;
        t[s][threadIdx.x] = Vb[(long long)(s0 + s) * D + d0 + threadIdx.x];
    }
    __syncthreads();
    const long long ob = (long long)b * D * S;
    #pragma unroll
    for (int i = 0; i < 4; ++i) {
        int d = threadIdx.y + i * 8;
        Th[ob + (long long)(d0 + d) * S + s0 + threadIdx.x] =
            __float2half_rn(t[threadIdx.x][d]);
    }
}

// ---------------------------------------------------------------------------
// Causal row softmax. Register-cached; zero-fills only the diagonal 128-band.
// ---------------------------------------------------------------------------
__global__ __launch_bounds__(256)
void softmax_causal_kernel(const float* __restrict__ P, __half* __restrict__ Ph,
                           __half* __restrict__ Pl, int S)
{
    const int b = blockIdx.y, i = blockIdx.x;
    const long long base = ((long long)b * S + i) * S;
    const float* row = P + base;
    const int n = i + 1;
    const int tid = threadIdx.x;
    __shared__ float red[8];

    float v[8];
    const int nt = (n + 255) >> 8;

    float m = -3.4e38f;
    #pragma unroll
    for (int t = 0; t < 8; ++t) {
        if (t < nt) {
            int j = t * 256 + tid;
            v[t] = (j < n) ? row[j] : -3.4e38f;
            m = fmaxf(m, v[t]);
        }
    }
    #pragma unroll
    for (int o = 16; o; o >>= 1) m = fmaxf(m, __shfl_xor_sync(~0u, m, o));
    if ((tid & 31) == 0) red[tid >> 5] = m;
    __syncthreads();
    if (tid < 32) {
        float x = (tid < 8) ? red[tid] : -3.4e38f;
        #pragma unroll
        for (int o = 4; o; o >>= 1) x = fmaxf(x, __shfl_xor_sync(~0u, x, o));
        if (tid == 0) red[0] = x;
    }
    __syncthreads();
    m = red[0];
    __syncthreads();

    float s = 0.f;
    #pragma unroll
    for (int t = 0; t < 8; ++t) {
        if (t < nt) {
            int j = t * 256 + tid;
            v[t] = (j < n) ? __expf(v[t] - m) : 0.f;
            s += v[t];
        }
    }
    #pragma unroll
    for (int o = 16; o; o >>= 1) s += __shfl_xor_sync(~0u, s, o);
    if ((tid & 31) == 0) red[tid >> 5] = s;
    __syncthreads();
    if (tid < 32) {
        float x = (tid < 8) ? red[tid] : 0.f;
        #pragma unroll
        for (int o = 4; o; o >>= 1) x += __shfl_xor_sync(~0u, x, o);
        if (tid == 0) red[0] = x;
    }
    __syncthreads();
    const float inv = 1.f / red[0];

    #pragma unroll
    for (int t = 0; t < 8; ++t) {
        if (t < nt) {
            int j = t * 256 + tid;
            if (j < n) {
                __half h, l;
                split_h(v[t] * inv, h, l);
                Ph[base + j] = h;
                Pl[base + j] = l;
            }
        }
    }
    const int band_end = (i & ~127) + 128;
    const __half z = __float2half_rn(0.f);
    for (int j = n + tid; j < band_end; j += 256) {
        Ph[base + j] = z;
        Pl[base + j] = z;
    }
}

// ---------------------------------------------------------------------------
extern "C" void kernel_launch(void* const* d_in, const int* in_sizes, int n_in,
                              void* d_out, int out_size)
{
    const float* X  = (const float*)d_in[0];
    const float* WQ = (const float*)d_in[1];
    const float* WK = (const float*)d_in[2];
    const float* WV = (const float*)d_in[3];
    const float* WO = (const float*)d_in[4];
    const float* bO = (const float*)d_in[5];
    float* out = (float*)d_out;

    float *V, *P;
    __half *Xh, *Xl, *WQh, *WQl, *WKh, *WKl, *WVh, *WVl, *WOh, *WOl;
    __half *Qh, *Ql, *Kh, *Kl, *Vth, *Ph, *Pl, *Oh, *Ol;
    cudaGetSymbolAddress((void**)&V, g_V);
    cudaGetSymbolAddress((void**)&P, g_P);
    cudaGetSymbolAddress((void**)&Xh, g_Xh);   cudaGetSymbolAddress((void**)&Xl, g_Xl);
    cudaGetSymbolAddress((void**)&WQh, g_WQh); cudaGetSymbolAddress((void**)&WQl, g_WQl);
    cudaGetSymbolAddress((void**)&WKh, g_WKh); cudaGetSymbolAddress((void**)&WKl, g_WKl);
    cudaGetSymbolAddress((void**)&WVh, g_WVh); cudaGetSymbolAddress((void**)&WVl, g_WVl);
    cudaGetSymbolAddress((void**)&WOh, g_WOh); cudaGetSymbolAddress((void**)&WOl, g_WOl);
    cudaGetSymbolAddress((void**)&Qh, g_Qh);   cudaGetSymbolAddress((void**)&Ql, g_Ql);
    cudaGetSymbolAddress((void**)&Kh, g_Kh);   cudaGetSymbolAddress((void**)&Kl, g_Kl);
    cudaGetSymbolAddress((void**)&Vth, g_Vth);
    cudaGetSymbolAddress((void**)&Ph, g_Ph);   cudaGetSymbolAddress((void**)&Pl, g_Pl);
    cudaGetSymbolAddress((void**)&Oh, g_Oh);   cudaGetSymbolAddress((void**)&Ol, g_Ol);

    cudaFuncSetAttribute(hmma_gemm<0>,
                         cudaFuncAttributeMaxDynamicSharedMemorySize, SMEM_TOTAL);
    cudaFuncSetAttribute(hmma_gemm<1>,
                         cudaFuncAttributeMaxDynamicSharedMemorySize, SMEM_TOTAL);
    cudaFuncSetAttribute(qkv_gemm,
                         cudaFuncAttributeMaxDynamicSharedMemorySize, SMEM_TOTAL);

    const int B = 4, S = 2048, D = 1024, M = B * S;
    const long long SD = (long long)S * D;
    const long long SS = (long long)S * S;

    dim3 blk(256);

    // ---- merged split: X + 4 weights, one launch ----
    const int nbX = (int)((long long)M * D / 4 / 256);   // 8192
    const int nbW = D * D / 4 / 256;                     // 1024
    split_all_kernel<<<nbX + 4 * nbW, blk>>>(X, WQ, WK, WV, WO,
                                             Xh, Xl, WQh, WQl, WKh, WKl,
                                             WVh, WVl, WOh, WOl, nbX, nbW);

    // merged Q/K/V projections (Q,K 3-pass fp16 out; V 2-pass fp32 out)
    dim3 gqkv(D / BN, M / BM, 3);
    qkv_gemm<<<gqkv, blk, SMEM_TOTAL>>>(Xh, Xl, WQh, WQl, WKh, WKl, WVh, WVl,
                                        Qh, Ql, Kh, Kl, V, D, D);
    trans_split_kernel<<<dim3(S / 32, D / 32, B), dim3(32, 8)>>>(V, Vth, S, D);

    // logits: P[b] = Q[b] @ K[b]^T  (causal tile skip, 3-pass)
    dim3 glog(S / BN, S / BM, B);
    hmma_gemm<0><<<glog, blk, SMEM_TOTAL>>>(Qh, Ql, Kh, Kl, P, nullptr, nullptr,
                                            nullptr, S, S, D, SD, SD, SS, 1, 3);

    // causal softmax -> fp16 hi/lo probs (diagonal-band zero fill only)
    softmax_causal_kernel<<<dim3(S, B), blk>>>(P, Ph, Pl, S);

    // attn out: O[b] = P[b] @ Vt[b]^T (NT, k-limited, heavy-first, 2-pass)
    dim3 gpv(D / BN, S / BM, B);
    hmma_gemm<1><<<gpv, blk, SMEM_TOTAL>>>(Ph, Pl, Vth, Vth, nullptr, Oh, Ol,
                                           nullptr, S, D, S, SS, SD, SD, 2, 2);

    // output projection + bias -> fp32 out (2-pass)
    dim3 gproj(D / BN, M / BM, 1);
    hmma_gemm<0><<<gproj, blk, SMEM_TOTAL>>>(Oh, Ol, WOh, WOl, out, nullptr, nullptr,
                                             bO, M, D, D, 0, 0, 0, 0, 2);
}

// round 10
// speedup vs baseline: 3.3599x; 1.0166x over previous
#include <cuda_runtime.h>
#include <cuda_fp16.h>
#include <stdint.h>

#define BM 128
#define BN 128
#define BK 32
#define STAGES 3
#define TILE_B (BM * BK * 2)            // 8 KB per operand tile
#define STAGE_B (4 * TILE_B)            // 32 KB  (Ah, Al, Bh, Bl)
#define SMEM_TOTAL (STAGES * STAGE_B)   // 96 KB -> 2 CTAs/SM

// ---------------- scratch (device globals: allocation-free) ----------------
__device__ float  g_V[4LL * 2048 * 1024];
__device__ float  g_P[4LL * 2048 * 2048];
__device__ __half g_Xh[8192LL * 1024],  g_Xl[8192LL * 1024];
__device__ __half g_WQh[1024 * 1024],   g_WQl[1024 * 1024];
__device__ __half g_WKh[1024 * 1024],   g_WKl[1024 * 1024];
__device__ __half g_WVh[1024 * 1024],   g_WVl[1024 * 1024];
__device__ __half g_WOh[1024 * 1024],   g_WOl[1024 * 1024];
__device__ __half g_Qh[8192LL * 1024],  g_Ql[8192LL * 1024];
__device__ __half g_Kh[8192LL * 1024],  g_Kl[8192LL * 1024];
__device__ __half g_Vth[4LL * 1024 * 2048];
__device__ __half g_Ph[4LL * 2048 * 2048],  g_Pl[4LL * 2048 * 2048];
__device__ __half g_Oh[8192LL * 1024],  g_Ol[8192LL * 1024];

// ---------------- base-PTX helpers ----------------
__device__ __forceinline__ uint32_t smem_u32(const void* p) {
    uint32_t a;
    asm("{ .reg .u64 t; cvta.to.shared.u64 t, %1; cvt.u32.u64 %0, t; }"
        : "=r"(a) : "l"(p));
    return a;
}
#define CP_ASYNC16(sa, ga) \
    asm volatile("cp.async.cg.shared.global [%0], [%1], 16;" :: "r"(sa), "l"(ga))
#define CP_COMMIT() asm volatile("cp.async.commit_group;" ::: "memory")
#define CP_WAIT(n)  asm volatile("cp.async.wait_group %0;" :: "n"(n) : "memory")
#define LDSM4(d0, d1, d2, d3, a) \
    asm volatile("ldmatrix.sync.aligned.m8n8.x4.shared.b16 {%0,%1,%2,%3}, [%4];" \
                 : "=r"(d0), "=r"(d1), "=r"(d2), "=r"(d3) : "r"(a))
#define MMA(d, a, b0, b1) \
    asm volatile("mma.sync.aligned.m16n8k16.row.col.f32.f16.f16.f32 " \
                 "{%0,%1,%2,%3}, {%4,%5,%6,%7}, {%8,%9}, {%0,%1,%2,%3};" \
                 : "+f"((d)[0]), "+f"((d)[1]), "+f"((d)[2]), "+f"((d)[3]) \
                 : "r"((a)[0]), "r"((a)[1]), "r"((a)[2]), "r"((a)[3]), \
                   "r"(b0), "r"(b1))

// smem tile layout: [128 rows][4 chunks of 16B], chunk xor-swizzled.
__device__ __forceinline__ uint32_t swz(uint32_t r, uint32_t c) {
    return r * 64u + ((c ^ ((r >> 1) & 3u)) << 4);
}

__device__ __forceinline__ void split_h(float x, __half& h, __half& l) {
    h = __float2half_rn(x);
    l = __float2half_rn(x - __half2float(h));
}

// ---------------------------------------------------------------------------
// fp16x3 HMMA GEMM body:  C[m,n] = sum_k A[m,k] * B[n,k]  (NT, row-major)
//   PASSES==3: Ah*Bh + Al*Bh + Ah*Bl.  PASSES==2: Ah*Bh + Al*Bh (Bl unused).
// PASSES is compile-time: the hot loop is branch-free. Gmem pointers advance
// incrementally; LDSM address components are hoisted out of the k-loop.
// OUT_HALF 0: write fp32 C (+bias).  1: write fp16 hi/lo pair.
// ---------------------------------------------------------------------------
template <int OUT_HALF, int PASSES>
__device__ __forceinline__ void gemm_body(
    const __half* __restrict__ pAh, const __half* __restrict__ pAl,
    const __half* __restrict__ pBh, const __half* __restrict__ pBl,
    float* __restrict__ Cf, __half* __restrict__ Ch, __half* __restrict__ Cl,
    const float* __restrict__ bias,
    int N, int K, int kend, int m0, int n0)
{
    extern __shared__ char smem[];
    const int nk = kend / BK;
    constexpr int NLOAD = (PASSES >= 3) ? 8 : 6;

    const int tid = threadIdx.x;
    const int r0 = tid >> 2;        // 0..63
    const int c0 = tid & 3;         // 16B chunk within 64B row

    // incremental gmem pointers (advance by BK halves per issued stage)
    const __half* src0 = pAh + (long long)(m0 + r0) * K + c0 * 8;
    const __half* src1 = src0 + 64LL * K;
    const __half* src2 = pAl + (long long)(m0 + r0) * K + c0 * 8;
    const __half* src3 = src2 + 64LL * K;
    const __half* src4 = pBh + (long long)(n0 + r0) * K + c0 * 8;
    const __half* src5 = src4 + 64LL * K;
    const __half* src6 = pBl + (long long)(n0 + r0) * K + c0 * 8;
    const __half* src7 = src6 + 64LL * K;

    const uint32_t sbase = smem_u32(smem);
    const uint32_t w0 = swz((uint32_t)r0, (uint32_t)c0);
    const uint32_t w1 = w0 + 64u * 64u;
    uint32_t dsts[8];
    #pragma unroll
    for (int t = 0; t < 4; ++t) {
        dsts[2 * t]     = (uint32_t)t * TILE_B + w0;
        dsts[2 * t + 1] = (uint32_t)t * TILE_B + w1;
    }

    const int wid = tid >> 5, lid = tid & 31;
    const int wm = (wid >> 2) * 64;
    const int wn = (wid & 3) * 32;
    const int lrow = lid & 15;
    const int lkh  = lid >> 4;

    // hoisted LDSM address components (row*64 and xor nibble per subtile)
    uint32_t aoff[4], axr[4], boff[2], bxr[2];
    #pragma unroll
    for (int mt = 0; mt < 4; ++mt) {
        uint32_t row = (uint32_t)(wm + mt * 16 + lrow);
        aoff[mt] = row * 64u;
        axr[mt]  = (row >> 1) & 3u;
    }
    #pragma unroll
    for (int np = 0; np < 2; ++np) {
        uint32_t row = (uint32_t)(wn + np * 16 + lrow);
        boff[np] = row * 64u;
        bxr[np]  = (row >> 1) & 3u;
    }

    float acc[4][4][4] = {};

    #define ISSUE_STAGE(st_idx)                                              \
        do {                                                                 \
            const uint32_t st_ = sbase + (uint32_t)(st_idx) * STAGE_B;       \
            CP_ASYNC16(st_ + dsts[0], src0); CP_ASYNC16(st_ + dsts[1], src1);\
            CP_ASYNC16(st_ + dsts[2], src2); CP_ASYNC16(st_ + dsts[3], src3);\
            CP_ASYNC16(st_ + dsts[4], src4); CP_ASYNC16(st_ + dsts[5], src5);\
            if (NLOAD > 6) {                                                 \
                CP_ASYNC16(st_ + dsts[6], src6);                             \
                CP_ASYNC16(st_ + dsts[7], src7);                             \
            }                                                                \
            src0 += BK; src1 += BK; src2 += BK; src3 += BK;                  \
            src4 += BK; src5 += BK; src6 += BK; src7 += BK;                  \
        } while (0)

    #pragma unroll
    for (int s = 0; s < STAGES - 1; ++s) {
        if (s < nk) ISSUE_STAGE(s % STAGES);
        CP_COMMIT();
    }

    for (int kt = 0; kt < nk; ++kt) {
        CP_WAIT(STAGES - 2);
        __syncthreads();   // stage kt visible; all threads past iter kt-1 compute

        const int nxt = kt + STAGES - 1;
        if (nxt < nk) ISSUE_STAGE(nxt % STAGES);
        CP_COMMIT();

        const uint32_t sb = sbase + (uint32_t)(kt % STAGES) * STAGE_B;
        #pragma unroll
        for (int ks = 0; ks < 2; ++ks) {
            const uint32_t ckh = 2u * ks + (uint32_t)lkh;
            uint32_t ah[4][4], al[4][4], bh[4][2], bl[4][2];

            // ---- fragment loads: Ah(4), Bh(2), Al(4) ----
            #pragma unroll
            for (int mt = 0; mt < 4; ++mt) {
                uint32_t ad = sb + aoff[mt] + ((ckh ^ axr[mt]) << 4);  // Ah
                LDSM4(ah[mt][0], ah[mt][1], ah[mt][2], ah[mt][3], ad);
            }
            #pragma unroll
            for (int np = 0; np < 2; ++np) {
                uint32_t ad = sb + 2u * TILE_B + boff[np]
                            + ((ckh ^ bxr[np]) << 4);                  // Bh
                uint32_t q0, q1, q2, q3;
                LDSM4(q0, q1, q2, q3, ad);
                bh[2 * np][0] = q0; bh[2 * np + 1][0] = q1;
                bh[2 * np][1] = q2; bh[2 * np + 1][1] = q3;
            }
            #pragma unroll
            for (int mt = 0; mt < 4; ++mt) {
                uint32_t ad = sb + 1u * TILE_B + aoff[mt]
                            + ((ckh ^ axr[mt]) << 4);                  // Al
                LDSM4(al[mt][0], al[mt][1], al[mt][2], al[mt][3], ad);
            }

            // ---- pass 1: Ah * Bh ----
            #pragma unroll
            for (int mt = 0; mt < 4; ++mt)
                #pragma unroll
                for (int nt = 0; nt < 4; ++nt)
                    MMA(acc[mt][nt], ah[mt], bh[nt][0], bh[nt][1]);

            // ---- Bl loads under the pass-2 MMA shadow ----
            if (PASSES >= 3) {
                #pragma unroll
                for (int np = 0; np < 2; ++np) {
                    uint32_t ad = sb + 3u * TILE_B + boff[np]
                                + ((ckh ^ bxr[np]) << 4);              // Bl
                    uint32_t q0, q1, q2, q3;
                    LDSM4(q0, q1, q2, q3, ad);
                    bl[2 * np][0] = q0; bl[2 * np + 1][0] = q1;
                    bl[2 * np][1] = q2; bl[2 * np + 1][1] = q3;
                }
            }

            // ---- pass 2: Al * Bh ----
            #pragma unroll
            for (int mt = 0; mt < 4; ++mt)
                #pragma unroll
                for (int nt = 0; nt < 4; ++nt)
                    MMA(acc[mt][nt], al[mt], bh[nt][0], bh[nt][1]);

            // ---- pass 3: Ah * Bl ----
            if (PASSES >= 3) {
                #pragma unroll
                for (int mt = 0; mt < 4; ++mt)
                    #pragma unroll
                    for (int nt = 0; nt < 4; ++nt)
                        MMA(acc[mt][nt], ah[mt], bl[nt][0], bl[nt][1]);
            }
        }
        // no bottom barrier: next iteration's top barrier orders reuse
    }
    #undef ISSUE_STAGE

    const int lm = lid >> 2, lc = (lid & 3) * 2;
    #pragma unroll
    for (int mt = 0; mt < 4; ++mt) {
        #pragma unroll
        for (int hrow = 0; hrow < 2; ++hrow) {
            const int row = m0 + wm + mt * 16 + lm + hrow * 8;
            #pragma unroll
            for (int nt = 0; nt < 4; ++nt) {
                const int col = n0 + wn + nt * 8 + lc;
                float d0 = acc[mt][nt][hrow * 2 + 0];
                float d1 = acc[mt][nt][hrow * 2 + 1];
                const long long idx = (long long)row * N + col;
                if (OUT_HALF) {
                    __half h0, l0, h1, l1;
                    split_h(d0, h0, l0);
                    split_h(d1, h1, l1);
                    *(__half2*)&Ch[idx] = __halves2half2(h0, h1);
                    *(__half2*)&Cl[idx] = __halves2half2(l0, l1);
                } else {
                    if (bias) { d0 += bias[col]; d1 += bias[col + 1]; }
                    *(float2*)&Cf[idx] = make_float2(d0, d1);
                }
            }
        }
    }
}

// ---------------------------------------------------------------------------
// mode 0: plain  mode 1: causal tile skip  mode 2: k-limit (heavy tiles first)
// ---------------------------------------------------------------------------
template <int OUT_HALF, int PASSES>
__global__ __launch_bounds__(256, 2)
void hmma_gemm(const __half* __restrict__ pAh, const __half* __restrict__ pAl,
               const __half* __restrict__ pBh, const __half* __restrict__ pBl,
               float* __restrict__ Cf, __half* __restrict__ Ch,
               __half* __restrict__ Cl, const float* __restrict__ bias,
               int M, int N, int K,
               long long sA, long long sB, long long sC, int mode)
{
    const int bn = blockIdx.x, bz = blockIdx.z;
    int bm = blockIdx.y;
    if (mode == 1 && bn > bm) return;
    if (mode == 2) bm = gridDim.y - 1 - blockIdx.y;
    const int kend = (mode == 2) ? (bm * BM + BM) : K;

    gemm_body<OUT_HALF, PASSES>(
        pAh + (long long)bz * sA, pAl + (long long)bz * sA,
        pBh + (long long)bz * sB, pBl + (long long)bz * sB,
        OUT_HALF ? nullptr : Cf + (long long)bz * sC,
        OUT_HALF ? Ch + (long long)bz * sC : nullptr,
        OUT_HALF ? Cl + (long long)bz * sC : nullptr,
        bias, N, K, kend, bm * BM, bn * BN);
}

// ---------------------------------------------------------------------------
// Merged Q/K/V projection: blockIdx.z selects the weight + output.
// Q,K -> fp16 hi/lo (3-pass).  V -> fp32 (2-pass).
// ---------------------------------------------------------------------------
__global__ __launch_bounds__(256, 2)
void qkv_gemm(const __half* __restrict__ Xh, const __half* __restrict__ Xl,
              const __half* __restrict__ WQh, const __half* __restrict__ WQl,
              const __half* __restrict__ WKh, const __half* __restrict__ WKl,
              const __half* __restrict__ WVh, const __half* __restrict__ WVl,
              __half* __restrict__ Qh, __half* __restrict__ Ql,
              __half* __restrict__ Kh, __half* __restrict__ Kl,
              float* __restrict__ Vf, int N, int K)
{
    const int m0 = blockIdx.y * BM, n0 = blockIdx.x * BN, bz = blockIdx.z;
    if (bz == 0)
        gemm_body<1, 3>(Xh, Xl, WQh, WQl, nullptr, Qh, Ql, nullptr,
                        N, K, K, m0, n0);
    else if (bz == 1)
        gemm_body<1, 3>(Xh, Xl, WKh, WKl, nullptr, Kh, Kl, nullptr,
                        N, K, K, m0, n0);
    else
        gemm_body<0, 2>(Xh, Xl, WVh, WVl, Vf, nullptr, nullptr, nullptr,
                        N, K, K, m0, n0);
}

// ---------------------------------------------------------------------------
// Merged fp32 -> fp16 hi/lo split for X + the 4 weight matrices (one launch).
// ---------------------------------------------------------------------------
__global__ __launch_bounds__(256)
void split_all_kernel(const float* __restrict__ X, const float* __restrict__ WQ,
                      const float* __restrict__ WK, const float* __restrict__ WV,
                      const float* __restrict__ WO,
                      __half* __restrict__ Xh, __half* __restrict__ Xl,
                      __half* __restrict__ WQh, __half* __restrict__ WQl,
                      __half* __restrict__ WKh, __half* __restrict__ WKl,
                      __half* __restrict__ WVh, __half* __restrict__ WVl,
                      __half* __restrict__ WOh, __half* __restrict__ WOl,
                      int nbX, int nbW)
{
    const float* in;
    __half *h, *l;
    long long i;
    int bid = blockIdx.x;
    if (bid < nbX) {
        in = X; h = Xh; l = Xl;
        i = (long long)bid * 256 + threadIdx.x;
    } else {
        int w = (bid - nbX) / nbW;
        int rb = (bid - nbX) - w * nbW;
        in = (w == 0) ? WQ : (w == 1) ? WK : (w == 2) ? WV : WO;
        h  = (w == 0) ? WQh : (w == 1) ? WKh : (w == 2) ? WVh : WOh;
        l  = (w == 0) ? WQl : (w == 1) ? WKl : (w == 2) ? WVl : WOl;
        i = (long long)rb * 256 + threadIdx.x;
    }
    float4 v = ((const float4*)in)[i];
    __half h0, l0, h1, l1, h2, l2, h3, l3;
    split_h(v.x, h0, l0); split_h(v.y, h1, l1);
    split_h(v.z, h2, l2); split_h(v.w, h3, l3);
    ((__half2*)h)[2 * i]     = __halves2half2(h0, h1);
    ((__half2*)h)[2 * i + 1] = __halves2half2(h2, h3);
    ((__half2*)l)[2 * i]     = __halves2half2(l0, l1);
    ((__half2*)l)[2 * i + 1] = __halves2half2(l2, l3);
}

// ---------------------------------------------------------------------------
// per-batch transpose: V[b][s][d] fp32 -> Vt[b][d][s] fp16 (hi only)
// ---------------------------------------------------------------------------
__global__ __launch_bounds__(256)
void trans_split_kernel(const float* __restrict__ V, __half* __restrict__ Th,
                        int S, int D)
{
    __shared__ float t[32][33];
    const int b = blockIdx.z;
    const int s0 = blockIdx.x * 32, d0 = blockIdx.y * 32;
    const float* Vb = V + (long long)b * S * D;
    #pragma unroll
    for (int i = 0; i < 4; ++i) {
        int s = threadIdx.y + i * 8;
        t[s][threadIdx.x] = Vb[(long long)(s0 + s) * D + d0 + threadIdx.x];
    }
    __syncthreads();
    const long long ob = (long long)b * D * S;
    #pragma unroll
    for (int i = 0; i < 4; ++i) {
        int d = threadIdx.y + i * 8;
        Th[ob + (long long)(d0 + d) * S + s0 + threadIdx.x] =
            __float2half_rn(t[threadIdx.x][d]);
    }
}

// ---------------------------------------------------------------------------
// Causal row softmax. Register-cached; zero-fills only the diagonal 128-band.
// ---------------------------------------------------------------------------
__global__ __launch_bounds__(256)
void softmax_causal_kernel(const float* __restrict__ P, __half* __restrict__ Ph,
                           __half* __restrict__ Pl, int S)
{
    const int b = blockIdx.y, i = blockIdx.x;
    const long long base = ((long long)b * S + i) * S;
    const float* row = P + base;
    const int n = i + 1;
    const int tid = threadIdx.x;
    __shared__ float red[8];

    float v[8];
    const int nt = (n + 255) >> 8;

    float m = -3.4e38f;
    #pragma unroll
    for (int t = 0; t < 8; ++t) {
        if (t < nt) {
            int j = t * 256 + tid;
            v[t] = (j < n) ? row[j] : -3.4e38f;
            m = fmaxf(m, v[t]);
        }
    }
    #pragma unroll
    for (int o = 16; o; o >>= 1) m = fmaxf(m, __shfl_xor_sync(~0u, m, o));
    if ((tid & 31) == 0) red[tid >> 5] = m;
    __syncthreads();
    if (tid < 32) {
        float x = (tid < 8) ? red[tid] : -3.4e38f;
        #pragma unroll
        for (int o = 4; o; o >>= 1) x = fmaxf(x, __shfl_xor_sync(~0u, x, o));
        if (tid == 0) red[0] = x;
    }
    __syncthreads();
    m = red[0];
    __syncthreads();

    float s = 0.f;
    #pragma unroll
    for (int t = 0; t < 8; ++t) {
        if (t < nt) {
            int j = t * 256 + tid;
            v[t] = (j < n) ? __expf(v[t] - m) : 0.f;
            s += v[t];
        }
    }
    #pragma unroll
    for (int o = 16; o; o >>= 1) s += __shfl_xor_sync(~0u, s, o);
    if ((tid & 31) == 0) red[tid >> 5] = s;
    __syncthreads();
    if (tid < 32) {
        float x = (tid < 8) ? red[tid] : 0.f;
        #pragma unroll
        for (int o = 4; o; o >>= 1) x += __shfl_xor_sync(~0u, x, o);
        if (tid == 0) red[0] = x;
    }
    __syncthreads();
    const float inv = 1.f / red[0];

    #pragma unroll
    for (int t = 0; t < 8; ++t) {
        if (t < nt) {
            int j = t * 256 + tid;
            if (j < n) {
                __half h, l;
                split_h(v[t] * inv, h, l);
                Ph[base + j] = h;
                Pl[base + j] = l;
            }
        }
    }
    const int band_end = (i & ~127) + 128;
    const __half z = __float2half_rn(0.f);
    for (int j = n + tid; j < band_end; j += 256) {
        Ph[base + j] = z;
        Pl[base + j] = z;
    }
}

// ---------------------------------------------------------------------------
extern "C" void kernel_launch(void* const* d_in, const int* in_sizes, int n_in,
                              void* d_out, int out_size)
{
    const float* X  = (const float*)d_in[0];
    const float* WQ = (const float*)d_in[1];
    const float* WK = (const float*)d_in[2];
    const float* WV = (const float*)d_in[3];
    const float* WO = (const float*)d_in[4];
    const float* bO = (const float*)d_in[5];
    float* out = (float*)d_out;

    float *V, *P;
    __half *Xh, *Xl, *WQh, *WQl, *WKh, *WKl, *WVh, *WVl, *WOh, *WOl;
    __half *Qh, *Ql, *Kh, *Kl, *Vth, *Ph, *Pl, *Oh, *Ol;
    cudaGetSymbolAddress((void**)&V, g_V);
    cudaGetSymbolAddress((void**)&P, g_P);
    cudaGetSymbolAddress((void**)&Xh, g_Xh);   cudaGetSymbolAddress((void**)&Xl, g_Xl);
    cudaGetSymbolAddress((void**)&WQh, g_WQh); cudaGetSymbolAddress((void**)&WQl, g_WQl);
    cudaGetSymbolAddress((void**)&WKh, g_WKh); cudaGetSymbolAddress((void**)&WKl, g_WKl);
    cudaGetSymbolAddress((void**)&WVh, g_WVh); cudaGetSymbolAddress((void**)&WVl, g_WVl);
    cudaGetSymbolAddress((void**)&WOh, g_WOh); cudaGetSymbolAddress((void**)&WOl, g_WOl);
    cudaGetSymbolAddress((void**)&Qh, g_Qh);   cudaGetSymbolAddress((void**)&Ql, g_Ql);
    cudaGetSymbolAddress((void**)&Kh, g_Kh);   cudaGetSymbolAddress((void**)&Kl, g_Kl);
    cudaGetSymbolAddress((void**)&Vth, g_Vth);
    cudaGetSymbolAddress((void**)&Ph, g_Ph);   cudaGetSymbolAddress((void**)&Pl, g_Pl);
    cudaGetSymbolAddress((void**)&Oh, g_Oh);   cudaGetSymbolAddress((void**)&Ol, g_Ol);

    cudaFuncSetAttribute((const void*)hmma_gemm<0, 3>,
                         cudaFuncAttributeMaxDynamicSharedMemorySize, SMEM_TOTAL);
    cudaFuncSetAttribute((const void*)hmma_gemm<0, 2>,
                         cudaFuncAttributeMaxDynamicSharedMemorySize, SMEM_TOTAL);
    cudaFuncSetAttribute((const void*)hmma_gemm<1, 2>,
                         cudaFuncAttributeMaxDynamicSharedMemorySize, SMEM_TOTAL);
    cudaFuncSetAttribute((const void*)qkv_gemm,
                         cudaFuncAttributeMaxDynamicSharedMemorySize, SMEM_TOTAL);

    const int B = 4, S = 2048, D = 1024, M = B * S;
    const long long SD = (long long)S * D;
    const long long SS = (long long)S * S;

    dim3 blk(256);

    // ---- merged split: X + 4 weights, one launch ----
    const int nbX = (int)((long long)M * D / 4 / 256);   // 8192
    const int nbW = D * D / 4 / 256;                     // 1024
    split_all_kernel<<<nbX + 4 * nbW, blk>>>(X, WQ, WK, WV, WO,
                                             Xh, Xl, WQh, WQl, WKh, WKl,
                                             WVh, WVl, WOh, WOl, nbX, nbW);

    // merged Q/K/V projections (Q,K 3-pass fp16 out; V 2-pass fp32 out)
    dim3 gqkv(D / BN, M / BM, 3);
    qkv_gemm<<<gqkv, blk, SMEM_TOTAL>>>(Xh, Xl, WQh, WQl, WKh, WKl, WVh, WVl,
                                        Qh, Ql, Kh, Kl, V, D, D);
    trans_split_kernel<<<dim3(S / 32, D / 32, B), dim3(32, 8)>>>(V, Vth, S, D);

    // logits: P[b] = Q[b] @ K[b]^T  (causal tile skip, 3-pass)
    dim3 glog(S / BN, S / BM, B);
    hmma_gemm<0, 3><<<glog, blk, SMEM_TOTAL>>>(Qh, Ql, Kh, Kl, P, nullptr,
                                               nullptr, nullptr,
                                               S, S, D, SD, SD, SS, 1);

    // causal softmax -> fp16 hi/lo probs (diagonal-band zero fill only)
    softmax_causal_kernel<<<dim3(S, B), blk>>>(P, Ph, Pl, S);

    // attn out: O[b] = P[b] @ Vt[b]^T (NT, k-limited, heavy-first, 2-pass)
    dim3 gpv(D / BN, S / BM, B);
    hmma_gemm<1, 2><<<gpv, blk, SMEM_TOTAL>>>(Ph, Pl, Vth, Vth, nullptr, Oh,
                                              Ol, nullptr,
                                              S, D, S, SS, SD, SD, 2);

    // output projection + bias -> fp32 out (2-pass)
    dim3 gproj(D / BN, M / BM, 1);
    hmma_gemm<0, 2><<<gproj, blk, SMEM_TOTAL>>>(Oh, Ol, WOh, WOl, out, nullptr,
                                                nullptr, bO,
                                                M, D, D, 0, 0, 0, 0);
}

// round 11
// speedup vs baseline: 3.4576x; 1.0291x over previous
#include <cuda_runtime.h>
#include <cuda_fp16.h>
#include <stdint.h>

#define BM 128
#define BN 128
#define BK 32
#define TILE_B (BM * BK * 2)            // 8 KB per operand tile
#define STAGE_B (4 * TILE_B)            // 32 KB  (Ah, Al, Bh, Bl)
#define SMEM_TOTAL (2 * STAGE_B)        // 64 KB, 2 stages -> 2 CTAs/SM

// ---------------- scratch (device globals: allocation-free) ----------------
__device__ float  g_V[4LL * 2048 * 1024];
__device__ float  g_P[4LL * 2048 * 2048];
__device__ __half g_Xh[8192LL * 1024],  g_Xl[8192LL * 1024];
__device__ __half g_WQh[1024 * 1024],   g_WQl[1024 * 1024];
__device__ __half g_WKh[1024 * 1024],   g_WKl[1024 * 1024];
__device__ __half g_WVh[1024 * 1024],   g_WVl[1024 * 1024];
__device__ __half g_WOh[1024 * 1024],   g_WOl[1024 * 1024];
__device__ __half g_Qh[8192LL * 1024],  g_Ql[8192LL * 1024];
__device__ __half g_Kh[8192LL * 1024],  g_Kl[8192LL * 1024];
__device__ __half g_Vth[4LL * 1024 * 2048];
__device__ __half g_Ph[4LL * 2048 * 2048],  g_Pl[4LL * 2048 * 2048];
__device__ __half g_Oh[8192LL * 1024],  g_Ol[8192LL * 1024];

// ---------------- base-PTX helpers ----------------
__device__ __forceinline__ uint32_t smem_u32(const void* p) {
    uint32_t a;
    asm("{ .reg .u64 t; cvta.to.shared.u64 t, %1; cvt.u32.u64 %0, t; }"
        : "=r"(a) : "l"(p));
    return a;
}
#define CP_ASYNC16(sa, ga) \
    asm volatile("cp.async.cg.shared.global [%0], [%1], 16;" :: "r"(sa), "l"(ga))
#define CP_COMMIT() asm volatile("cp.async.commit_group;" ::: "memory")
#define CP_WAIT(n)  asm volatile("cp.async.wait_group %0;" :: "n"(n) : "memory")
#define LDSM4(d0, d1, d2, d3, a) \
    asm volatile("ldmatrix.sync.aligned.m8n8.x4.shared.b16 {%0,%1,%2,%3}, [%4];" \
                 : "=r"(d0), "=r"(d1), "=r"(d2), "=r"(d3) : "r"(a))
#define MMA(d, a, b0, b1) \
    asm volatile("mma.sync.aligned.m16n8k16.row.col.f32.f16.f16.f32 " \
                 "{%0,%1,%2,%3}, {%4,%5,%6,%7}, {%8,%9}, {%0,%1,%2,%3};" \
                 : "+f"((d)[0]), "+f"((d)[1]), "+f"((d)[2]), "+f"((d)[3]) \
                 : "r"((a)[0]), "r"((a)[1]), "r"((a)[2]), "r"((a)[3]), \
                   "r"(b0), "r"(b1))

// smem tile layout: [128 rows][4 chunks of 16B], chunk xor-swizzled.
__device__ __forceinline__ uint32_t swz(uint32_t r, uint32_t c) {
    return r * 64u + ((c ^ ((r >> 1) & 3u)) << 4);
}

__device__ __forceinline__ void split_h(float x, __half& h, __half& l) {
    h = __float2half_rn(x);
    l = __float2half_rn(x - __half2float(h));
}

// ---------------------------------------------------------------------------
// One stage of fp16x3 compute. ST (stage slot) is compile-time so every LDSM
// address is a single add of a precomputed register and an immediate.
// aoffk/boffk hold sbase + row*64 + (xor<<4) per (ks, subtile).
// ---------------------------------------------------------------------------
template <int ST, int PASSES>
__device__ __forceinline__ void compute_stage(
    const uint32_t aoffk[2][4], const uint32_t boffk[2][2],
    float acc[4][4][4])
{
    #pragma unroll
    for (int ks = 0; ks < 2; ++ks) {
        uint32_t ah[4][4], al[4][4], bh[4][2], bl[4][2];

        // ---- fragment loads: Ah(4), Bh(2), Al(4) ----
        #pragma unroll
        for (int mt = 0; mt < 4; ++mt) {
            uint32_t ad = aoffk[ks][mt] + (ST * STAGE_B);          // Ah
            LDSM4(ah[mt][0], ah[mt][1], ah[mt][2], ah[mt][3], ad);
        }
        #pragma unroll
        for (int np = 0; np < 2; ++np) {
            uint32_t ad = boffk[ks][np] + (ST * STAGE_B + 2 * TILE_B); // Bh
            uint32_t q0, q1, q2, q3;
            LDSM4(q0, q1, q2, q3, ad);
            bh[2 * np][0] = q0; bh[2 * np + 1][0] = q1;
            bh[2 * np][1] = q2; bh[2 * np + 1][1] = q3;
        }
        #pragma unroll
        for (int mt = 0; mt < 4; ++mt) {
            uint32_t ad = aoffk[ks][mt] + (ST * STAGE_B + TILE_B); // Al
            LDSM4(al[mt][0], al[mt][1], al[mt][2], al[mt][3], ad);
        }

        // ---- pass 1: Ah * Bh ----
        #pragma unroll
        for (int mt = 0; mt < 4; ++mt)
            #pragma unroll
            for (int nt = 0; nt < 4; ++nt)
                MMA(acc[mt][nt], ah[mt], bh[nt][0], bh[nt][1]);

        // ---- Bl loads under the pass-2 MMA shadow ----
        if (PASSES >= 3) {
            #pragma unroll
            for (int np = 0; np < 2; ++np) {
                uint32_t ad = boffk[ks][np] + (ST * STAGE_B + 3 * TILE_B); // Bl
                uint32_t q0, q1, q2, q3;
                LDSM4(q0, q1, q2, q3, ad);
                bl[2 * np][0] = q0; bl[2 * np + 1][0] = q1;
                bl[2 * np][1] = q2; bl[2 * np + 1][1] = q3;
            }
        }

        // ---- pass 2: Al * Bh ----
        #pragma unroll
        for (int mt = 0; mt < 4; ++mt)
            #pragma unroll
            for (int nt = 0; nt < 4; ++nt)
                MMA(acc[mt][nt], al[mt], bh[nt][0], bh[nt][1]);

        // ---- pass 3: Ah * Bl ----
        if (PASSES >= 3) {
            #pragma unroll
            for (int mt = 0; mt < 4; ++mt)
                #pragma unroll
                for (int nt = 0; nt < 4; ++nt)
                    MMA(acc[mt][nt], ah[mt], bl[nt][0], bl[nt][1]);
        }
    }
}

// ---------------------------------------------------------------------------
// fp16x3 HMMA GEMM body:  C[m,n] = sum_k A[m,k] * B[n,k]  (NT, row-major)
//   PASSES==3: Ah*Bh + Al*Bh + Ah*Bl.  PASSES==2: Ah*Bh + Al*Bh (Bl unused).
// 2-stage pipeline, k-loop hand-unrolled x2 so all smem addressing folds to
// register + immediate. nk is always even (kend multiple of 128).
// OUT_HALF 0: write fp32 C (+bias).  1: write fp16 hi/lo pair.
// ---------------------------------------------------------------------------
template <int OUT_HALF, int PASSES>
__device__ __forceinline__ void gemm_body(
    const __half* __restrict__ pAh, const __half* __restrict__ pAl,
    const __half* __restrict__ pBh, const __half* __restrict__ pBl,
    float* __restrict__ Cf, __half* __restrict__ Ch, __half* __restrict__ Cl,
    const float* __restrict__ bias,
    int N, int K, int kend, int m0, int n0)
{
    extern __shared__ char smem[];
    const int nk = kend / BK;
    constexpr int NLOAD = (PASSES >= 3) ? 8 : 6;

    const int tid = threadIdx.x;
    const int r0 = tid >> 2;        // 0..63
    const int c0 = tid & 3;         // 16B chunk within 64B row

    // incremental gmem pointers (advance by BK halves per issued stage)
    const __half* src0 = pAh + (long long)(m0 + r0) * K + c0 * 8;
    const __half* src1 = src0 + 64LL * K;
    const __half* src2 = pAl + (long long)(m0 + r0) * K + c0 * 8;
    const __half* src3 = src2 + 64LL * K;
    const __half* src4 = pBh + (long long)(n0 + r0) * K + c0 * 8;
    const __half* src5 = src4 + 64LL * K;
    const __half* src6 = pBl + (long long)(n0 + r0) * K + c0 * 8;
    const __half* src7 = src6 + 64LL * K;

    const uint32_t sbase = smem_u32(smem);
    const uint32_t w0 = sbase + swz((uint32_t)r0, (uint32_t)c0);
    const uint32_t w1 = w0 + 64u * 64u;
    uint32_t dsts[8];
    #pragma unroll
    for (int t = 0; t < 4; ++t) {
        dsts[2 * t]     = (uint32_t)t * TILE_B + w0;
        dsts[2 * t + 1] = (uint32_t)t * TILE_B + w1;
    }

    const int wid = tid >> 5, lid = tid & 31;
    const int wm = (wid >> 2) * 64;
    const int wn = (wid & 3) * 32;
    const int lrow = lid & 15;
    const int lkh  = lid >> 4;

    // fully precomputed LDSM base addresses (incl. sbase) per (ks, subtile)
    uint32_t aoffk[2][4], boffk[2][2];
    #pragma unroll
    for (int ks = 0; ks < 2; ++ks) {
        const uint32_t ckh = 2u * ks + (uint32_t)lkh;
        #pragma unroll
        for (int mt = 0; mt < 4; ++mt) {
            uint32_t row = (uint32_t)(wm + mt * 16 + lrow);
            aoffk[ks][mt] = sbase + row * 64u
                          + ((ckh ^ ((row >> 1) & 3u)) << 4);
        }
        #pragma unroll
        for (int np = 0; np < 2; ++np) {
            uint32_t row = (uint32_t)(wn + np * 16 + lrow);
            boffk[ks][np] = sbase + row * 64u
                          + ((ckh ^ ((row >> 1) & 3u)) << 4);
        }
    }

    float acc[4][4][4] = {};

    #define ISSUE_STAGE(ST)                                                  \
        do {                                                                 \
            CP_ASYNC16(dsts[0] + (ST) * STAGE_B, src0);                      \
            CP_ASYNC16(dsts[1] + (ST) * STAGE_B, src1);                      \
            CP_ASYNC16(dsts[2] + (ST) * STAGE_B, src2);                      \
            CP_ASYNC16(dsts[3] + (ST) * STAGE_B, src3);                      \
            CP_ASYNC16(dsts[4] + (ST) * STAGE_B, src4);                      \
            CP_ASYNC16(dsts[5] + (ST) * STAGE_B, src5);                      \
            if (NLOAD > 6) {                                                 \
                CP_ASYNC16(dsts[6] + (ST) * STAGE_B, src6);                  \
                CP_ASYNC16(dsts[7] + (ST) * STAGE_B, src7);                  \
            }                                                                \
            src0 += BK; src1 += BK; src2 += BK; src3 += BK;                  \
            src4 += BK; src5 += BK; src6 += BK; src7 += BK;                  \
        } while (0)

    // prologue: stage 0 in flight
    ISSUE_STAGE(0);
    CP_COMMIT();

    for (int kt = 0; kt < nk; kt += 2) {
        // ---- stage slot 0 (k-tile kt) ----
        CP_WAIT(0);
        __syncthreads();            // slot 0 data ready; slot 1 free to write
        if (kt + 1 < nk) ISSUE_STAGE(1);
        CP_COMMIT();
        compute_stage<0, PASSES>(aoffk, boffk, acc);

        // ---- stage slot 1 (k-tile kt+1) ----
        CP_WAIT(0);
        __syncthreads();            // slot 1 data ready; slot 0 free to write
        if (kt + 2 < nk) ISSUE_STAGE(0);
        CP_COMMIT();
        compute_stage<1, PASSES>(aoffk, boffk, acc);
    }
    #undef ISSUE_STAGE

    const int lm = lid >> 2, lc = (lid & 3) * 2;
    #pragma unroll
    for (int mt = 0; mt < 4; ++mt) {
        #pragma unroll
        for (int hrow = 0; hrow < 2; ++hrow) {
            const int row = m0 + wm + mt * 16 + lm + hrow * 8;
            #pragma unroll
            for (int nt = 0; nt < 4; ++nt) {
                const int col = n0 + wn + nt * 8 + lc;
                float d0 = acc[mt][nt][hrow * 2 + 0];
                float d1 = acc[mt][nt][hrow * 2 + 1];
                const long long idx = (long long)row * N + col;
                if (OUT_HALF) {
                    __half h0, l0, h1, l1;
                    split_h(d0, h0, l0);
                    split_h(d1, h1, l1);
                    *(__half2*)&Ch[idx] = __halves2half2(h0, h1);
                    *(__half2*)&Cl[idx] = __halves2half2(l0, l1);
                } else {
                    if (bias) { d0 += bias[col]; d1 += bias[col + 1]; }
                    *(float2*)&Cf[idx] = make_float2(d0, d1);
                }
            }
        }
    }
}

// ---------------------------------------------------------------------------
// mode 0: plain  mode 1: causal tile skip  mode 2: k-limit (heavy tiles first)
// ---------------------------------------------------------------------------
template <int OUT_HALF, int PASSES>
__global__ __launch_bounds__(256, 2)
void hmma_gemm(const __half* __restrict__ pAh, const __half* __restrict__ pAl,
               const __half* __restrict__ pBh, const __half* __restrict__ pBl,
               float* __restrict__ Cf, __half* __restrict__ Ch,
               __half* __restrict__ Cl, const float* __restrict__ bias,
               int M, int N, int K,
               long long sA, long long sB, long long sC, int mode)
{
    const int bn = blockIdx.x, bz = blockIdx.z;
    int bm = blockIdx.y;
    if (mode == 1 && bn > bm) return;
    if (mode == 2) bm = gridDim.y - 1 - blockIdx.y;
    const int kend = (mode == 2) ? (bm * BM + BM) : K;

    gemm_body<OUT_HALF, PASSES>(
        pAh + (long long)bz * sA, pAl + (long long)bz * sA,
        pBh + (long long)bz * sB, pBl + (long long)bz * sB,
        OUT_HALF ? nullptr : Cf + (long long)bz * sC,
        OUT_HALF ? Ch + (long long)bz * sC : nullptr,
        OUT_HALF ? Cl + (long long)bz * sC : nullptr,
        bias, N, K, kend, bm * BM, bn * BN);
}

// ---------------------------------------------------------------------------
// Merged Q/K/V projection: blockIdx.z selects the weight + output.
// Q,K -> fp16 hi/lo (3-pass).  V -> fp32 (2-pass).
// ---------------------------------------------------------------------------
__global__ __launch_bounds__(256, 2)
void qkv_gemm(const __half* __restrict__ Xh, const __half* __restrict__ Xl,
              const __half* __restrict__ WQh, const __half* __restrict__ WQl,
              const __half* __restrict__ WKh, const __half* __restrict__ WKl,
              const __half* __restrict__ WVh, const __half* __restrict__ WVl,
              __half* __restrict__ Qh, __half* __restrict__ Ql,
              __half* __restrict__ Kh, __half* __restrict__ Kl,
              float* __restrict__ Vf, int N, int K)
{
    const int m0 = blockIdx.y * BM, n0 = blockIdx.x * BN, bz = blockIdx.z;
    if (bz == 0)
        gemm_body<1, 3>(Xh, Xl, WQh, WQl, nullptr, Qh, Ql, nullptr,
                        N, K, K, m0, n0);
    else if (bz == 1)
        gemm_body<1, 3>(Xh, Xl, WKh, WKl, nullptr, Kh, Kl, nullptr,
                        N, K, K, m0, n0);
    else
        gemm_body<0, 2>(Xh, Xl, WVh, WVl, Vf, nullptr, nullptr, nullptr,
                        N, K, K, m0, n0);
}

// ---------------------------------------------------------------------------
// Merged fp32 -> fp16 hi/lo split for X + the 4 weight matrices (one launch).
// ---------------------------------------------------------------------------
__global__ __launch_bounds__(256)
void split_all_kernel(const float* __restrict__ X, const float* __restrict__ WQ,
                      const float* __restrict__ WK, const float* __restrict__ WV,
                      const float* __restrict__ WO,
                      __half* __restrict__ Xh, __half* __restrict__ Xl,
                      __half* __restrict__ WQh, __half* __restrict__ WQl,
                      __half* __restrict__ WKh, __half* __restrict__ WKl,
                      __half* __restrict__ WVh, __half* __restrict__ WVl,
                      __half* __restrict__ WOh, __half* __restrict__ WOl,
                      int nbX, int nbW)
{
    const float* in;
    __half *h, *l;
    long long i;
    int bid = blockIdx.x;
    if (bid < nbX) {
        in = X; h = Xh; l = Xl;
        i = (long long)bid * 256 + threadIdx.x;
    } else {
        int w = (bid - nbX) / nbW;
        int rb = (bid - nbX) - w * nbW;
        in = (w == 0) ? WQ : (w == 1) ? WK : (w == 2) ? WV : WO;
        h  = (w == 0) ? WQh : (w == 1) ? WKh : (w == 2) ? WVh : WOh;
        l  = (w == 0) ? WQl : (w == 1) ? WKl : (w == 2) ? WVl : WOl;
        i = (long long)rb * 256 + threadIdx.x;
    }
    float4 v = ((const float4*)in)[i];
    __half h0, l0, h1, l1, h2, l2, h3, l3;
    split_h(v.x, h0, l0); split_h(v.y, h1, l1);
    split_h(v.z, h2, l2); split_h(v.w, h3, l3);
    ((__half2*)h)[2 * i]     = __halves2half2(h0, h1);
    ((__half2*)h)[2 * i + 1] = __halves2half2(h2, h3);
    ((__half2*)l)[2 * i]     = __halves2half2(l0, l1);
    ((__half2*)l)[2 * i + 1] = __halves2half2(l2, l3);
}

// ---------------------------------------------------------------------------
// per-batch transpose: V[b][s][d] fp32 -> Vt[b][d][s] fp16 (hi only)
// ---------------------------------------------------------------------------
__global__ __launch_bounds__(256)
void trans_split_kernel(const float* __restrict__ V, __half* __restrict__ Th,
                        int S, int D)
{
    __shared__ float t[32][33];
    const int b = blockIdx.z;
    const int s0 = blockIdx.x * 32, d0 = blockIdx.y * 32;
    const float* Vb = V + (long long)b * S * D;
    #pragma unroll
    for (int i = 0; i < 4; ++i) {
        int s = threadIdx.y + i * 8;
        t[s][threadIdx.x] = Vb[(long long)(s0 + s) * D + d0 + threadIdx.x];
    }
    __syncthreads();
    const long long ob = (long long)b * D * S;
    #pragma unroll
    for (int i = 0; i < 4; ++i) {
        int d = threadIdx.y + i * 8;
        Th[ob + (long long)(d0 + d) * S + s0 + threadIdx.x] =
            __float2half_rn(t[threadIdx.x][d]);
    }
}

// ---------------------------------------------------------------------------
// Causal row softmax. Register-cached; zero-fills only the diagonal 128-band.
// ---------------------------------------------------------------------------
__global__ __launch_bounds__(256)
void softmax_causal_kernel(const float* __restrict__ P, __half* __restrict__ Ph,
                           __half* __restrict__ Pl, int S)
{
    const int b = blockIdx.y, i = blockIdx.x;
    const long long base = ((long long)b * S + i) * S;
    const float* row = P + base;
    const int n = i + 1;
    const int tid = threadIdx.x;
    __shared__ float red[8];

    float v[8];
    const int nt = (n + 255) >> 8;

    float m = -3.4e38f;
    #pragma unroll
    for (int t = 0; t < 8; ++t) {
        if (t < nt) {
            int j = t * 256 + tid;
            v[t] = (j < n) ? row[j] : -3.4e38f;
            m = fmaxf(m, v[t]);
        }
    }
    #pragma unroll
    for (int o = 16; o; o >>= 1) m = fmaxf(m, __shfl_xor_sync(~0u, m, o));
    if ((tid & 31) == 0) red[tid >> 5] = m;
    __syncthreads();
    if (tid < 32) {
        float x = (tid < 8) ? red[tid] : -3.4e38f;
        #pragma unroll
        for (int o = 4; o; o >>= 1) x = fmaxf(x, __shfl_xor_sync(~0u, x, o));
        if (tid == 0) red[0] = x;
    }
    __syncthreads();
    m = red[0];
    __syncthreads();

    float s = 0.f;
    #pragma unroll
    for (int t = 0; t < 8; ++t) {
        if (t < nt) {
            int j = t * 256 + tid;
            v[t] = (j < n) ? __expf(v[t] - m) : 0.f;
            s += v[t];
        }
    }
    #pragma unroll
    for (int o = 16; o; o >>= 1) s += __shfl_xor_sync(~0u, s, o);
    if ((tid & 31) == 0) red[tid >> 5] = s;
    __syncthreads();
    if (tid < 32) {
        float x = (tid < 8) ? red[tid] : 0.f;
        #pragma unroll
        for (int o = 4; o; o >>= 1) x += __shfl_xor_sync(~0u, x, o);
        if (tid == 0) red[0] = x;
    }
    __syncthreads();
    const float inv = 1.f / red[0];

    #pragma unroll
    for (int t = 0; t < 8; ++t) {
        if (t < nt) {
            int j = t * 256 + tid;
            if (j < n) {
                __half h, l;
                split_h(v[t] * inv, h, l);
                Ph[base + j] = h;
                Pl[base + j] = l;
            }
        }
    }
    const int band_end = (i & ~127) + 128;
    const __half z = __float2half_rn(0.f);
    for (int j = n + tid; j < band_end; j += 256) {
        Ph[base + j] = z;
        Pl[base + j] = z;
    }
}

// ---------------------------------------------------------------------------
extern "C" void kernel_launch(void* const* d_in, const int* in_sizes, int n_in,
                              void* d_out, int out_size)
{
    const float* X  = (const float*)d_in[0];
    const float* WQ = (const float*)d_in[1];
    const float* WK = (const float*)d_in[2];
    const float* WV = (const float*)d_in[3];
    const float* WO = (const float*)d_in[4];
    const float* bO = (const float*)d_in[5];
    float* out = (float*)d_out;

    float *V, *P;
    __half *Xh, *Xl, *WQh, *WQl, *WKh, *WKl, *WVh, *WVl, *WOh, *WOl;
    __half *Qh, *Ql, *Kh, *Kl, *Vth, *Ph, *Pl, *Oh, *Ol;
    cudaGetSymbolAddress((void**)&V, g_V);
    cudaGetSymbolAddress((void**)&P, g_P);
    cudaGetSymbolAddress((void**)&Xh, g_Xh);   cudaGetSymbolAddress((void**)&Xl, g_Xl);
    cudaGetSymbolAddress((void**)&WQh, g_WQh); cudaGetSymbolAddress((void**)&WQl, g_WQl);
    cudaGetSymbolAddress((void**)&WKh, g_WKh); cudaGetSymbolAddress((void**)&WKl, g_WKl);
    cudaGetSymbolAddress((void**)&WVh, g_WVh); cudaGetSymbolAddress((void**)&WVl, g_WVl);
    cudaGetSymbolAddress((void**)&WOh, g_WOh); cudaGetSymbolAddress((void**)&WOl, g_WOl);
    cudaGetSymbolAddress((void**)&Qh, g_Qh);   cudaGetSymbolAddress((void**)&Ql, g_Ql);
    cudaGetSymbolAddress((void**)&Kh, g_Kh);   cudaGetSymbolAddress((void**)&Kl, g_Kl);
    cudaGetSymbolAddress((void**)&Vth, g_Vth);
    cudaGetSymbolAddress((void**)&Ph, g_Ph);   cudaGetSymbolAddress((void**)&Pl, g_Pl);
    cudaGetSymbolAddress((void**)&Oh, g_Oh);   cudaGetSymbolAddress((void**)&Ol, g_Ol);

    cudaFuncSetAttribute((const void*)hmma_gemm<0, 3>,
                         cudaFuncAttributeMaxDynamicSharedMemorySize, SMEM_TOTAL);
    cudaFuncSetAttribute((const void*)hmma_gemm<0, 2>,
                         cudaFuncAttributeMaxDynamicSharedMemorySize, SMEM_TOTAL);
    cudaFuncSetAttribute((const void*)hmma_gemm<1, 2>,
                         cudaFuncAttributeMaxDynamicSharedMemorySize, SMEM_TOTAL);
    cudaFuncSetAttribute((const void*)qkv_gemm,
                         cudaFuncAttributeMaxDynamicSharedMemorySize, SMEM_TOTAL);

    const int B = 4, S = 2048, D = 1024, M = B * S;
    const long long SD = (long long)S * D;
    const long long SS = (long long)S * S;

    dim3 blk(256);

    // ---- merged split: X + 4 weights, one launch ----
    const int nbX = (int)((long long)M * D / 4 / 256);   // 8192
    const int nbW = D * D / 4 / 256;                     // 1024
    split_all_kernel<<<nbX + 4 * nbW, blk>>>(X, WQ, WK, WV, WO,
                                             Xh, Xl, WQh, WQl, WKh, WKl,
                                             WVh, WVl, WOh, WOl, nbX, nbW);

    // merged Q/K/V projections (Q,K 3-pass fp16 out; V 2-pass fp32 out)
    dim3 gqkv(D / BN, M / BM, 3);
    qkv_gemm<<<gqkv, blk, SMEM_TOTAL>>>(Xh, Xl, WQh, WQl, WKh, WKl, WVh, WVl,
                                        Qh, Ql, Kh, Kl, V, D, D);
    trans_split_kernel<<<dim3(S / 32, D / 32, B), dim3(32, 8)>>>(V, Vth, S, D);

    // logits: P[b] = Q[b] @ K[b]^T  (causal tile skip, 3-pass)
    dim3 glog(S / BN, S / BM, B);
    hmma_gemm<0, 3><<<glog, blk, SMEM_TOTAL>>>(Qh, Ql, Kh, Kl, P, nullptr,
                                               nullptr, nullptr,
                                               S, S, D, SD, SD, SS, 1);

    // causal softmax -> fp16 hi/lo probs (diagonal-band zero fill only)
    softmax_causal_kernel<<<dim3(S, B), blk>>>(P, Ph, Pl, S);

    // attn out: O[b] = P[b] @ Vt[b]^T (NT, k-limited, heavy-first, 2-pass)
    dim3 gpv(D / BN, S / BM, B);
    hmma_gemm<1, 2><<<gpv, blk, SMEM_TOTAL>>>(Ph, Pl, Vth, Vth, nullptr, Oh,
                                              Ol, nullptr,
                                              S, D, S, SS, SD, SD, 2);

    // output projection + bias -> fp32 out (2-pass)
    dim3 gproj(D / BN, M / BM, 1);
    hmma_gemm<0, 2><<<gproj, blk, SMEM_TOTAL>>>(Oh, Ol, WOh, WOl, out, nullptr,
                                                nullptr, bO,
                                                M, D, D, 0, 0, 0, 0);
}

// round 12
// speedup vs baseline: 4.0410x; 1.1687x over previous
#include <cuda_runtime.h>
#include <cuda_fp16.h>
#include <stdint.h>

#define BM 128
#define BN 128
#define BK 32
#define TILE_B (BM * BK * 2)            // 8 KB per operand tile
#define STAGE_B (4 * TILE_B)            // 32 KB  (Ah, Al, Bh, Bl)
#define SMEM_TOTAL (2 * STAGE_B)        // 64 KB, 2 stages -> 2 CTAs/SM

// ---------------- scratch (device globals: allocation-free) ----------------
__device__ float  g_P[4LL * 2048 * 2048];
__device__ __half g_Xh[8192LL * 1024],  g_Xl[8192LL * 1024];
__device__ __half g_WOh[1024 * 1024],   g_WOl[1024 * 1024];
__device__ __half g_Wqth[1024 * 1024],  g_Wqtl[1024 * 1024];
__device__ __half g_Wkth[1024 * 1024],  g_Wktl[1024 * 1024];
__device__ __half g_Wvth[1024 * 1024],  g_Wvtl[1024 * 1024];
__device__ __half g_Nh[1024 * 1024],    g_Nl[1024 * 1024];
__device__ __half g_Rh[1024 * 1024],    g_Rl[1024 * 1024];
__device__ __half g_Th[8192LL * 1024],  g_Tl[8192LL * 1024];
__device__ __half g_Uth[4LL * 1024 * 2048], g_Utl[4LL * 1024 * 2048];
__device__ __half g_Ph[4LL * 2048 * 2048],  g_Pl[4LL * 2048 * 2048];

// ---------------- base-PTX helpers ----------------
__device__ __forceinline__ uint32_t smem_u32(const void* p) {
    uint32_t a;
    asm("{ .reg .u64 t; cvta.to.shared.u64 t, %1; cvt.u32.u64 %0, t; }"
        : "=r"(a) : "l"(p));
    return a;
}
#define CP_ASYNC16(sa, ga) \
    asm volatile("cp.async.cg.shared.global [%0], [%1], 16;" :: "r"(sa), "l"(ga))
#define CP_COMMIT() asm volatile("cp.async.commit_group;" ::: "memory")
#define CP_WAIT(n)  asm volatile("cp.async.wait_group %0;" :: "n"(n) : "memory")
#define LDSM4(d0, d1, d2, d3, a) \
    asm volatile("ldmatrix.sync.aligned.m8n8.x4.shared.b16 {%0,%1,%2,%3}, [%4];" \
                 : "=r"(d0), "=r"(d1), "=r"(d2), "=r"(d3) : "r"(a))
#define MMA(d, a, b0, b1) \
    asm volatile("mma.sync.aligned.m16n8k16.row.col.f32.f16.f16.f32 " \
                 "{%0,%1,%2,%3}, {%4,%5,%6,%7}, {%8,%9}, {%0,%1,%2,%3};" \
                 : "+f"((d)[0]), "+f"((d)[1]), "+f"((d)[2]), "+f"((d)[3]) \
                 : "r"((a)[0]), "r"((a)[1]), "r"((a)[2]), "r"((a)[3]), \
                   "r"(b0), "r"(b1))

// smem tile layout: [128 rows][4 chunks of 16B], chunk xor-swizzled.
__device__ __forceinline__ uint32_t swz(uint32_t r, uint32_t c) {
    return r * 64u + ((c ^ ((r >> 1) & 3u)) << 4);
}

__device__ __forceinline__ void split_h(float x, __half& h, __half& l) {
    h = __float2half_rn(x);
    l = __float2half_rn(x - __half2float(h));
}

// ---------------------------------------------------------------------------
// One stage of fp16x3 compute (compile-time stage slot => reg+imm addressing).
// ---------------------------------------------------------------------------
template <int ST, int PASSES>
__device__ __forceinline__ void compute_stage(
    const uint32_t aoffk[2][4], const uint32_t boffk[2][2],
    float acc[4][4][4])
{
    #pragma unroll
    for (int ks = 0; ks < 2; ++ks) {
        uint32_t ah[4][4], al[4][4], bh[4][2], bl[4][2];

        #pragma unroll
        for (int mt = 0; mt < 4; ++mt) {
            uint32_t ad = aoffk[ks][mt] + (ST * STAGE_B);          // Ah
            LDSM4(ah[mt][0], ah[mt][1], ah[mt][2], ah[mt][3], ad);
        }
        #pragma unroll
        for (int np = 0; np < 2; ++np) {
            uint32_t ad = boffk[ks][np] + (ST * STAGE_B + 2 * TILE_B); // Bh
            uint32_t q0, q1, q2, q3;
            LDSM4(q0, q1, q2, q3, ad);
            bh[2 * np][0] = q0; bh[2 * np + 1][0] = q1;
            bh[2 * np][1] = q2; bh[2 * np + 1][1] = q3;
        }
        #pragma unroll
        for (int mt = 0; mt < 4; ++mt) {
            uint32_t ad = aoffk[ks][mt] + (ST * STAGE_B + TILE_B); // Al
            LDSM4(al[mt][0], al[mt][1], al[mt][2], al[mt][3], ad);
        }

        #pragma unroll
        for (int mt = 0; mt < 4; ++mt)
            #pragma unroll
            for (int nt = 0; nt < 4; ++nt)
                MMA(acc[mt][nt], ah[mt], bh[nt][0], bh[nt][1]);

        if (PASSES >= 3) {
            #pragma unroll
            for (int np = 0; np < 2; ++np) {
                uint32_t ad = boffk[ks][np] + (ST * STAGE_B + 3 * TILE_B); // Bl
                uint32_t q0, q1, q2, q3;
                LDSM4(q0, q1, q2, q3, ad);
                bl[2 * np][0] = q0; bl[2 * np + 1][0] = q1;
                bl[2 * np][1] = q2; bl[2 * np + 1][1] = q3;
            }
        }

        #pragma unroll
        for (int mt = 0; mt < 4; ++mt)
            #pragma unroll
            for (int nt = 0; nt < 4; ++nt)
                MMA(acc[mt][nt], al[mt], bh[nt][0], bh[nt][1]);

        if (PASSES >= 3) {
            #pragma unroll
            for (int mt = 0; mt < 4; ++mt)
                #pragma unroll
                for (int nt = 0; nt < 4; ++nt)
                    MMA(acc[mt][nt], ah[mt], bl[nt][0], bl[nt][1]);
        }
    }
}

// ---------------------------------------------------------------------------
// fp16x3 HMMA GEMM body:  C[m,n] = sum_k A[m,k] * B[n,k]  (NT, row-major)
//   PASSES==3: Ah*Bh + Al*Bh + Ah*Bl.  PASSES==2: Ah*Bh + Al*Bh (Bl unused).
// 2-stage pipeline, k-loop hand-unrolled x2. nk always even (kend mult of 128).
// OUT_HALF 0: write fp32 C (+bias).  1: write fp16 hi/lo pair.
// ---------------------------------------------------------------------------
template <int OUT_HALF, int PASSES>
__device__ __forceinline__ void gemm_body(
    const __half* __restrict__ pAh, const __half* __restrict__ pAl,
    const __half* __restrict__ pBh, const __half* __restrict__ pBl,
    float* __restrict__ Cf, __half* __restrict__ Ch, __half* __restrict__ Cl,
    const float* __restrict__ bias,
    int N, int K, int kend, int m0, int n0)
{
    extern __shared__ char smem[];
    const int nk = kend / BK;
    constexpr int NLOAD = (PASSES >= 3) ? 8 : 6;

    const int tid = threadIdx.x;
    const int r0 = tid >> 2;
    const int c0 = tid & 3;

    const __half* src0 = pAh + (long long)(m0 + r0) * K + c0 * 8;
    const __half* src1 = src0 + 64LL * K;
    const __half* src2 = pAl + (long long)(m0 + r0) * K + c0 * 8;
    const __half* src3 = src2 + 64LL * K;
    const __half* src4 = pBh + (long long)(n0 + r0) * K + c0 * 8;
    const __half* src5 = src4 + 64LL * K;
    const __half* src6 = pBl + (long long)(n0 + r0) * K + c0 * 8;
    const __half* src7 = src6 + 64LL * K;

    const uint32_t sbase = smem_u32(smem);
    const uint32_t w0 = sbase + swz((uint32_t)r0, (uint32_t)c0);
    const uint32_t w1 = w0 + 64u * 64u;
    uint32_t dsts[8];
    #pragma unroll
    for (int t = 0; t < 4; ++t) {
        dsts[2 * t]     = (uint32_t)t * TILE_B + w0;
        dsts[2 * t + 1] = (uint32_t)t * TILE_B + w1;
    }

    const int wid = tid >> 5, lid = tid & 31;
    const int wm = (wid >> 2) * 64;
    const int wn = (wid & 3) * 32;
    const int lrow = lid & 15;
    const int lkh  = lid >> 4;

    uint32_t aoffk[2][4], boffk[2][2];
    #pragma unroll
    for (int ks = 0; ks < 2; ++ks) {
        const uint32_t ckh = 2u * ks + (uint32_t)lkh;
        #pragma unroll
        for (int mt = 0; mt < 4; ++mt) {
            uint32_t row = (uint32_t)(wm + mt * 16 + lrow);
            aoffk[ks][mt] = sbase + row * 64u
                          + ((ckh ^ ((row >> 1) & 3u)) << 4);
        }
        #pragma unroll
        for (int np = 0; np < 2; ++np) {
            uint32_t row = (uint32_t)(wn + np * 16 + lrow);
            boffk[ks][np] = sbase + row * 64u
                          + ((ckh ^ ((row >> 1) & 3u)) << 4);
        }
    }

    float acc[4][4][4] = {};

    #define ISSUE_STAGE(ST)                                                  \
        do {                                                                 \
            CP_ASYNC16(dsts[0] + (ST) * STAGE_B, src0);                      \
            CP_ASYNC16(dsts[1] + (ST) * STAGE_B, src1);                      \
            CP_ASYNC16(dsts[2] + (ST) * STAGE_B, src2);                      \
            CP_ASYNC16(dsts[3] + (ST) * STAGE_B, src3);                      \
            CP_ASYNC16(dsts[4] + (ST) * STAGE_B, src4);                      \
            CP_ASYNC16(dsts[5] + (ST) * STAGE_B, src5);                      \
            if (NLOAD > 6) {                                                 \
                CP_ASYNC16(dsts[6] + (ST) * STAGE_B, src6);                  \
                CP_ASYNC16(dsts[7] + (ST) * STAGE_B, src7);                  \
            }                                                                \
            src0 += BK; src1 += BK; src2 += BK; src3 += BK;                  \
            src4 += BK; src5 += BK; src6 += BK; src7 += BK;                  \
        } while (0)

    ISSUE_STAGE(0);
    CP_COMMIT();

    for (int kt = 0; kt < nk; kt += 2) {
        CP_WAIT(0);
        __syncthreads();
        if (kt + 1 < nk) ISSUE_STAGE(1);
        CP_COMMIT();
        compute_stage<0, PASSES>(aoffk, boffk, acc);

        CP_WAIT(0);
        __syncthreads();
        if (kt + 2 < nk) ISSUE_STAGE(0);
        CP_COMMIT();
        compute_stage<1, PASSES>(aoffk, boffk, acc);
    }
    #undef ISSUE_STAGE

    const int lm = lid >> 2, lc = (lid & 3) * 2;
    #pragma unroll
    for (int mt = 0; mt < 4; ++mt) {
        #pragma unroll
        for (int hrow = 0; hrow < 2; ++hrow) {
            const int row = m0 + wm + mt * 16 + lm + hrow * 8;
            #pragma unroll
            for (int nt = 0; nt < 4; ++nt) {
                const int col = n0 + wn + nt * 8 + lc;
                float d0 = acc[mt][nt][hrow * 2 + 0];
                float d1 = acc[mt][nt][hrow * 2 + 1];
                const long long idx = (long long)row * N + col;
                if (OUT_HALF) {
                    __half h0, l0, h1, l1;
                    split_h(d0, h0, l0);
                    split_h(d1, h1, l1);
                    *(__half2*)&Ch[idx] = __halves2half2(h0, h1);
                    *(__half2*)&Cl[idx] = __halves2half2(l0, l1);
                } else {
                    if (bias) { d0 += bias[col]; d1 += bias[col + 1]; }
                    *(float2*)&Cf[idx] = make_float2(d0, d1);
                }
            }
        }
    }
}

// ---------------------------------------------------------------------------
// mode 0: plain  mode 1: causal tile skip  mode 2: k-limit (heavy tiles first)
// ---------------------------------------------------------------------------
template <int OUT_HALF, int PASSES>
__global__ __launch_bounds__(256, 2)
void hmma_gemm(const __half* __restrict__ pAh, const __half* __restrict__ pAl,
               const __half* __restrict__ pBh, const __half* __restrict__ pBl,
               float* __restrict__ Cf, __half* __restrict__ Ch,
               __half* __restrict__ Cl, const float* __restrict__ bias,
               int M, int N, int K,
               long long sA, long long sB, long long sC, int mode)
{
    const int bn = blockIdx.x, bz = blockIdx.z;
    int bm = blockIdx.y;
    if (mode == 1 && bn > bm) return;
    if (mode == 2) bm = gridDim.y - 1 - blockIdx.y;
    const int kend = (mode == 2) ? (bm * BM + BM) : K;

    gemm_body<OUT_HALF, PASSES>(
        pAh + (long long)bz * sA, pAl + (long long)bz * sA,
        pBh + (long long)bz * sB, pBl + (long long)bz * sB,
        OUT_HALF ? nullptr : Cf + (long long)bz * sC,
        OUT_HALF ? Ch + (long long)bz * sC : nullptr,
        OUT_HALF ? Cl + (long long)bz * sC : nullptr,
        bias, N, K, kend, bm * BM, bn * BN);
}

// ---------------------------------------------------------------------------
// Folded-weight mini-GEMMs (one launch, z selects):
//  z=0: N[d',d] = sum_e Wkt[d',e]*Wqt[d,e]   ( = (Wq^T Wk)^T )
//  z=1: R[e,d]  = sum_c Wo[e,c]*Wvt[d,c]     ( = Wo Wv )
// ---------------------------------------------------------------------------
__global__ __launch_bounds__(256, 2)
void nr_gemm(const __half* __restrict__ Wkth, const __half* __restrict__ Wktl,
             const __half* __restrict__ Wqth, const __half* __restrict__ Wqtl,
             const __half* __restrict__ WOh,  const __half* __restrict__ WOl,
             const __half* __restrict__ Wvth, const __half* __restrict__ Wvtl,
             __half* __restrict__ Nh, __half* __restrict__ Nl,
             __half* __restrict__ Rh, __half* __restrict__ Rl)
{
    const int m0 = blockIdx.y * BM, n0 = blockIdx.x * BN;
    if (blockIdx.z == 0)
        gemm_body<1, 3>(Wkth, Wktl, Wqth, Wqtl, nullptr, Nh, Nl, nullptr,
                        1024, 1024, 1024, m0, n0);
    else
        gemm_body<1, 3>(WOh, WOl, Wvth, Wvtl, nullptr, Rh, Rl, nullptr,
                        1024, 1024, 1024, m0, n0);
}

// ---------------------------------------------------------------------------
// fp32 -> fp16 hi/lo split for X and WO (one launch).
// ---------------------------------------------------------------------------
__global__ __launch_bounds__(256)
void split_all_kernel(const float* __restrict__ X, const float* __restrict__ WO,
                      __half* __restrict__ Xh, __half* __restrict__ Xl,
                      __half* __restrict__ WOh, __half* __restrict__ WOl,
                      int nbX)
{
    const float* in;
    __half *h, *l;
    long long i;
    int bid = blockIdx.x;
    if (bid < nbX) {
        in = X; h = Xh; l = Xl;
        i = (long long)bid * 256 + threadIdx.x;
    } else {
        in = WO; h = WOh; l = WOl;
        i = (long long)(bid - nbX) * 256 + threadIdx.x;
    }
    float4 v = ((const float4*)in)[i];
    __half h0, l0, h1, l1, h2, l2, h3, l3;
    split_h(v.x, h0, l0); split_h(v.y, h1, l1);
    split_h(v.z, h2, l2); split_h(v.w, h3, l3);
    ((__half2*)h)[2 * i]     = __halves2half2(h0, h1);
    ((__half2*)h)[2 * i + 1] = __halves2half2(h2, h3);
    ((__half2*)l)[2 * i]     = __halves2half2(l0, l1);
    ((__half2*)l)[2 * i + 1] = __halves2half2(l2, l3);
}

// ---------------------------------------------------------------------------
// transpose + hi/lo split of the three 1024x1024 weights (z selects which).
// Wt[j,i] = W[i,j].
// ---------------------------------------------------------------------------
__global__ __launch_bounds__(256)
void trans_split_w(const float* __restrict__ WQ, const float* __restrict__ WK,
                   const float* __restrict__ WV,
                   __half* __restrict__ Qh, __half* __restrict__ Ql,
                   __half* __restrict__ Kh, __half* __restrict__ Kl,
                   __half* __restrict__ Vh, __half* __restrict__ Vl)
{
    const int z = blockIdx.z;
    const float* in = (z == 0) ? WQ : (z == 1) ? WK : WV;
    __half* oh = (z == 0) ? Qh : (z == 1) ? Kh : Vh;
    __half* ol = (z == 0) ? Ql : (z == 1) ? Kl : Vl;

    __shared__ float t[32][33];
    const int i0 = blockIdx.x * 32, j0 = blockIdx.y * 32;
    #pragma unroll
    for (int k = 0; k < 4; ++k) {
        int r = threadIdx.y + k * 8;
        t[r][threadIdx.x] = in[(i0 + r) * 1024 + j0 + threadIdx.x];
    }
    __syncthreads();
    #pragma unroll
    for (int k = 0; k < 4; ++k) {
        int j = threadIdx.y + k * 8;
        float v = t[threadIdx.x][j];
        __half h, l;
        split_h(v, h, l);
        const int idx = (j0 + j) * 1024 + i0 + threadIdx.x;
        oh[idx] = h;
        ol[idx] = l;
    }
}

// ---------------------------------------------------------------------------
// Causal row softmax. Register-cached; zero-fills only the diagonal 128-band.
// ---------------------------------------------------------------------------
__global__ __launch_bounds__(256)
void softmax_causal_kernel(const float* __restrict__ P, __half* __restrict__ Ph,
                           __half* __restrict__ Pl, int S)
{
    const int b = blockIdx.y, i = blockIdx.x;
    const long long base = ((long long)b * S + i) * S;
    const float* row = P + base;
    const int n = i + 1;
    const int tid = threadIdx.x;
    __shared__ float red[8];

    float v[8];
    const int nt = (n + 255) >> 8;

    float m = -3.4e38f;
    #pragma unroll
    for (int t = 0; t < 8; ++t) {
        if (t < nt) {
            int j = t * 256 + tid;
            v[t] = (j < n) ? row[j] : -3.4e38f;
            m = fmaxf(m, v[t]);
        }
    }
    #pragma unroll
    for (int o = 16; o; o >>= 1) m = fmaxf(m, __shfl_xor_sync(~0u, m, o));
    if ((tid & 31) == 0) red[tid >> 5] = m;
    __syncthreads();
    if (tid < 32) {
        float x = (tid < 8) ? red[tid] : -3.4e38f;
        #pragma unroll
        for (int o = 4; o; o >>= 1) x = fmaxf(x, __shfl_xor_sync(~0u, x, o));
        if (tid == 0) red[0] = x;
    }
    __syncthreads();
    m = red[0];
    __syncthreads();

    float s = 0.f;
    #pragma unroll
    for (int t = 0; t < 8; ++t) {
        if (t < nt) {
            int j = t * 256 + tid;
            v[t] = (j < n) ? __expf(v[t] - m) : 0.f;
            s += v[t];
        }
    }
    #pragma unroll
    for (int o = 16; o; o >>= 1) s += __shfl_xor_sync(~0u, s, o);
    if ((tid & 31) == 0) red[tid >> 5] = s;
    __syncthreads();
    if (tid < 32) {
        float x = (tid < 8) ? red[tid] : 0.f;
        #pragma unroll
        for (int o = 4; o; o >>= 1) x += __shfl_xor_sync(~0u, x, o);
        if (tid == 0) red[0] = x;
    }
    __syncthreads();
    const float inv = 1.f / red[0];

    #pragma unroll
    for (int t = 0; t < 8; ++t) {
        if (t < nt) {
            int j = t * 256 + tid;
            if (j < n) {
                __half h, l;
                split_h(v[t] * inv, h, l);
                Ph[base + j] = h;
                Pl[base + j] = l;
            }
        }
    }
    const int band_end = (i & ~127) + 128;
    const __half z = __float2half_rn(0.f);
    for (int j = n + tid; j < band_end; j += 256) {
        Ph[base + j] = z;
        Pl[base + j] = z;
    }
}

// ---------------------------------------------------------------------------
extern "C" void kernel_launch(void* const* d_in, const int* in_sizes, int n_in,
                              void* d_out, int out_size)
{
    const float* X  = (const float*)d_in[0];
    const float* WQ = (const float*)d_in[1];
    const float* WK = (const float*)d_in[2];
    const float* WV = (const float*)d_in[3];
    const float* WO = (const float*)d_in[4];
    const float* bO = (const float*)d_in[5];
    float* out = (float*)d_out;

    float* P;
    __half *Xh, *Xl, *WOh, *WOl;
    __half *Wqth, *Wqtl, *Wkth, *Wktl, *Wvth, *Wvtl;
    __half *Nh, *Nl, *Rh, *Rl, *Th, *Tl, *Uth, *Utl, *Ph, *Pl;
    cudaGetSymbolAddress((void**)&P, g_P);
    cudaGetSymbolAddress((void**)&Xh, g_Xh);     cudaGetSymbolAddress((void**)&Xl, g_Xl);
    cudaGetSymbolAddress((void**)&WOh, g_WOh);   cudaGetSymbolAddress((void**)&WOl, g_WOl);
    cudaGetSymbolAddress((void**)&Wqth, g_Wqth); cudaGetSymbolAddress((void**)&Wqtl, g_Wqtl);
    cudaGetSymbolAddress((void**)&Wkth, g_Wkth); cudaGetSymbolAddress((void**)&Wktl, g_Wktl);
    cudaGetSymbolAddress((void**)&Wvth, g_Wvth); cudaGetSymbolAddress((void**)&Wvtl, g_Wvtl);
    cudaGetSymbolAddress((void**)&Nh, g_Nh);     cudaGetSymbolAddress((void**)&Nl, g_Nl);
    cudaGetSymbolAddress((void**)&Rh, g_Rh);     cudaGetSymbolAddress((void**)&Rl, g_Rl);
    cudaGetSymbolAddress((void**)&Th, g_Th);     cudaGetSymbolAddress((void**)&Tl, g_Tl);
    cudaGetSymbolAddress((void**)&Uth, g_Uth);   cudaGetSymbolAddress((void**)&Utl, g_Utl);
    cudaGetSymbolAddress((void**)&Ph, g_Ph);     cudaGetSymbolAddress((void**)&Pl, g_Pl);

    cudaFuncSetAttribute((const void*)hmma_gemm<1, 3>,
                         cudaFuncAttributeMaxDynamicSharedMemorySize, SMEM_TOTAL);
    cudaFuncSetAttribute((const void*)hmma_gemm<0, 3>,
                         cudaFuncAttributeMaxDynamicSharedMemorySize, SMEM_TOTAL);
    cudaFuncSetAttribute((const void*)hmma_gemm<0, 2>,
                         cudaFuncAttributeMaxDynamicSharedMemorySize, SMEM_TOTAL);
    cudaFuncSetAttribute((const void*)nr_gemm,
                         cudaFuncAttributeMaxDynamicSharedMemorySize, SMEM_TOTAL);

    const int B = 4, S = 2048, D = 1024, M = B * S;
    const long long SD = (long long)S * D;      // 2097152
    const long long SS = (long long)S * S;      // 4194304
    const long long DS = (long long)D * S;      // 2097152 (Ut per-batch)

    dim3 blk(256);

    // 1) splits: X + WO straight; WQ/WK/WV transposed (hi/lo)
    const int nbX = (int)((long long)M * D / 4 / 256);   // 8192
    const int nbW = D * D / 4 / 256;                     // 1024
    split_all_kernel<<<nbX + nbW, blk>>>(X, WO, Xh, Xl, WOh, WOl, nbX);
    trans_split_w<<<dim3(32, 32, 3), dim3(32, 8)>>>(WQ, WK, WV,
                                                    Wqth, Wqtl, Wkth, Wktl,
                                                    Wvth, Wvtl);

    // 2) folded weights: N = (Wq^T Wk)^T, R = Wo*Wv  (one launch, 3-pass)
    nr_gemm<<<dim3(8, 8, 2), blk, SMEM_TOTAL>>>(Wkth, Wktl, Wqth, Wqtl,
                                                WOh, WOl, Wvth, Wvtl,
                                                Nh, Nl, Rh, Rl);

    // 3) T = X*N^T-fold: T[s,d'] = sum_d X[s,d]*N[d',d]  (replaces Q,K projs)
    hmma_gemm<1, 3><<<dim3(D / BN, M / BM, 1), blk, SMEM_TOTAL>>>(
        Xh, Xl, Nh, Nl, nullptr, Th, Tl, nullptr, M, D, D, 0, 0, 0, 0);

    // 4) Ut[b][e,t] = sum_d R[e,d]*X_b[t,d]  (replaces V proj + O proj)
    hmma_gemm<1, 3><<<dim3(S / BN, D / BM, B), blk, SMEM_TOTAL>>>(
        Rh, Rl, Xh, Xl, nullptr, Uth, Utl, nullptr,
        D, S, D, 0, SD, DS, 0);

    // 5) logits: P[b] = T[b] @ X[b]^T  (causal tile skip, 3-pass)
    hmma_gemm<0, 3><<<dim3(S / BN, S / BM, B), blk, SMEM_TOTAL>>>(
        Th, Tl, Xh, Xl, P, nullptr, nullptr, nullptr,
        S, S, D, SD, SD, SS, 1);

    // 6) causal softmax -> fp16 hi/lo probs (diagonal-band zero fill)
    softmax_causal_kernel<<<dim3(S, B), blk>>>(P, Ph, Pl, S);

    // 7) out[b] = P[b] @ Ut[b]^T + bO  (k-limited, heavy-first, 2-pass)
    hmma_gemm<0, 2><<<dim3(D / BN, S / BM, B), blk, SMEM_TOTAL>>>(
        Ph, Pl, Uth, Uth, out, nullptr, nullptr, bO,
        S, D, S, SS, DS, SD, 2);
}